// round 9
// baseline (speedup 1.0000x reference)
#include <cuda_runtime.h>
#include <cuda_bf16.h>
#include <math.h>
#include <stdint.h>

#define SEQ     1024
#define D_MODEL 1024
#define NHEADS  16
#define DHEAD   64
#define HIDDEN  4096
#define NBATCH  2
#define ROWS    (NBATCH*SEQ)   // 2048

// ---------------- scratch (device statics; no allocation) ----------------
__device__ __align__(128) float g_Qr[ROWS*D_MODEL];
__device__ __align__(128) float g_Qi[ROWS*D_MODEL];
__device__ __align__(128) float g_Kr[ROWS*D_MODEL];
__device__ __align__(128) float g_Ki[ROWS*D_MODEL];
__device__ __align__(128) float g_Vr[ROWS*D_MODEL];
__device__ __align__(128) float g_Vi[ROWS*D_MODEL];
__device__ __align__(128) float g_Xr[ROWS*D_MODEL];
__device__ __align__(128) float g_Xi[ROWS*D_MODEL];
__device__ __align__(128) float g_Or[ROWS*D_MODEL];
__device__ __align__(128) float g_Oi[ROWS*D_MODEL];
__device__ __align__(128) float g_Hr[ROWS*HIDDEN];
__device__ __align__(128) float g_Hi[ROWS*HIDDEN];
__device__ __align__(128) float g_Sc[NBATCH*NHEADS*SEQ*SEQ];
__device__ __align__(128) float g_M [D_MODEL*D_MODEL];
__device__ __align__(128) float g_Ta[D_MODEL*D_MODEL];
__device__ __align__(128) float g_Tb[D_MODEL*D_MODEL];
__device__ __align__(128) float g_Ur[D_MODEL*D_MODEL];
__device__ __align__(128) float g_Ui[D_MODEL*D_MODEL];

// ---------------- low-level helpers ----------------
__device__ __forceinline__ uint32_t f2tf32(float x) {
    uint32_t r;
    asm("cvt.rna.tf32.f32 %0, %1;" : "=r"(r) : "f"(x));
    return r;
}
__device__ __forceinline__ void mma_tf32(float* d, const uint32_t* a, const uint32_t* b) {
    asm volatile(
        "mma.sync.aligned.m16n8k8.row.col.f32.tf32.tf32.f32 "
        "{%0,%1,%2,%3}, {%4,%5,%6,%7}, {%8,%9}, {%0,%1,%2,%3};\n"
        : "+f"(d[0]), "+f"(d[1]), "+f"(d[2]), "+f"(d[3])
        : "r"(a[0]), "r"(a[1]), "r"(a[2]), "r"(a[3]), "r"(b[0]), "r"(b[1]));
}
__device__ __forceinline__ void mma_bf16(float* d, const uint32_t* a, const uint32_t* b) {
    asm volatile(
        "mma.sync.aligned.m16n8k16.row.col.f32.bf16.bf16.f32 "
        "{%0,%1,%2,%3}, {%4,%5,%6,%7}, {%8,%9}, {%0,%1,%2,%3};\n"
        : "+f"(d[0]), "+f"(d[1]), "+f"(d[2]), "+f"(d[3])
        : "r"(a[0]), "r"(a[1]), "r"(a[2]), "r"(a[3]), "r"(b[0]), "r"(b[1]));
}
__device__ __forceinline__ uint32_t pack_pair(float x0, float x1) {
    uint32_t r;
    asm("cvt.rn.bf16x2.f32 %0, %1, %2;" : "=r"(r) : "f"(x1), "f"(x0));
    return r;
}
__device__ __forceinline__ float gelu_f(float v) {
    return 0.5f * v * (1.0f + erff(v * 0.7071067811865476f));
}

// =================== FAST tf32 GEMM (double-buffered, op-major MMA order) ===================
// MODE 0: REAL    C  = alpha*(Ar.Br^T)  (+C)
// MODE 1: COMPLEX Cr = Ar.Br^T - Ai.Bi^T (+bias,gelu) (+C); Ci = Ar.Bi^T + Ai.Br^T
// MODE 3: REAL_A  Cr = Ar.Br^T ; Ci = Ar.Bi^T
// A k-contiguous (sAk==1). B: sBk==1 (k-contig) or sBn==1 (n-contig).
// M%128==0, N%64==0, K%32==0.
template<int MODE>
__global__ __launch_bounds__(256, 1) void cgemm_f(
    float* __restrict__ Cr, float* __restrict__ Ci,
    const float* __restrict__ Ar, const float* __restrict__ Ai,
    const float* __restrict__ Br, const float* __restrict__ Bi,
    int M, int N, int K,
    long long sAm, long long sBn, long long sBk, long long sCm,
    long long aB1, long long aB2, long long bB1, long long bB2,
    long long cB1, long long cB2, int batchDiv,
    float alpha, int accumulate,
    const float* __restrict__ biasR, const float* __restrict__ biasI, int gelu)
{
    constexpr bool AC = (MODE == 1);
    constexpr bool BC = (MODE == 1 || MODE == 3);
    constexpr int BM = 128, BN = 64, BK = 32, LDS = 36;
    constexpr int MT = 2, NT = 4;
    constexpr int AT = BM * LDS, BT = BN * LDS;
    constexpr int nA = AC ? 2 : 1, nB = BC ? 2 : 1;
    constexpr int STAGE = nA * AT + nB * BT;

    extern __shared__ uint32_t smem[];

    int z = blockIdx.z, zb = z / batchDiv, zh = z % batchDiv;
    Ar += (long long)zb * aB1 + (long long)zh * aB2;
    if constexpr (AC) Ai += (long long)zb * aB1 + (long long)zh * aB2;
    Br += (long long)zb * bB1 + (long long)zh * bB2;
    if constexpr (BC) Bi += (long long)zb * bB1 + (long long)zh * bB2;
    Cr += (long long)zb * cB1 + (long long)zh * cB2;
    if constexpr (MODE == 1 || MODE == 3) Ci += (long long)zb * cB1 + (long long)zh * cB2;

    int m0 = blockIdx.y * BM, n0 = blockIdx.x * BN;
    int tid = threadIdx.x;
    int lane = tid & 31, w = tid >> 5;
    int mbase = (w >> 1) * 32, nbase = (w & 1) * 32;
    int lg = lane >> 2, lt = lane & 3;

    float accP[MT][NT][4], accI[MT][NT][4];
    #pragma unroll
    for (int mt = 0; mt < MT; mt++)
        #pragma unroll
        for (int nt = 0; nt < NT; nt++)
            #pragma unroll
            for (int e = 0; e < 4; e++) { accP[mt][nt][e] = 0.f; accI[mt][nt][e] = 0.f; }

    float4 pA[nA][4], pB[nB][2];

    auto ldg = [&](int k0) {
        #pragma unroll
        for (int c = 0; c < nA; c++) {
            const float* G = c ? Ai : Ar;
            #pragma unroll
            for (int i = 0; i < 4; i++) {
                int idx = i * 256 + tid;
                int row = idx >> 3, c4 = idx & 7;
                pA[c][i] = *(const float4*)(G + (long long)(m0 + row) * sAm + k0 + c4 * 4);
            }
        }
        if (sBk == 1) {
            #pragma unroll
            for (int c = 0; c < nB; c++) {
                const float* G = c ? Bi : Br;
                #pragma unroll
                for (int i = 0; i < 2; i++) {
                    int idx = i * 256 + tid;
                    int row = idx >> 3, c4 = idx & 7;
                    pB[c][i] = *(const float4*)(G + (long long)(n0 + row) * sBn + k0 + c4 * 4);
                }
            }
        } else {
            #pragma unroll
            for (int c = 0; c < nB; c++) {
                const float* G = c ? Bi : Br;
                #pragma unroll
                for (int i = 0; i < 2; i++) {
                    int idx = i * 256 + tid;
                    int k = idx >> 4, c4 = idx & 15;
                    pB[c][i] = *(const float4*)(G + (long long)(k0 + k) * sBk + n0 + c4 * 4);
                }
            }
        }
    };

    auto stsA = [&](uint32_t* base) {
        #pragma unroll
        for (int c = 0; c < nA; c++) {
            uint32_t* SH = base + c * AT;
            #pragma unroll
            for (int i = 0; i < 4; i++) {
                int idx = i * 256 + tid;
                int row = idx >> 3, c4 = idx & 7;
                float4 v = pA[c][i];
                uint32_t* p = SH + row * LDS + c4 * 4;
                p[0] = f2tf32(v.x); p[1] = f2tf32(v.y);
                p[2] = f2tf32(v.z); p[3] = f2tf32(v.w);
            }
        }
    };
    auto stsB = [&](uint32_t* base) {
        if (sBk == 1) {
            #pragma unroll
            for (int c = 0; c < nB; c++) {
                uint32_t* SH = base + nA * AT + c * BT;
                #pragma unroll
                for (int i = 0; i < 2; i++) {
                    int idx = i * 256 + tid;
                    int row = idx >> 3, c4 = idx & 7;
                    float4 v = pB[c][i];
                    uint32_t* p = SH + row * LDS + c4 * 4;
                    p[0] = f2tf32(v.x); p[1] = f2tf32(v.y);
                    p[2] = f2tf32(v.z); p[3] = f2tf32(v.w);
                }
            }
        } else {
            #pragma unroll
            for (int c = 0; c < nB; c++) {
                uint32_t* SH = base + nA * AT + c * BT;
                #pragma unroll
                for (int i = 0; i < 2; i++) {
                    int idx = i * 256 + tid;
                    int k = idx >> 4, c4 = idx & 15;
                    float4 v = pB[c][i];
                    float xs[4] = { v.x, v.y, v.z, v.w };
                    #pragma unroll
                    for (int j = 0; j < 4; j++)
                        SH[(c4 * 4 + j) * LDS + k] = f2tf32(xs[j]);
                }
            }
        }
    };

    // one pair of kk-steps (kk0, kk0+8); op-major MMA emission
    auto compute2 = [&](const uint32_t* base, int kk0) {
        const uint32_t* sAr = base;
        const uint32_t* sAi = base + AT;
        const uint32_t* sBr = base + nA * AT;
        const uint32_t* sBi = sBr + BT;
        #pragma unroll
        for (int q = 0; q < 2; q++) {
            int kk = kk0 + q * 8;
            uint32_t ar[MT][4], ai[MT][4];
            uint32_t br[NT][2], bi[NT][2], nbi[NT][2];
            #pragma unroll
            for (int mt = 0; mt < MT; mt++) {
                int o0 = (mbase + mt * 16 + lg) * LDS + kk + lt;
                int o1 = o0 + 8 * LDS;
                ar[mt][0] = sAr[o0];   ar[mt][1] = sAr[o1];
                ar[mt][2] = sAr[o0+4]; ar[mt][3] = sAr[o1+4];
                if constexpr (AC) {
                    ai[mt][0] = sAi[o0];   ai[mt][1] = sAi[o1];
                    ai[mt][2] = sAi[o0+4]; ai[mt][3] = sAi[o1+4];
                }
            }
            #pragma unroll
            for (int nt = 0; nt < NT; nt++) {
                int o0 = (nbase + nt * 8 + lg) * LDS + kk + lt;
                br[nt][0] = sBr[o0]; br[nt][1] = sBr[o0+4];
                if constexpr (BC) { bi[nt][0] = sBi[o0]; bi[nt][1] = sBi[o0+4]; }
                if constexpr (MODE == 1) {
                    nbi[nt][0] = bi[nt][0] ^ 0x80000000u;
                    nbi[nt][1] = bi[nt][1] ^ 0x80000000u;
                }
            }
            // op-major: same accumulator reused only every 8-16 MMAs
            #pragma unroll
            for (int nt = 0; nt < NT; nt++)
                #pragma unroll
                for (int mt = 0; mt < MT; mt++)
                    mma_tf32(accP[mt][nt], ar[mt], br[nt]);
            if constexpr (MODE == 1 || MODE == 3) {
                #pragma unroll
                for (int nt = 0; nt < NT; nt++)
                    #pragma unroll
                    for (int mt = 0; mt < MT; mt++)
                        mma_tf32(accI[mt][nt], ar[mt], bi[nt]);
            }
            if constexpr (MODE == 1) {
                #pragma unroll
                for (int nt = 0; nt < NT; nt++)
                    #pragma unroll
                    for (int mt = 0; mt < MT; mt++)
                        mma_tf32(accP[mt][nt], ai[mt], nbi[nt]);
                #pragma unroll
                for (int nt = 0; nt < NT; nt++)
                    #pragma unroll
                    for (int mt = 0; mt < MT; mt++)
                        mma_tf32(accI[mt][nt], ai[mt], br[nt]);
            }
        }
    };

    uint32_t* cur = smem;
    uint32_t* nxt = smem + STAGE;
    ldg(0);
    stsA(cur); stsB(cur);
    __syncthreads();
    for (int k0 = 0;;) {
        int kn = k0 + BK;
        bool more = kn < K;
        if (more) ldg(kn);
        compute2(cur, 0);
        if (more) stsA(nxt);
        compute2(cur, 16);
        if (more) stsB(nxt);
        if (!more) break;
        __syncthreads();
        uint32_t* t = cur; cur = nxt; nxt = t;
        k0 = kn;
    }

    // ---- epilogue ----
    #pragma unroll
    for (int mt = 0; mt < MT; mt++)
        #pragma unroll
        for (int nt = 0; nt < NT; nt++)
            #pragma unroll
            for (int e = 0; e < 4; e++) {
                int gm = m0 + mbase + mt * 16 + lg + (e >> 1) * 8;
                int gn = n0 + nbase + nt * 8 + lt * 2 + (e & 1);
                long long p = (long long)gm * sCm + gn;
                if constexpr (MODE == 1) {
                    float vr = accP[mt][nt][e];
                    float vi = accI[mt][nt][e];
                    if (biasR) { vr += biasR[gn]; vi += biasI[gn]; }
                    if (gelu)  { vr = gelu_f(vr); vi = gelu_f(vi); }
                    if (accumulate) { vr += Cr[p]; vi += Ci[p]; }
                    Cr[p] = vr; Ci[p] = vi;
                } else if constexpr (MODE == 3) {
                    Cr[p] = accP[mt][nt][e];
                    Ci[p] = accI[mt][nt][e];
                } else {
                    float v = alpha * accP[mt][nt][e];
                    if (accumulate) v += Cr[p];
                    Cr[p] = v;
                }
            }
}

// =================== PRECISE split-bf16 GEMM (double-buffered, op-major MMA order) ===================
// fp32 = bf16_hi + bf16_lo; D += AhBh + AhBl + AlBh
// MODE 1: COMPLEX; MODE 2: CONJ_REAL  C = alpha*(Ar.Br^T + Ai.Bi^T)
template<int MODE>
__global__ __launch_bounds__(256, 1) void cgemm_p(
    float* __restrict__ Cr, float* __restrict__ Ci,
    const float* __restrict__ Ar, const float* __restrict__ Ai,
    const float* __restrict__ Br, const float* __restrict__ Bi,
    int M, int N, int K,
    long long sAm, long long sBn, long long sBk, long long sCm,
    long long aB1, long long aB2, long long bB1, long long bB2,
    long long cB1, long long cB2, int batchDiv,
    float alpha, int accumulate,
    const float* __restrict__ biasR, const float* __restrict__ biasI, int gelu)
{
    constexpr int BM = 128, BN = 64, BK = 32, LDB = 20;
    constexpr int MT = 2, NT = 4;
    constexpr int APW = BM * LDB;
    constexpr int BPW = BN * LDB;
    constexpr int STAGE = 4 * APW + 4 * BPW;

    extern __shared__ uint32_t smem[];

    int z = blockIdx.z, zb = z / batchDiv, zh = z % batchDiv;
    Ar += (long long)zb * aB1 + (long long)zh * aB2;
    Ai += (long long)zb * aB1 + (long long)zh * aB2;
    Br += (long long)zb * bB1 + (long long)zh * bB2;
    Bi += (long long)zb * bB1 + (long long)zh * bB2;
    Cr += (long long)zb * cB1 + (long long)zh * cB2;
    if constexpr (MODE == 1) Ci += (long long)zb * cB1 + (long long)zh * cB2;

    int m0 = blockIdx.y * BM, n0 = blockIdx.x * BN;
    int tid = threadIdx.x;
    int lane = tid & 31, w = tid >> 5;
    int mbase = (w >> 1) * 32, nbase = (w & 1) * 32;
    int lg = lane >> 2, lt = lane & 3;

    float accP[MT][NT][4], accI[MT][NT][4];
    #pragma unroll
    for (int mt = 0; mt < MT; mt++)
        #pragma unroll
        for (int nt = 0; nt < NT; nt++)
            #pragma unroll
            for (int e = 0; e < 4; e++) { accP[mt][nt][e] = 0.f; accI[mt][nt][e] = 0.f; }

    float4 pA[2][4], pB[2][2];

    auto ldg = [&](int k0) {
        #pragma unroll
        for (int c = 0; c < 2; c++) {
            const float* G = c ? Ai : Ar;
            #pragma unroll
            for (int i = 0; i < 4; i++) {
                int idx = i * 256 + tid;
                int row = idx >> 3, c4 = idx & 7;
                pA[c][i] = *(const float4*)(G + (long long)(m0 + row) * sAm + k0 + c4 * 4);
            }
        }
        #pragma unroll
        for (int c = 0; c < 2; c++) {
            const float* G = c ? Bi : Br;
            #pragma unroll
            for (int i = 0; i < 2; i++) {
                int idx = i * 256 + tid;
                int row = idx >> 3, c4 = idx & 7;
                pB[c][i] = *(const float4*)(G + (long long)(n0 + row) * sBn + k0 + c4 * 4);
            }
        }
    };

    auto split_store = [&](float4 v, uint32_t* hiP, uint32_t* loP) {
        uint32_t h0 = pack_pair(v.x, v.y);
        uint32_t h1 = pack_pair(v.z, v.w);
        float fx = __uint_as_float(h0 << 16);
        float fy = __uint_as_float(h0 & 0xFFFF0000u);
        float fz = __uint_as_float(h1 << 16);
        float fw = __uint_as_float(h1 & 0xFFFF0000u);
        uint32_t l0 = pack_pair(v.x - fx, v.y - fy);
        uint32_t l1 = pack_pair(v.z - fz, v.w - fw);
        hiP[0] = h0; hiP[1] = h1;
        loP[0] = l0; loP[1] = l1;
    };

    auto stsA = [&](uint32_t* base) {
        #pragma unroll
        for (int c = 0; c < 2; c++) {
            uint32_t* SH = base + c * 2 * APW;
            #pragma unroll
            for (int i = 0; i < 4; i++) {
                int idx = i * 256 + tid;
                int row = idx >> 3, c4 = idx & 7;
                uint32_t* p = SH + row * LDB + c4 * 2;
                split_store(pA[c][i], p, p + APW);
            }
        }
    };
    auto stsB = [&](uint32_t* base) {
        #pragma unroll
        for (int c = 0; c < 2; c++) {
            uint32_t* SH = base + 4 * APW + c * 2 * BPW;
            #pragma unroll
            for (int i = 0; i < 2; i++) {
                int idx = i * 256 + tid;
                int row = idx >> 3, c4 = idx & 7;
                uint32_t* p = SH + row * LDB + c4 * 2;
                split_store(pB[c][i], p, p + BPW);
            }
        }
    };

    auto computeChunk = [&](const uint32_t* base, int kk) {
        const uint32_t* sArH = base;
        const uint32_t* sAiH = base + 2 * APW;
        const uint32_t* sBrH = base + 4 * APW;
        const uint32_t* sBiH = sBrH + 2 * BPW;
        uint32_t arH[MT][4], arL[MT][4], aiH[MT][4], aiL[MT][4];
        uint32_t brH[NT][2], brL[NT][2], biH[NT][2], biL[NT][2];
        uint32_t nbiH[NT][2], nbiL[NT][2];
        #pragma unroll
        for (int mt = 0; mt < MT; mt++) {
            int o0 = (mbase + mt * 16 + lg) * LDB + kk + lt;
            int o1 = o0 + 8 * LDB;
            arH[mt][0] = sArH[o0];     arH[mt][1] = sArH[o1];
            arH[mt][2] = sArH[o0+4];   arH[mt][3] = sArH[o1+4];
            arL[mt][0] = sArH[o0+APW];   arL[mt][1] = sArH[o1+APW];
            arL[mt][2] = sArH[o0+4+APW]; arL[mt][3] = sArH[o1+4+APW];
            aiH[mt][0] = sAiH[o0];     aiH[mt][1] = sAiH[o1];
            aiH[mt][2] = sAiH[o0+4];   aiH[mt][3] = sAiH[o1+4];
            aiL[mt][0] = sAiH[o0+APW];   aiL[mt][1] = sAiH[o1+APW];
            aiL[mt][2] = sAiH[o0+4+APW]; aiL[mt][3] = sAiH[o1+4+APW];
        }
        #pragma unroll
        for (int nt = 0; nt < NT; nt++) {
            int o0 = (nbase + nt * 8 + lg) * LDB + kk + lt;
            brH[nt][0] = sBrH[o0];     brH[nt][1] = sBrH[o0+4];
            brL[nt][0] = sBrH[o0+BPW]; brL[nt][1] = sBrH[o0+4+BPW];
            biH[nt][0] = sBiH[o0];     biH[nt][1] = sBiH[o0+4];
            biL[nt][0] = sBiH[o0+BPW]; biL[nt][1] = sBiH[o0+4+BPW];
            if constexpr (MODE == 1) {
                nbiH[nt][0] = biH[nt][0] ^ 0x80008000u; nbiH[nt][1] = biH[nt][1] ^ 0x80008000u;
                nbiL[nt][0] = biL[nt][0] ^ 0x80008000u; nbiL[nt][1] = biL[nt][1] ^ 0x80008000u;
            }
        }
        // op-major: each pass sweeps all 8 tiles before touching any accumulator again
        #define SWEEP(D, A, B) \
            { _Pragma("unroll") for (int nt = 0; nt < NT; nt++) \
                _Pragma("unroll") for (int mt = 0; mt < MT; mt++) \
                    mma_bf16(D[mt][nt], A[mt], B[nt]); }
        if constexpr (MODE == 1) {
            SWEEP(accP, arH, brH);  SWEEP(accI, arH, biH);
            SWEEP(accP, aiH, nbiH); SWEEP(accI, aiH, brH);
            SWEEP(accP, arH, brL);  SWEEP(accI, arH, biL);
            SWEEP(accP, aiH, nbiL); SWEEP(accI, aiH, brL);
            SWEEP(accP, arL, brH);  SWEEP(accI, arL, biH);
            SWEEP(accP, aiL, nbiH); SWEEP(accI, aiL, brH);
        } else {
            SWEEP(accP, arH, brH);
            SWEEP(accP, aiH, biH);
            SWEEP(accP, arH, brL);
            SWEEP(accP, aiH, biL);
            SWEEP(accP, arL, brH);
            SWEEP(accP, aiL, biH);
        }
        #undef SWEEP
    };

    uint32_t* cur = smem;
    uint32_t* nxt = smem + STAGE;
    ldg(0);
    stsA(cur); stsB(cur);
    __syncthreads();
    for (int k0 = 0;;) {
        int kn = k0 + BK;
        bool more = kn < K;
        if (more) ldg(kn);
        computeChunk(cur, 0);
        if (more) stsA(nxt);
        computeChunk(cur, 8);
        if (more) stsB(nxt);
        if (!more) break;
        __syncthreads();
        uint32_t* t = cur; cur = nxt; nxt = t;
        k0 = kn;
    }

    #pragma unroll
    for (int mt = 0; mt < MT; mt++)
        #pragma unroll
        for (int nt = 0; nt < NT; nt++)
            #pragma unroll
            for (int e = 0; e < 4; e++) {
                int gm = m0 + mbase + mt * 16 + lg + (e >> 1) * 8;
                int gn = n0 + nbase + nt * 8 + lt * 2 + (e & 1);
                long long p = (long long)gm * sCm + gn;
                if constexpr (MODE == 1) {
                    float vr = accP[mt][nt][e];
                    float vi = accI[mt][nt][e];
                    if (biasR) { vr += biasR[gn]; vi += biasI[gn]; }
                    if (gelu)  { vr = gelu_f(vr); vi = gelu_f(vi); }
                    if (accumulate) { vr += Cr[p]; vi += Ci[p]; }
                    Cr[p] = vr; Ci[p] = vi;
                } else {
                    float v = alpha * accP[mt][nt][e];
                    if (accumulate) v += Cr[p];
                    Cr[p] = v;
                }
            }
}

// ---------------- coalesced 1024-pt FFT, twiddle table, 8 cols/block ----------------
#define FFT_COLS 8
#define FFT_LDP  1025
__global__ __launch_bounds__(256) void fft8_kernel(float* __restrict__ re,
                                                   float* __restrict__ im,
                                                   int inverse)
{
    extern __shared__ float fs[];
    float* sr = fs;
    float* si = fs + FFT_COLS * FFT_LDP;
    __shared__ float twr[512], twi[512];
    int blk = blockIdx.x;
    int b  = blk / (D_MODEL / FFT_COLS);
    int d0 = (blk % (D_MODEL / FFT_COLS)) * FFT_COLS;
    long long base = (long long)b * SEQ * D_MODEL + d0;
    int tid = threadIdx.x;

    float sgn = inverse ? 6.283185307179586f : -6.283185307179586f;
    #pragma unroll
    for (int j = 0; j < 2; j++) {
        int idx = j * 256 + tid;
        float ang = sgn * (float)idx * (1.0f / 1024.0f);
        float cs, sn;
        sincosf(ang, &sn, &cs);
        twr[idx] = cs; twi[idx] = sn;
    }

    #pragma unroll
    for (int i = 0; i < 8; i++) {
        int idx = i * 256 + tid;
        int row = idx >> 1, h = (idx & 1) * 4;
        int br = __brev((unsigned)row) >> 22;
        float4 vr = *(const float4*)(re + base + (long long)row * D_MODEL + h);
        float4 vi = *(const float4*)(im + base + (long long)row * D_MODEL + h);
        sr[(h+0)*FFT_LDP + br] = vr.x; sr[(h+1)*FFT_LDP + br] = vr.y;
        sr[(h+2)*FFT_LDP + br] = vr.z; sr[(h+3)*FFT_LDP + br] = vr.w;
        si[(h+0)*FFT_LDP + br] = vi.x; si[(h+1)*FFT_LDP + br] = vi.y;
        si[(h+2)*FFT_LDP + br] = vi.z; si[(h+3)*FFT_LDP + br] = vi.w;
    }
    __syncthreads();

    #pragma unroll
    for (int s = 1; s <= 10; s++) {
        int half = 1 << (s - 1);
        #pragma unroll
        for (int i = 0; i < 16; i++) {
            int idx = i * 256 + tid;
            int j = idx >> 3, c = idx & 7;
            int pos = j & (half - 1);
            int g = j >> (s - 1);
            int i0 = g * (half << 1) + pos, i1 = i0 + half;
            int tw = pos << (10 - s);
            float cs = twr[tw], sn = twi[tw];
            float* pr = sr + c * FFT_LDP;
            float* pi = si + c * FFT_LDP;
            float ur = pr[i0], ui = pi[i0];
            float vr = pr[i1], vi = pi[i1];
            float tr = cs * vr - sn * vi;
            float ti = cs * vi + sn * vr;
            pr[i0] = ur + tr; pi[i0] = ui + ti;
            pr[i1] = ur - tr; pi[i1] = ui - ti;
        }
        __syncthreads();
    }

    float sc = inverse ? (1.0f / 1024.0f) : 1.0f;
    #pragma unroll
    for (int i = 0; i < 8; i++) {
        int idx = i * 256 + tid;
        int row = idx >> 1, h = (idx & 1) * 4;
        float4 vr, vi;
        vr.x = sr[(h+0)*FFT_LDP + row] * sc; vr.y = sr[(h+1)*FFT_LDP + row] * sc;
        vr.z = sr[(h+2)*FFT_LDP + row] * sc; vr.w = sr[(h+3)*FFT_LDP + row] * sc;
        vi.x = si[(h+0)*FFT_LDP + row] * sc; vi.y = si[(h+1)*FFT_LDP + row] * sc;
        vi.z = si[(h+2)*FFT_LDP + row] * sc; vi.w = si[(h+3)*FFT_LDP + row] * sc;
        *(float4*)(re + base + (long long)row * D_MODEL + h) = vr;
        *(float4*)(im + base + (long long)row * D_MODEL + h) = vi;
    }
}
#define FFT_SMEM (2 * FFT_COLS * FFT_LDP * 4)

// ---------------- row softmax over 1024 columns ----------------
__global__ __launch_bounds__(256) void softmax_kernel(float* __restrict__ S)
{
    long long row = blockIdx.x;
    float* p = S + row*1024;
    int t = threadIdx.x;
    __shared__ float red[256];

    float vals[4];
    float m = -1e30f;
    #pragma unroll
    for (int i = 0; i < 4; i++) { vals[i] = p[t + i*256]; m = fmaxf(m, vals[i]); }
    red[t] = m; __syncthreads();
    for (int s = 128; s > 0; s >>= 1) { if (t < s) red[t] = fmaxf(red[t], red[t+s]); __syncthreads(); }
    m = red[0]; __syncthreads();

    float sum = 0.f;
    #pragma unroll
    for (int i = 0; i < 4; i++) { vals[i] = expf(vals[i] - m); sum += vals[i]; }
    red[t] = sum; __syncthreads();
    for (int s = 128; s > 0; s >>= 1) { if (t < s) red[t] += red[t+s]; __syncthreads(); }
    float inv = 1.0f / red[0];
    #pragma unroll
    for (int i = 0; i < 4; i++) p[t + i*256] = vals[i]*inv;
}

// ---------------- elementwise helpers ----------------
__global__ void copy_kernel(float* __restrict__ y, const float* __restrict__ x, long long n)
{
    long long i = (long long)blockIdx.x*blockDim.x + threadIdx.x;
    if (i < n) y[i] = x[i];
}
__global__ void scale_kernel(float* __restrict__ y, const float* __restrict__ x,
                             const float* __restrict__ dt, long long n)
{
    long long i = (long long)blockIdx.x*blockDim.x + threadIdx.x;
    if (i < n) y[i] = x[i]*dt[0];
}
// D = U - I with U = I - E/2 - i(M - G/6):  Dr = -E/2, Di = -M + G/6
__global__ void buildD_kernel(float* __restrict__ Dr, float* __restrict__ Di,
                              const float* __restrict__ Mm, const float* __restrict__ E,
                              const float* __restrict__ G, long long n)
{
    long long i = (long long)blockIdx.x*blockDim.x + threadIdx.x;
    if (i < n) {
        Dr[i] = -0.5f * E[i];
        Di[i] = -Mm[i] + G[i] * (1.0f/6.0f);
    }
}

// ---------------- host orchestration ----------------
static void cgf(int mode,
    float* Cr, float* Ci,
    const float* Ar, const float* Ai,
    const float* Br, const float* Bi,
    int M, int N, int K,
    long long sAm, long long sBn, long long sBk, long long sCm,
    float alpha, int acc,
    const float* bR = nullptr, const float* bI = nullptr, int gelu = 0,
    int batch = 1, int batchDiv = 1,
    long long aB1 = 0, long long aB2 = 0,
    long long bB1 = 0, long long bB2 = 0,
    long long cB1 = 0, long long cB2 = 0)
{
    dim3 grid(N / 64, M / 128, batch);
    int nA = (mode == 1) ? 2 : 1;
    int nB = (mode == 0) ? 1 : 2;
    size_t sh = (size_t)(nA * 128 + nB * 64) * 36 * 4 * 2;
    #define ARGS Cr, Ci, Ar, Ai, Br, Bi, M, N, K, sAm, sBn, sBk, sCm, \
                 aB1, aB2, bB1, bB2, cB1, cB2, batchDiv, alpha, acc, bR, bI, gelu
    if      (mode == 1) cgemm_f<1><<<grid, 256, sh>>>(ARGS);
    else if (mode == 3) cgemm_f<3><<<grid, 256, sh>>>(ARGS);
    else                cgemm_f<0><<<grid, 256, sh>>>(ARGS);
    #undef ARGS
}

static void cgp(int mode,
    float* Cr, float* Ci,
    const float* Ar, const float* Ai,
    const float* Br, const float* Bi,
    int M, int N, int K,
    long long sAm, long long sBn, long long sBk, long long sCm,
    float alpha, int acc,
    const float* bR = nullptr, const float* bI = nullptr, int gelu = 0,
    int batch = 1, int batchDiv = 1,
    long long aB1 = 0, long long aB2 = 0,
    long long bB1 = 0, long long bB2 = 0,
    long long cB1 = 0, long long cB2 = 0)
{
    dim3 grid(N / 64, M / 128, batch);
    size_t sh = (size_t)(4 * 128 * 20 + 4 * 64 * 20) * 4 * 2;
    #define ARGS Cr, Ci, Ar, Ai, Br, Bi, M, N, K, sAm, sBn, sBk, sCm, \
                 aB1, aB2, bB1, bB2, cB1, cB2, batchDiv, alpha, acc, bR, bI, gelu
    if (mode == 1) cgemm_p<1><<<grid, 256, sh>>>(ARGS);
    else           cgemm_p<2><<<grid, 256, sh>>>(ARGS);
    #undef ARGS
}

extern "C" void kernel_launch(void* const* d_in, const int* in_sizes, int n_in,
                              void* d_out, int out_size)
{
    cudaFuncSetAttribute(cgemm_f<1>, cudaFuncAttributeMaxDynamicSharedMemorySize, 110592);
    cudaFuncSetAttribute(cgemm_f<3>, cudaFuncAttributeMaxDynamicSharedMemorySize, 73728);
    cudaFuncSetAttribute(cgemm_f<0>, cudaFuncAttributeMaxDynamicSharedMemorySize, 55296);
    cudaFuncSetAttribute(cgemm_p<1>, cudaFuncAttributeMaxDynamicSharedMemorySize, 122880);
    cudaFuncSetAttribute(cgemm_p<2>, cudaFuncAttributeMaxDynamicSharedMemorySize, 122880);
    cudaFuncSetAttribute(fft8_kernel, cudaFuncAttributeMaxDynamicSharedMemorySize, FFT_SMEM);

    const float* x_real = (const float*)d_in[0];
    const float* x_imag = (const float*)d_in[1];
    const float* Wr_q = (const float*)d_in[2];   const float* Wi_q = (const float*)d_in[3];
    const float* br_q = (const float*)d_in[4];   const float* bi_q = (const float*)d_in[5];
    const float* Wr_k = (const float*)d_in[6];   const float* Wi_k = (const float*)d_in[7];
    const float* br_k = (const float*)d_in[8];   const float* bi_k = (const float*)d_in[9];
    const float* Wr_v = (const float*)d_in[10];  const float* Wi_v = (const float*)d_in[11];
    const float* br_v = (const float*)d_in[12];  const float* bi_v = (const float*)d_in[13];
    const float* Wr_o = (const float*)d_in[14];  const float* Wi_o = (const float*)d_in[15];
    const float* br_o = (const float*)d_in[16];  const float* bi_o = (const float*)d_in[17];
    const float* Wr_f1 = (const float*)d_in[18]; const float* Wi_f1 = (const float*)d_in[19];
    const float* br_f1 = (const float*)d_in[20]; const float* bi_f1 = (const float*)d_in[21];
    const float* Wr_f2 = (const float*)d_in[22]; const float* Wi_f2 = (const float*)d_in[23];
    const float* br_f2 = (const float*)d_in[24]; const float* bi_f2 = (const float*)d_in[25];
    const float* Hmat = (const float*)d_in[26];
    const float* dtp  = (const float*)d_in[27];

    float* outRe = (float*)d_out;
    float* outIm = outRe + (long long)ROWS*D_MODEL;

    float *Qr,*Qi,*Kr,*Ki,*Vr,*Vi,*Xr,*Xi,*Or,*Oi,*Hr,*Hi,*Sc,*Mb,*Ta,*Tb,*Ur,*Ui;
    cudaGetSymbolAddress((void**)&Qr, g_Qr); cudaGetSymbolAddress((void**)&Qi, g_Qi);
    cudaGetSymbolAddress((void**)&Kr, g_Kr); cudaGetSymbolAddress((void**)&Ki, g_Ki);
    cudaGetSymbolAddress((void**)&Vr, g_Vr); cudaGetSymbolAddress((void**)&Vi, g_Vi);
    cudaGetSymbolAddress((void**)&Xr, g_Xr); cudaGetSymbolAddress((void**)&Xi, g_Xi);
    cudaGetSymbolAddress((void**)&Or, g_Or); cudaGetSymbolAddress((void**)&Oi, g_Oi);
    cudaGetSymbolAddress((void**)&Hr, g_Hr); cudaGetSymbolAddress((void**)&Hi, g_Hi);
    cudaGetSymbolAddress((void**)&Sc, g_Sc);
    cudaGetSymbolAddress((void**)&Mb, g_M);  cudaGetSymbolAddress((void**)&Ta, g_Ta);
    cudaGetSymbolAddress((void**)&Tb, g_Tb);
    cudaGetSymbolAddress((void**)&Ur, g_Ur); cudaGetSymbolAddress((void**)&Ui, g_Ui);

    const long long ND = (long long)ROWS*D_MODEL;
    const long long DD = (long long)D_MODEL*D_MODEL;
    const long long hM = (long long)SEQ*SEQ;
    const int FFT_GRID = NBATCH * (D_MODEL / FFT_COLS);
    copy_kernel<<<(int)((ND+255)/256), 256>>>(Xr, x_real, ND);
    copy_kernel<<<(int)((ND+255)/256), 256>>>(Xi, x_imag, ND);

    // ---- Q/K/V projections (Q/K precise for softmax logit sensitivity) ----
    cgp(1, Qr,Qi, Xr,Xi, Wr_q,Wi_q, ROWS,D_MODEL,D_MODEL, D_MODEL,D_MODEL,1,D_MODEL, 1.f,0, br_q,bi_q,0);
    cgp(1, Kr,Ki, Xr,Xi, Wr_k,Wi_k, ROWS,D_MODEL,D_MODEL, D_MODEL,D_MODEL,1,D_MODEL, 1.f,0, br_k,bi_k,0);
    cgf(1, Vr,Vi, Xr,Xi, Wr_v,Wi_v, ROWS,D_MODEL,D_MODEL, D_MODEL,D_MODEL,1,D_MODEL, 1.f,0, br_v,bi_v,0);

    // ---- forward FFT along sequence axis ----
    fft8_kernel<<<FFT_GRID, 256, FFT_SMEM>>>(Qr, Qi, 0);
    fft8_kernel<<<FFT_GRID, 256, FFT_SMEM>>>(Kr, Ki, 0);
    fft8_kernel<<<FFT_GRID, 256, FFT_SMEM>>>(Vr, Vi, 0);

    // ---- scores = scale*Re(Qf conj(Kf)); precise ----
    cgp(2, Sc,nullptr, Qr,Qi, Kr,Ki, SEQ,SEQ,DHEAD,
        D_MODEL,D_MODEL,1,SEQ, 0.125f,0, nullptr,nullptr,0,
        NBATCH*NHEADS, NHEADS,
        (long long)SEQ*D_MODEL, DHEAD,
        (long long)SEQ*D_MODEL, DHEAD,
        (long long)NHEADS*hM, hM);

    softmax_kernel<<<NBATCH*NHEADS*SEQ, 256>>>(Sc);

    // ---- out_f = attn @ Vf ----
    cgf(3, Or,Oi, Sc,nullptr, Vr,Vi, SEQ,DHEAD,SEQ,
        SEQ,1,D_MODEL,D_MODEL, 1.f,0, nullptr,nullptr,0,
        NBATCH*NHEADS, NHEADS,
        (long long)NHEADS*hM, hM,
        (long long)SEQ*D_MODEL, DHEAD,
        (long long)SEQ*D_MODEL, DHEAD);

    // ---- inverse FFT ----
    fft8_kernel<<<FFT_GRID, 256, FFT_SMEM>>>(Or, Oi, 1);

    // ---- x += clin(out, Wo) ----
    cgf(1, Xr,Xi, Or,Oi, Wr_o,Wi_o, ROWS,D_MODEL,D_MODEL, D_MODEL,D_MODEL,1,D_MODEL, 1.f,1, br_o,bi_o,0);

    // ---- FFN ----
    cgf(1, Hr,Hi, Xr,Xi, Wr_f1,Wi_f1, ROWS,HIDDEN,D_MODEL, D_MODEL,D_MODEL,1,HIDDEN, 1.f,0, br_f1,bi_f1,1);
    cgf(1, Xr,Xi, Hr,Hi, Wr_f2,Wi_f2, ROWS,D_MODEL,HIDDEN, HIDDEN,HIDDEN,1,D_MODEL, 1.f,1, br_f2,bi_f2,0);

    // ---- U = expm(-i H dt), truncated Taylor: U = I - E/2 - i(M - G/6) ----
    scale_kernel<<<(int)((DD+255)/256), 256>>>(Mb, Hmat, dtp, DD);
    cgf(0, Ta,nullptr, Mb,nullptr, Mb,nullptr,
        D_MODEL,D_MODEL,D_MODEL, D_MODEL,D_MODEL,1,D_MODEL, 1.f,0);        // E = M^2
    cgf(0, Tb,nullptr, Mb,nullptr, Ta,nullptr,
        D_MODEL,D_MODEL,D_MODEL, D_MODEL,D_MODEL,1,D_MODEL, 1.f,0);        // G = M^3
    buildD_kernel<<<(int)((DD+255)/256), 256>>>(Ur, Ui, Mb, Ta, Tb, DD);   // D = U - I

    // ---- out = x + x @ D (D symmetric, small) ----
    copy_kernel<<<(int)((ND+255)/256), 256>>>(outRe, Xr, ND);
    copy_kernel<<<(int)((ND+255)/256), 256>>>(outIm, Xi, ND);
    cgf(1, outRe,outIm, Xr,Xi, Ur,Ui, ROWS,D_MODEL,D_MODEL,
        D_MODEL,D_MODEL,1,D_MODEL, 1.f,1);
}

// round 12
// speedup vs baseline: 1.1773x; 1.1773x over previous
#include <cuda_runtime.h>
#include <cuda_bf16.h>
#include <math.h>
#include <stdint.h>

#define SEQ     1024
#define D_MODEL 1024
#define NHEADS  16
#define DHEAD   64
#define HIDDEN  4096
#define NBATCH  2
#define ROWS    (NBATCH*SEQ)   // 2048

// ---------------- scratch (device statics; no allocation) ----------------
__device__ __align__(128) float g_Qr[ROWS*D_MODEL];
__device__ __align__(128) float g_Qi[ROWS*D_MODEL];
__device__ __align__(128) float g_Kr[ROWS*D_MODEL];
__device__ __align__(128) float g_Ki[ROWS*D_MODEL];
__device__ __align__(128) float g_Vr[ROWS*D_MODEL];
__device__ __align__(128) float g_Vi[ROWS*D_MODEL];
__device__ __align__(128) float g_Xr[ROWS*D_MODEL];
__device__ __align__(128) float g_Xi[ROWS*D_MODEL];
__device__ __align__(128) float g_Or[ROWS*D_MODEL];
__device__ __align__(128) float g_Oi[ROWS*D_MODEL];
__device__ __align__(128) float g_Hr[ROWS*HIDDEN];
__device__ __align__(128) float g_Hi[ROWS*HIDDEN];
__device__ __align__(128) float g_Sc[NBATCH*NHEADS*SEQ*SEQ];
__device__ __align__(128) float g_Ta[D_MODEL*D_MODEL];
// tf32-prerounded operand scratch (u32 payload)
__device__ __align__(128) uint32_t g_tAr[ROWS*HIDDEN];
__device__ __align__(128) uint32_t g_tAi[ROWS*HIDDEN];
__device__ __align__(128) uint32_t g_tBr[HIDDEN*D_MODEL];
__device__ __align__(128) uint32_t g_tBi[HIDDEN*D_MODEL];
__device__ __align__(128) uint32_t g_tM [D_MODEL*D_MODEL];

// ---------------- low-level helpers ----------------
__device__ __forceinline__ uint32_t f2tf32(float x) {
    uint32_t r;
    asm("cvt.rna.tf32.f32 %0, %1;" : "=r"(r) : "f"(x));
    return r;
}
__device__ __forceinline__ void mma_tf32(float* d, const uint32_t* a, const uint32_t* b) {
    asm volatile(
        "mma.sync.aligned.m16n8k8.row.col.f32.tf32.tf32.f32 "
        "{%0,%1,%2,%3}, {%4,%5,%6,%7}, {%8,%9}, {%0,%1,%2,%3};\n"
        : "+f"(d[0]), "+f"(d[1]), "+f"(d[2]), "+f"(d[3])
        : "r"(a[0]), "r"(a[1]), "r"(a[2]), "r"(a[3]), "r"(b[0]), "r"(b[1]));
}
__device__ __forceinline__ void mma_bf16(float* d, const uint32_t* a, const uint32_t* b) {
    asm volatile(
        "mma.sync.aligned.m16n8k16.row.col.f32.bf16.bf16.f32 "
        "{%0,%1,%2,%3}, {%4,%5,%6,%7}, {%8,%9}, {%0,%1,%2,%3};\n"
        : "+f"(d[0]), "+f"(d[1]), "+f"(d[2]), "+f"(d[3])
        : "r"(a[0]), "r"(a[1]), "r"(a[2]), "r"(a[3]), "r"(b[0]), "r"(b[1]));
}
__device__ __forceinline__ uint32_t pack_pair(float x0, float x1) {
    uint32_t r;
    asm("cvt.rn.bf16x2.f32 %0, %1, %2;" : "=r"(r) : "f"(x1), "f"(x0));
    return r;
}
__device__ __forceinline__ float gelu_f(float v) {
    return 0.5f * v * (1.0f + erff(v * 0.7071067811865476f));
}
__device__ __forceinline__ uint32_t smem_addr_of(const void* p) {
    return (uint32_t)__cvta_generic_to_shared(p);
}

// =================== cp.async tf32 GEMM (pre-rounded operands) ===================
// MODE 0: REAL    C  = alpha*(Ar.Br^T)  (+C)
// MODE 1: COMPLEX Cr = Ar.Br^T - Ai.Bi^T (+bias,gelu) (+C); Ci = Ar.Bi^T + Ai.Br^T
// A[m,k], B[n,k] are tf32-prerounded u32, k-contiguous.
// M%128==0, N%64==0, K%32==0.  2-stage cp.async pipeline; 2 CTAs/SM target.
template<int MODE>
__global__ __launch_bounds__(256, 2) void cgemm_c(
    float* __restrict__ Cr, float* __restrict__ Ci,
    const uint32_t* __restrict__ Ar, const uint32_t* __restrict__ Ai,
    const uint32_t* __restrict__ Br, const uint32_t* __restrict__ Bi,
    int M, int N, int K,
    long long sAm, long long sBn, long long sCm,
    float alpha, int accumulate,
    const float* __restrict__ biasR, const float* __restrict__ biasI, int gelu)
{
    constexpr int nAB = (MODE == 1) ? 2 : 1;
    constexpr int AW = 128 * 32;
    constexpr int BW = 64 * 32;
    constexpr int STAGE = nAB * (AW + BW);
    constexpr int MT = 2, NT = 4;

    extern __shared__ uint32_t sm[];

    int tid = threadIdx.x, lane = tid & 31, w = tid >> 5;
    int m0 = blockIdx.y * 128, n0 = blockIdx.x * 64;
    int mbase = (w >> 1) * 32, nbase = (w & 1) * 32;
    int lg = lane >> 2, lt = lane & 3;

    float accP[MT][NT][4], accI[MT][NT][4];
    #pragma unroll
    for (int mt = 0; mt < MT; mt++)
        #pragma unroll
        for (int nt = 0; nt < NT; nt++)
            #pragma unroll
            for (int e = 0; e < 4; e++) { accP[mt][nt][e] = 0.f; accI[mt][nt][e] = 0.f; }

    auto issue = [&](int k0, int buf) {
        uint32_t* base = sm + buf * STAGE;
        #pragma unroll
        for (int p = 0; p < nAB; p++) {
            const uint32_t* G = p ? Ai : Ar;
            uint32_t* S = base + p * AW;
            #pragma unroll
            for (int i = 0; i < 4; i++) {
                int idx = i * 256 + tid;
                int row = idx >> 3, c = idx & 7;
                const uint32_t* src = G + (long long)(m0 + row) * sAm + k0 + c * 4;
                uint32_t dst = smem_addr_of(S + row * 32 + ((c ^ (row & 7)) << 2));
                asm volatile("cp.async.cg.shared.global [%0], [%1], 16;"
                             :: "r"(dst), "l"(src) : "memory");
            }
        }
        #pragma unroll
        for (int p = 0; p < nAB; p++) {
            const uint32_t* G = p ? Bi : Br;
            uint32_t* S = base + nAB * AW + p * BW;
            #pragma unroll
            for (int i = 0; i < 2; i++) {
                int idx = i * 256 + tid;
                int row = idx >> 3, c = idx & 7;
                const uint32_t* src = G + (long long)(n0 + row) * sBn + k0 + c * 4;
                uint32_t dst = smem_addr_of(S + row * 32 + ((c ^ (row & 7)) << 2));
                asm volatile("cp.async.cg.shared.global [%0], [%1], 16;"
                             :: "r"(dst), "l"(src) : "memory");
            }
        }
        asm volatile("cp.async.commit_group;" ::: "memory");
    };

    auto compute = [&](int buf) {
        uint32_t* base = sm + buf * STAGE;
        const uint32_t* sAr = base;
        const uint32_t* sAi = base + AW;
        const uint32_t* sBr = base + nAB * AW;
        const uint32_t* sBi = sBr + BW;
        #pragma unroll
        for (int kk = 0; kk < 32; kk += 8) {
            int ck0 = kk >> 2, ck1 = ck0 + 1;
            uint32_t ar[MT][4], br[NT][2];
            #pragma unroll
            for (int mt = 0; mt < MT; mt++) {
                int row = mbase + mt * 16 + lg;
                int o0 = row * 32 + ((ck0 ^ (row & 7)) << 2) + lt;
                int o1 = row * 32 + ((ck1 ^ (row & 7)) << 2) + lt;
                ar[mt][0] = sAr[o0];       ar[mt][1] = sAr[o0 + 256];
                ar[mt][2] = sAr[o1];       ar[mt][3] = sAr[o1 + 256];
            }
            #pragma unroll
            for (int nt = 0; nt < NT; nt++) {
                int row = nbase + nt * 8 + lg;
                int o0 = row * 32 + ((ck0 ^ (row & 7)) << 2) + lt;
                int o1 = row * 32 + ((ck1 ^ (row & 7)) << 2) + lt;
                br[nt][0] = sBr[o0]; br[nt][1] = sBr[o1];
            }
            #pragma unroll
            for (int nt = 0; nt < NT; nt++)
                #pragma unroll
                for (int mt = 0; mt < MT; mt++)
                    mma_tf32(accP[mt][nt], ar[mt], br[nt]);
            if constexpr (MODE == 1) {
                uint32_t bi_[NT][2];
                #pragma unroll
                for (int nt = 0; nt < NT; nt++) {
                    int row = nbase + nt * 8 + lg;
                    int o0 = row * 32 + ((ck0 ^ (row & 7)) << 2) + lt;
                    int o1 = row * 32 + ((ck1 ^ (row & 7)) << 2) + lt;
                    bi_[nt][0] = sBi[o0]; bi_[nt][1] = sBi[o1];
                }
                #pragma unroll
                for (int nt = 0; nt < NT; nt++)
                    #pragma unroll
                    for (int mt = 0; mt < MT; mt++)
                        mma_tf32(accI[mt][nt], ar[mt], bi_[nt]);
                // negate Bi fragments in place, reuse ar regs for Ai
                #pragma unroll
                for (int nt = 0; nt < NT; nt++) {
                    bi_[nt][0] ^= 0x80000000u; bi_[nt][1] ^= 0x80000000u;
                }
                uint32_t ai_[MT][4];
                #pragma unroll
                for (int mt = 0; mt < MT; mt++) {
                    int row = mbase + mt * 16 + lg;
                    int o0 = row * 32 + ((ck0 ^ (row & 7)) << 2) + lt;
                    int o1 = row * 32 + ((ck1 ^ (row & 7)) << 2) + lt;
                    ai_[mt][0] = sAi[o0];     ai_[mt][1] = sAi[o0 + 256];
                    ai_[mt][2] = sAi[o1];     ai_[mt][3] = sAi[o1 + 256];
                }
                #pragma unroll
                for (int nt = 0; nt < NT; nt++)
                    #pragma unroll
                    for (int mt = 0; mt < MT; mt++)
                        mma_tf32(accP[mt][nt], ai_[mt], bi_[nt]);
                #pragma unroll
                for (int nt = 0; nt < NT; nt++)
                    #pragma unroll
                    for (int mt = 0; mt < MT; mt++)
                        mma_tf32(accI[mt][nt], ai_[mt], br[nt]);
            }
        }
    };

    int nst = K >> 5;
    issue(0, 0);
    if (nst > 1) issue(32, 1);
    int buf = 0;
    for (int s = 0; s < nst; s++) {
        if (s + 1 < nst)
            asm volatile("cp.async.wait_group 1;" ::: "memory");
        else
            asm volatile("cp.async.wait_group 0;" ::: "memory");
        __syncthreads();
        compute(buf);
        __syncthreads();
        if (s + 2 < nst) issue((s + 2) << 5, buf);
        buf ^= 1;
    }

    // ---- epilogue ----
    #pragma unroll
    for (int mt = 0; mt < MT; mt++)
        #pragma unroll
        for (int nt = 0; nt < NT; nt++)
            #pragma unroll
            for (int e = 0; e < 4; e++) {
                int gm = m0 + mbase + mt * 16 + lg + (e >> 1) * 8;
                int gn = n0 + nbase + nt * 8 + lt * 2 + (e & 1);
                long long p = (long long)gm * sCm + gn;
                if constexpr (MODE == 1) {
                    float vr = accP[mt][nt][e];
                    float vi = accI[mt][nt][e];
                    if (biasR) { vr += biasR[gn]; vi += biasI[gn]; }
                    if (gelu)  { vr = gelu_f(vr); vi = gelu_f(vi); }
                    if (accumulate) { vr += Cr[p]; vi += Ci[p]; }
                    Cr[p] = vr; Ci[p] = vi;
                } else {
                    float v = alpha * accP[mt][nt][e];
                    if (accumulate) v += Cr[p];
                    Cr[p] = v;
                }
            }
}

// =================== legacy tf32 GEMM, REAL_A mode only (attn @ V) ===================
// Cr = Ar.Br^T ; Ci = Ar.Bi^T   (B n-contiguous: sBn==1, k-strided)
__global__ __launch_bounds__(256, 1) void cgemm_av(
    float* __restrict__ Cr, float* __restrict__ Ci,
    const float* __restrict__ Ar,
    const float* __restrict__ Br, const float* __restrict__ Bi,
    int M, int N, int K,
    long long sAm, long long sBk, long long sCm,
    long long aB1, long long aB2, long long bB1, long long bB2,
    long long cB1, long long cB2, int batchDiv)
{
    constexpr int BM = 128, BN = 64, BK = 32, LDS = 36;
    constexpr int MT = 2, NT = 4;
    constexpr int AT = BM * LDS, BT = BN * LDS;
    constexpr int STAGE = AT + 2 * BT;

    extern __shared__ uint32_t smem[];

    int z = blockIdx.z, zb = z / batchDiv, zh = z % batchDiv;
    Ar += (long long)zb * aB1 + (long long)zh * aB2;
    Br += (long long)zb * bB1 + (long long)zh * bB2;
    Bi += (long long)zb * bB1 + (long long)zh * bB2;
    Cr += (long long)zb * cB1 + (long long)zh * cB2;
    Ci += (long long)zb * cB1 + (long long)zh * cB2;

    int m0 = blockIdx.y * BM, n0 = blockIdx.x * BN;
    int tid = threadIdx.x;
    int lane = tid & 31, w = tid >> 5;
    int mbase = (w >> 1) * 32, nbase = (w & 1) * 32;
    int lg = lane >> 2, lt = lane & 3;

    float accP[MT][NT][4], accI[MT][NT][4];
    #pragma unroll
    for (int mt = 0; mt < MT; mt++)
        #pragma unroll
        for (int nt = 0; nt < NT; nt++)
            #pragma unroll
            for (int e = 0; e < 4; e++) { accP[mt][nt][e] = 0.f; accI[mt][nt][e] = 0.f; }

    float4 pA[4], pB[2][2];

    auto ldg = [&](int k0) {
        #pragma unroll
        for (int i = 0; i < 4; i++) {
            int idx = i * 256 + tid;
            int row = idx >> 3, c4 = idx & 7;
            pA[i] = *(const float4*)(Ar + (long long)(m0 + row) * sAm + k0 + c4 * 4);
        }
        #pragma unroll
        for (int c = 0; c < 2; c++) {
            const float* G = c ? Bi : Br;
            #pragma unroll
            for (int i = 0; i < 2; i++) {
                int idx = i * 256 + tid;
                int k = idx >> 4, c4 = idx & 15;
                pB[c][i] = *(const float4*)(G + (long long)(k0 + k) * sBk + n0 + c4 * 4);
            }
        }
    };
    auto sts = [&](uint32_t* base) {
        #pragma unroll
        for (int i = 0; i < 4; i++) {
            int idx = i * 256 + tid;
            int row = idx >> 3, c4 = idx & 7;
            float4 v = pA[i];
            uint32_t* p = base + row * LDS + c4 * 4;
            p[0] = f2tf32(v.x); p[1] = f2tf32(v.y);
            p[2] = f2tf32(v.z); p[3] = f2tf32(v.w);
        }
        #pragma unroll
        for (int c = 0; c < 2; c++) {
            uint32_t* SH = base + AT + c * BT;
            #pragma unroll
            for (int i = 0; i < 2; i++) {
                int idx = i * 256 + tid;
                int k = idx >> 4, c4 = idx & 15;
                float4 v = pB[c][i];
                float xs[4] = { v.x, v.y, v.z, v.w };
                #pragma unroll
                for (int j = 0; j < 4; j++)
                    SH[(c4 * 4 + j) * LDS + k] = f2tf32(xs[j]);
            }
        }
    };
    auto compute = [&](const uint32_t* base) {
        const uint32_t* sAr = base;
        const uint32_t* sBr = base + AT;
        const uint32_t* sBi = sBr + BT;
        #pragma unroll
        for (int kk = 0; kk < BK; kk += 8) {
            uint32_t ar[MT][4], br[NT][2], bi[NT][2];
            #pragma unroll
            for (int mt = 0; mt < MT; mt++) {
                int o0 = (mbase + mt * 16 + lg) * LDS + kk + lt;
                int o1 = o0 + 8 * LDS;
                ar[mt][0] = sAr[o0];   ar[mt][1] = sAr[o1];
                ar[mt][2] = sAr[o0+4]; ar[mt][3] = sAr[o1+4];
            }
            #pragma unroll
            for (int nt = 0; nt < NT; nt++) {
                int o0 = (nbase + nt * 8 + lg) * LDS + kk + lt;
                br[nt][0] = sBr[o0]; br[nt][1] = sBr[o0+4];
                bi[nt][0] = sBi[o0]; bi[nt][1] = sBi[o0+4];
            }
            #pragma unroll
            for (int nt = 0; nt < NT; nt++)
                #pragma unroll
                for (int mt = 0; mt < MT; mt++) {
                    mma_tf32(accP[mt][nt], ar[mt], br[nt]);
                    mma_tf32(accI[mt][nt], ar[mt], bi[nt]);
                }
        }
    };

    uint32_t* cur = smem;
    uint32_t* nxt = smem + STAGE;
    ldg(0);
    sts(cur);
    __syncthreads();
    for (int k0 = 0;;) {
        int kn = k0 + BK;
        bool more = kn < K;
        if (more) ldg(kn);
        compute(cur);
        if (!more) break;
        sts(nxt);
        __syncthreads();
        uint32_t* t = cur; cur = nxt; nxt = t;
        k0 = kn;
    }

    #pragma unroll
    for (int mt = 0; mt < MT; mt++)
        #pragma unroll
        for (int nt = 0; nt < NT; nt++)
            #pragma unroll
            for (int e = 0; e < 4; e++) {
                int gm = m0 + mbase + mt * 16 + lg + (e >> 1) * 8;
                int gn = n0 + nbase + nt * 8 + lt * 2 + (e & 1);
                long long p = (long long)gm * sCm + gn;
                Cr[p] = accP[mt][nt][e];
                Ci[p] = accI[mt][nt][e];
            }
}

// =================== PRECISE split-bf16 GEMM (unchanged from R9) ===================
__device__ __forceinline__ void split2p(float x, float y, uint32_t& h, uint32_t& l) {
    h = pack_pair(x, y);
    float fx = __uint_as_float(h << 16);
    float fy = __uint_as_float(h & 0xFFFF0000u);
    l = pack_pair(x - fx, y - fy);
}
template<int MODE>
__global__ __launch_bounds__(256, 1) void cgemm_p(
    float* __restrict__ Cr, float* __restrict__ Ci,
    const float* __restrict__ Ar, const float* __restrict__ Ai,
    const float* __restrict__ Br, const float* __restrict__ Bi,
    int M, int N, int K,
    long long sAm, long long sBn, long long sBk, long long sCm,
    long long aB1, long long aB2, long long bB1, long long bB2,
    long long cB1, long long cB2, int batchDiv,
    float alpha, int accumulate,
    const float* __restrict__ biasR, const float* __restrict__ biasI, int gelu)
{
    constexpr int BM = 128, BN = 64, BK = 32, LDB = 20;
    constexpr int MT = 2, NT = 4;
    constexpr int APW = BM * LDB;
    constexpr int BPW = BN * LDB;
    constexpr int STAGE = 4 * APW + 4 * BPW;

    extern __shared__ uint32_t smem[];

    int z = blockIdx.z, zb = z / batchDiv, zh = z % batchDiv;
    Ar += (long long)zb * aB1 + (long long)zh * aB2;
    Ai += (long long)zb * aB1 + (long long)zh * aB2;
    Br += (long long)zb * bB1 + (long long)zh * bB2;
    Bi += (long long)zb * bB1 + (long long)zh * bB2;
    Cr += (long long)zb * cB1 + (long long)zh * cB2;
    if constexpr (MODE == 1) Ci += (long long)zb * cB1 + (long long)zh * cB2;

    int m0 = blockIdx.y * BM, n0 = blockIdx.x * BN;
    int tid = threadIdx.x;
    int lane = tid & 31, w = tid >> 5;
    int mbase = (w >> 1) * 32, nbase = (w & 1) * 32;
    int lg = lane >> 2, lt = lane & 3;

    float accP[MT][NT][4], accI[MT][NT][4];
    #pragma unroll
    for (int mt = 0; mt < MT; mt++)
        #pragma unroll
        for (int nt = 0; nt < NT; nt++)
            #pragma unroll
            for (int e = 0; e < 4; e++) { accP[mt][nt][e] = 0.f; accI[mt][nt][e] = 0.f; }

    float4 pA[2][4], pB[2][2];

    auto ldg = [&](int k0) {
        #pragma unroll
        for (int c = 0; c < 2; c++) {
            const float* G = c ? Ai : Ar;
            #pragma unroll
            for (int i = 0; i < 4; i++) {
                int idx = i * 256 + tid;
                int row = idx >> 3, c4 = idx & 7;
                pA[c][i] = *(const float4*)(G + (long long)(m0 + row) * sAm + k0 + c4 * 4);
            }
        }
        #pragma unroll
        for (int c = 0; c < 2; c++) {
            const float* G = c ? Bi : Br;
            #pragma unroll
            for (int i = 0; i < 2; i++) {
                int idx = i * 256 + tid;
                int row = idx >> 3, c4 = idx & 7;
                pB[c][i] = *(const float4*)(G + (long long)(n0 + row) * sBn + k0 + c4 * 4);
            }
        }
    };

    auto stsA = [&](uint32_t* base) {
        #pragma unroll
        for (int c = 0; c < 2; c++) {
            uint32_t* SH = base + c * 2 * APW;
            #pragma unroll
            for (int i = 0; i < 4; i++) {
                int idx = i * 256 + tid;
                int row = idx >> 3, c4 = idx & 7;
                uint32_t* p = SH + row * LDB + c4 * 2;
                uint32_t h0, l0, h1, l1;
                split2p(pA[c][i].x, pA[c][i].y, h0, l0);
                split2p(pA[c][i].z, pA[c][i].w, h1, l1);
                p[0] = h0; p[1] = h1; p[APW] = l0; p[APW+1] = l1;
            }
        }
    };
    auto stsB = [&](uint32_t* base) {
        #pragma unroll
        for (int c = 0; c < 2; c++) {
            uint32_t* SH = base + 4 * APW + c * 2 * BPW;
            #pragma unroll
            for (int i = 0; i < 2; i++) {
                int idx = i * 256 + tid;
                int row = idx >> 3, c4 = idx & 7;
                uint32_t* p = SH + row * LDB + c4 * 2;
                uint32_t h0, l0, h1, l1;
                split2p(pB[c][i].x, pB[c][i].y, h0, l0);
                split2p(pB[c][i].z, pB[c][i].w, h1, l1);
                p[0] = h0; p[1] = h1; p[BPW] = l0; p[BPW+1] = l1;
            }
        }
    };

    auto computeChunk = [&](const uint32_t* base, int kk) {
        const uint32_t* sArH = base;
        const uint32_t* sAiH = base + 2 * APW;
        const uint32_t* sBrH = base + 4 * APW;
        const uint32_t* sBiH = sBrH + 2 * BPW;
        uint32_t arH[MT][4], arL[MT][4], aiH[MT][4], aiL[MT][4];
        uint32_t brH[NT][2], brL[NT][2], biH[NT][2], biL[NT][2];
        uint32_t nbiH[NT][2], nbiL[NT][2];
        #pragma unroll
        for (int mt = 0; mt < MT; mt++) {
            int o0 = (mbase + mt * 16 + lg) * LDB + kk + lt;
            int o1 = o0 + 8 * LDB;
            arH[mt][0] = sArH[o0];     arH[mt][1] = sArH[o1];
            arH[mt][2] = sArH[o0+4];   arH[mt][3] = sArH[o1+4];
            arL[mt][0] = sArH[o0+APW];   arL[mt][1] = sArH[o1+APW];
            arL[mt][2] = sArH[o0+4+APW]; arL[mt][3] = sArH[o1+4+APW];
            aiH[mt][0] = sAiH[o0];     aiH[mt][1] = sAiH[o1];
            aiH[mt][2] = sAiH[o0+4];   aiH[mt][3] = sAiH[o1+4];
            aiL[mt][0] = sAiH[o0+APW];   aiL[mt][1] = sAiH[o1+APW];
            aiL[mt][2] = sAiH[o0+4+APW]; aiL[mt][3] = sAiH[o1+4+APW];
        }
        #pragma unroll
        for (int nt = 0; nt < NT; nt++) {
            int o0 = (nbase + nt * 8 + lg) * LDB + kk + lt;
            brH[nt][0] = sBrH[o0];     brH[nt][1] = sBrH[o0+4];
            brL[nt][0] = sBrH[o0+BPW]; brL[nt][1] = sBrH[o0+4+BPW];
            biH[nt][0] = sBiH[o0];     biH[nt][1] = sBiH[o0+4];
            biL[nt][0] = sBiH[o0+BPW]; biL[nt][1] = sBiH[o0+4+BPW];
            if constexpr (MODE == 1) {
                nbiH[nt][0] = biH[nt][0] ^ 0x80008000u; nbiH[nt][1] = biH[nt][1] ^ 0x80008000u;
                nbiL[nt][0] = biL[nt][0] ^ 0x80008000u; nbiL[nt][1] = biL[nt][1] ^ 0x80008000u;
            }
        }
        #define SWEEP(D, A, B) \
            { _Pragma("unroll") for (int nt = 0; nt < NT; nt++) \
                _Pragma("unroll") for (int mt = 0; mt < MT; mt++) \
                    mma_bf16(D[mt][nt], A[mt], B[nt]); }
        if constexpr (MODE == 1) {
            SWEEP(accP, arH, brH);  SWEEP(accI, arH, biH);
            SWEEP(accP, aiH, nbiH); SWEEP(accI, aiH, brH);
            SWEEP(accP, arH, brL);  SWEEP(accI, arH, biL);
            SWEEP(accP, aiH, nbiL); SWEEP(accI, aiH, brL);
            SWEEP(accP, arL, brH);  SWEEP(accI, arL, biH);
            SWEEP(accP, aiL, nbiH); SWEEP(accI, aiL, brH);
        } else {
            SWEEP(accP, arH, brH);
            SWEEP(accP, aiH, biH);
            SWEEP(accP, arH, brL);
            SWEEP(accP, aiH, biL);
            SWEEP(accP, arL, brH);
            SWEEP(accP, aiL, biH);
        }
        #undef SWEEP
    };

    uint32_t* cur = smem;
    uint32_t* nxt = smem + STAGE;
    ldg(0);
    stsA(cur); stsB(cur);
    __syncthreads();
    for (int k0 = 0;;) {
        int kn = k0 + BK;
        bool more = kn < K;
        if (more) ldg(kn);
        computeChunk(cur, 0);
        if (more) stsA(nxt);
        computeChunk(cur, 8);
        if (more) stsB(nxt);
        if (!more) break;
        __syncthreads();
        uint32_t* t = cur; cur = nxt; nxt = t;
        k0 = kn;
    }

    #pragma unroll
    for (int mt = 0; mt < MT; mt++)
        #pragma unroll
        for (int nt = 0; nt < NT; nt++)
            #pragma unroll
            for (int e = 0; e < 4; e++) {
                int gm = m0 + mbase + mt * 16 + lg + (e >> 1) * 8;
                int gn = n0 + nbase + nt * 8 + lt * 2 + (e & 1);
                long long p = (long long)gm * sCm + gn;
                if constexpr (MODE == 1) {
                    float vr = accP[mt][nt][e];
                    float vi = accI[mt][nt][e];
                    if (biasR) { vr += biasR[gn]; vi += biasI[gn]; }
                    if (gelu)  { vr = gelu_f(vr); vi = gelu_f(vi); }
                    if (accumulate) { vr += Cr[p]; vi += Ci[p]; }
                    Cr[p] = vr; Ci[p] = vi;
                } else {
                    float v = alpha * accP[mt][nt][e];
                    if (accumulate) v += Cr[p];
                    Cr[p] = v;
                }
            }
}

// ---------------- coalesced 1024-pt FFT, twiddle table, 8 cols/block ----------------
#define FFT_COLS 8
#define FFT_LDP  1025
__global__ __launch_bounds__(256) void fft8_kernel(float* __restrict__ re,
                                                   float* __restrict__ im,
                                                   int inverse)
{
    extern __shared__ float fs[];
    float* sr = fs;
    float* si = fs + FFT_COLS * FFT_LDP;
    __shared__ float twr[512], twi[512];
    int blk = blockIdx.x;
    int b  = blk / (D_MODEL / FFT_COLS);
    int d0 = (blk % (D_MODEL / FFT_COLS)) * FFT_COLS;
    long long base = (long long)b * SEQ * D_MODEL + d0;
    int tid = threadIdx.x;

    float sgn = inverse ? 6.283185307179586f : -6.283185307179586f;
    #pragma unroll
    for (int j = 0; j < 2; j++) {
        int idx = j * 256 + tid;
        float ang = sgn * (float)idx * (1.0f / 1024.0f);
        float cs, sn;
        sincosf(ang, &sn, &cs);
        twr[idx] = cs; twi[idx] = sn;
    }

    #pragma unroll
    for (int i = 0; i < 8; i++) {
        int idx = i * 256 + tid;
        int row = idx >> 1, h = (idx & 1) * 4;
        int br = __brev((unsigned)row) >> 22;
        float4 vr = *(const float4*)(re + base + (long long)row * D_MODEL + h);
        float4 vi = *(const float4*)(im + base + (long long)row * D_MODEL + h);
        sr[(h+0)*FFT_LDP + br] = vr.x; sr[(h+1)*FFT_LDP + br] = vr.y;
        sr[(h+2)*FFT_LDP + br] = vr.z; sr[(h+3)*FFT_LDP + br] = vr.w;
        si[(h+0)*FFT_LDP + br] = vi.x; si[(h+1)*FFT_LDP + br] = vi.y;
        si[(h+2)*FFT_LDP + br] = vi.z; si[(h+3)*FFT_LDP + br] = vi.w;
    }
    __syncthreads();

    #pragma unroll
    for (int s = 1; s <= 10; s++) {
        int half = 1 << (s - 1);
        #pragma unroll
        for (int i = 0; i < 16; i++) {
            int idx = i * 256 + tid;
            int j = idx >> 3, c = idx & 7;
            int pos = j & (half - 1);
            int g = j >> (s - 1);
            int i0 = g * (half << 1) + pos, i1 = i0 + half;
            int tw = pos << (10 - s);
            float cs = twr[tw], sn = twi[tw];
            float* pr = sr + c * FFT_LDP;
            float* pi = si + c * FFT_LDP;
            float ur = pr[i0], ui = pi[i0];
            float vr = pr[i1], vi = pi[i1];
            float tr = cs * vr - sn * vi;
            float ti = cs * vi + sn * vr;
            pr[i0] = ur + tr; pi[i0] = ui + ti;
            pr[i1] = ur - tr; pi[i1] = ui - ti;
        }
        __syncthreads();
    }

    float sc = inverse ? (1.0f / 1024.0f) : 1.0f;
    #pragma unroll
    for (int i = 0; i < 8; i++) {
        int idx = i * 256 + tid;
        int row = idx >> 1, h = (idx & 1) * 4;
        float4 vr, vi;
        vr.x = sr[(h+0)*FFT_LDP + row] * sc; vr.y = sr[(h+1)*FFT_LDP + row] * sc;
        vr.z = sr[(h+2)*FFT_LDP + row] * sc; vr.w = sr[(h+3)*FFT_LDP + row] * sc;
        vi.x = si[(h+0)*FFT_LDP + row] * sc; vi.y = si[(h+1)*FFT_LDP + row] * sc;
        vi.z = si[(h+2)*FFT_LDP + row] * sc; vi.w = si[(h+3)*FFT_LDP + row] * sc;
        *(float4*)(re + base + (long long)row * D_MODEL + h) = vr;
        *(float4*)(im + base + (long long)row * D_MODEL + h) = vi;
    }
}
#define FFT_SMEM (2 * FFT_COLS * FFT_LDP * 4)

// ---------------- row softmax over 1024 columns ----------------
__global__ __launch_bounds__(256) void softmax_kernel(float* __restrict__ S)
{
    long long row = blockIdx.x;
    float* p = S + row*1024;
    int t = threadIdx.x;
    __shared__ float red[256];

    float vals[4];
    float m = -1e30f;
    #pragma unroll
    for (int i = 0; i < 4; i++) { vals[i] = p[t + i*256]; m = fmaxf(m, vals[i]); }
    red[t] = m; __syncthreads();
    for (int s = 128; s > 0; s >>= 1) { if (t < s) red[t] = fmaxf(red[t], red[t+s]); __syncthreads(); }
    m = red[0]; __syncthreads();

    float sum = 0.f;
    #pragma unroll
    for (int i = 0; i < 4; i++) { vals[i] = expf(vals[i] - m); sum += vals[i]; }
    red[t] = sum; __syncthreads();
    for (int s = 128; s > 0; s >>= 1) { if (t < s) red[t] += red[t+s]; __syncthreads(); }
    float inv = 1.0f / red[0];
    #pragma unroll
    for (int i = 0; i < 4; i++) p[t + i*256] = vals[i]*inv;
}

// ---------------- elementwise helpers ----------------
__global__ void copy_kernel(float* __restrict__ y, const float* __restrict__ x, long long n)
{
    long long i = (long long)blockIdx.x*blockDim.x + threadIdx.x;
    if (i < n) y[i] = x[i];
}
// tf32 pre-rounding: dst[i] = tf32(src[i]) as u32 payload (float4-vectorized)
__global__ void cvt_tf32_kernel(uint32_t* __restrict__ dst, const float* __restrict__ src,
                                long long n4)
{
    long long i = (long long)blockIdx.x*blockDim.x + threadIdx.x;
    if (i < n4) {
        float4 v = ((const float4*)src)[i];
        uint4 o;
        o.x = f2tf32(v.x); o.y = f2tf32(v.y);
        o.z = f2tf32(v.z); o.w = f2tf32(v.w);
        ((uint4*)dst)[i] = o;
    }
}
__global__ void scale_tf32_kernel(uint32_t* __restrict__ y, const float* __restrict__ x,
                                  const float* __restrict__ dt, long long n)
{
    long long i = (long long)blockIdx.x*blockDim.x + threadIdx.x;
    if (i < n) y[i] = f2tf32(x[i]*dt[0]);
}
// D = U - I with U ~ I - E/2 - i M  (G/6 term dropped; < 2e-5 final effect)
// Dr = tf32(-E/2), Di = -M (sign flip of tf32 M)
__global__ void buildD_kernel(uint32_t* __restrict__ Dr, uint32_t* __restrict__ Di,
                              const uint32_t* __restrict__ tM, const float* __restrict__ E,
                              long long n)
{
    long long i = (long long)blockIdx.x*blockDim.x + threadIdx.x;
    if (i < n) {
        Dr[i] = f2tf32(-0.5f * E[i]);
        Di[i] = tM[i] ^ 0x80000000u;
    }
}

// ---------------- host orchestration ----------------
static void cgc(int mode, float* Cr, float* Ci,
    const uint32_t* Ar, const uint32_t* Ai,
    const uint32_t* Br, const uint32_t* Bi,
    int M, int N, int K, long long sAm, long long sBn, long long sCm,
    float alpha, int acc,
    const float* bR = nullptr, const float* bI = nullptr, int gelu = 0)
{
    dim3 grid(N / 64, M / 128);
    if (mode == 1) {
        size_t sh = 2 * 2 * (128*32 + 64*32) * 4;   // 98304
        cgemm_c<1><<<grid, 256, sh>>>(Cr, Ci, Ar, Ai, Br, Bi, M, N, K,
                                      sAm, sBn, sCm, alpha, acc, bR, bI, gelu);
    } else {
        size_t sh = 2 * (128*32 + 64*32) * 4;       // 49152
        cgemm_c<0><<<grid, 256, sh>>>(Cr, Ci, Ar, Ai, Br, Bi, M, N, K,
                                      sAm, sBn, sCm, alpha, acc, bR, bI, gelu);
    }
}

static void cvt(uint32_t* dst, const float* src, long long n)
{
    long long n4 = n >> 2;
    cvt_tf32_kernel<<<(int)((n4 + 255) / 256), 256>>>(dst, src, n4);
}

static void cgp(int mode,
    float* Cr, float* Ci,
    const float* Ar, const float* Ai,
    const float* Br, const float* Bi,
    int M, int N, int K,
    long long sAm, long long sBn, long long sBk, long long sCm,
    float alpha, int acc,
    const float* bR = nullptr, const float* bI = nullptr, int gelu = 0,
    int batch = 1, int batchDiv = 1,
    long long aB1 = 0, long long aB2 = 0,
    long long bB1 = 0, long long bB2 = 0,
    long long cB1 = 0, long long cB2 = 0)
{
    dim3 grid(N / 64, M / 128, batch);
    size_t sh = (size_t)(4 * 128 * 20 + 4 * 64 * 20) * 4 * 2;
    #define ARGS Cr, Ci, Ar, Ai, Br, Bi, M, N, K, sAm, sBn, sBk, sCm, \
                 aB1, aB2, bB1, bB2, cB1, cB2, batchDiv, alpha, acc, bR, bI, gelu
    if (mode == 1) cgemm_p<1><<<grid, 256, sh>>>(ARGS);
    else           cgemm_p<2><<<grid, 256, sh>>>(ARGS);
    #undef ARGS
}

extern "C" void kernel_launch(void* const* d_in, const int* in_sizes, int n_in,
                              void* d_out, int out_size)
{
    cudaFuncSetAttribute(cgemm_c<1>, cudaFuncAttributeMaxDynamicSharedMemorySize, 98304);
    cudaFuncSetAttribute(cgemm_c<0>, cudaFuncAttributeMaxDynamicSharedMemorySize, 49152);
    cudaFuncSetAttribute(cgemm_av,  cudaFuncAttributeMaxDynamicSharedMemorySize, 73728);
    cudaFuncSetAttribute(cgemm_p<1>, cudaFuncAttributeMaxDynamicSharedMemorySize, 122880);
    cudaFuncSetAttribute(cgemm_p<2>, cudaFuncAttributeMaxDynamicSharedMemorySize, 122880);
    cudaFuncSetAttribute(fft8_kernel, cudaFuncAttributeMaxDynamicSharedMemorySize, FFT_SMEM);

    const float* x_real = (const float*)d_in[0];
    const float* x_imag = (const float*)d_in[1];
    const float* Wr_q = (const float*)d_in[2];   const float* Wi_q = (const float*)d_in[3];
    const float* br_q = (const float*)d_in[4];   const float* bi_q = (const float*)d_in[5];
    const float* Wr_k = (const float*)d_in[6];   const float* Wi_k = (const float*)d_in[7];
    const float* br_k = (const float*)d_in[8];   const float* bi_k = (const float*)d_in[9];
    const float* Wr_v = (const float*)d_in[10];  const float* Wi_v = (const float*)d_in[11];
    const float* br_v = (const float*)d_in[12];  const float* bi_v = (const float*)d_in[13];
    const float* Wr_o = (const float*)d_in[14];  const float* Wi_o = (const float*)d_in[15];
    const float* br_o = (const float*)d_in[16];  const float* bi_o = (const float*)d_in[17];
    const float* Wr_f1 = (const float*)d_in[18]; const float* Wi_f1 = (const float*)d_in[19];
    const float* br_f1 = (const float*)d_in[20]; const float* bi_f1 = (const float*)d_in[21];
    const float* Wr_f2 = (const float*)d_in[22]; const float* Wi_f2 = (const float*)d_in[23];
    const float* br_f2 = (const float*)d_in[24]; const float* bi_f2 = (const float*)d_in[25];
    const float* Hmat = (const float*)d_in[26];
    const float* dtp  = (const float*)d_in[27];

    float* outRe = (float*)d_out;
    float* outIm = outRe + (long long)ROWS*D_MODEL;

    float *Qr,*Qi,*Kr,*Ki,*Vr,*Vi,*Xr,*Xi,*Or,*Oi,*Hr,*Hi,*Sc,*Ta;
    uint32_t *tAr,*tAi,*tBr,*tBi,*tM;
    cudaGetSymbolAddress((void**)&Qr, g_Qr); cudaGetSymbolAddress((void**)&Qi, g_Qi);
    cudaGetSymbolAddress((void**)&Kr, g_Kr); cudaGetSymbolAddress((void**)&Ki, g_Ki);
    cudaGetSymbolAddress((void**)&Vr, g_Vr); cudaGetSymbolAddress((void**)&Vi, g_Vi);
    cudaGetSymbolAddress((void**)&Xr, g_Xr); cudaGetSymbolAddress((void**)&Xi, g_Xi);
    cudaGetSymbolAddress((void**)&Or, g_Or); cudaGetSymbolAddress((void**)&Oi, g_Oi);
    cudaGetSymbolAddress((void**)&Hr, g_Hr); cudaGetSymbolAddress((void**)&Hi, g_Hi);
    cudaGetSymbolAddress((void**)&Sc, g_Sc); cudaGetSymbolAddress((void**)&Ta, g_Ta);
    cudaGetSymbolAddress((void**)&tAr, g_tAr); cudaGetSymbolAddress((void**)&tAi, g_tAi);
    cudaGetSymbolAddress((void**)&tBr, g_tBr); cudaGetSymbolAddress((void**)&tBi, g_tBi);
    cudaGetSymbolAddress((void**)&tM,  g_tM);

    const long long ND = (long long)ROWS*D_MODEL;
    const long long NH = (long long)ROWS*HIDDEN;
    const long long DD = (long long)D_MODEL*D_MODEL;
    const long long DH = (long long)D_MODEL*HIDDEN;
    const long long hM = (long long)SEQ*SEQ;
    const int FFT_GRID = NBATCH * (D_MODEL / FFT_COLS);
    copy_kernel<<<(int)((ND+255)/256), 256>>>(Xr, x_real, ND);
    copy_kernel<<<(int)((ND+255)/256), 256>>>(Xi, x_imag, ND);

    // ---- Q/K projections (precise split-bf16, softmax logit sensitivity) ----
    cgp(1, Qr,Qi, Xr,Xi, Wr_q,Wi_q, ROWS,D_MODEL,D_MODEL, D_MODEL,D_MODEL,1,D_MODEL, 1.f,0, br_q,bi_q,0);
    cgp(1, Kr,Ki, Xr,Xi, Wr_k,Wi_k, ROWS,D_MODEL,D_MODEL, D_MODEL,D_MODEL,1,D_MODEL, 1.f,0, br_k,bi_k,0);

    // ---- V projection (cp.async tf32 engine) ----
    cvt(tAr, Xr, ND); cvt(tAi, Xi, ND);
    cvt(tBr, Wr_v, DD); cvt(tBi, Wi_v, DD);
    cgc(1, Vr,Vi, tAr,tAi, tBr,tBi, ROWS,D_MODEL,D_MODEL, D_MODEL,D_MODEL,D_MODEL,
        1.f,0, br_v,bi_v,0);

    // ---- forward FFT along sequence axis ----
    fft8_kernel<<<FFT_GRID, 256, FFT_SMEM>>>(Qr, Qi, 0);
    fft8_kernel<<<FFT_GRID, 256, FFT_SMEM>>>(Kr, Ki, 0);
    fft8_kernel<<<FFT_GRID, 256, FFT_SMEM>>>(Vr, Vi, 0);

    // ---- scores = scale*Re(Qf conj(Kf)); precise ----
    cgp(2, Sc,nullptr, Qr,Qi, Kr,Ki, SEQ,SEQ,DHEAD,
        D_MODEL,D_MODEL,1,SEQ, 0.125f,0, nullptr,nullptr,0,
        NBATCH*NHEADS, NHEADS,
        (long long)SEQ*D_MODEL, DHEAD,
        (long long)SEQ*D_MODEL, DHEAD,
        (long long)NHEADS*hM, hM);

    softmax_kernel<<<NBATCH*NHEADS*SEQ, 256>>>(Sc);

    // ---- out_f = attn @ Vf (legacy path; B n-contiguous) ----
    cgemm_av<<<dim3(1, SEQ/128, NBATCH*NHEADS), 256, 73728>>>(
        Or, Oi, Sc, Vr, Vi, SEQ, DHEAD, SEQ,
        SEQ, D_MODEL, D_MODEL,
        (long long)NHEADS*hM, hM,
        (long long)SEQ*D_MODEL, DHEAD,
        (long long)SEQ*D_MODEL, DHEAD, NHEADS);

    // ---- inverse FFT ----
    fft8_kernel<<<FFT_GRID, 256, FFT_SMEM>>>(Or, Oi, 1);

    // ---- x += clin(out, Wo) ----
    cvt(tAr, Or, ND); cvt(tAi, Oi, ND);
    cvt(tBr, Wr_o, DD); cvt(tBi, Wi_o, DD);
    cgc(1, Xr,Xi, tAr,tAi, tBr,tBi, ROWS,D_MODEL,D_MODEL, D_MODEL,D_MODEL,D_MODEL,
        1.f,1, br_o,bi_o,0);

    // ---- FFN ----
    cvt(tAr, Xr, ND); cvt(tAi, Xi, ND);
    cvt(tBr, Wr_f1, DH); cvt(tBi, Wi_f1, DH);
    cgc(1, Hr,Hi, tAr,tAi, tBr,tBi, ROWS,HIDDEN,D_MODEL, D_MODEL,D_MODEL,HIDDEN,
        1.f,0, br_f1,bi_f1,1);
    cvt(tAr, Hr, NH); cvt(tAi, Hi, NH);
    cvt(tBr, Wr_f2, DH); cvt(tBi, Wi_f2, DH);
    cgc(1, Xr,Xi, tAr,tAi, tBr,tBi, ROWS,D_MODEL,HIDDEN, HIDDEN,HIDDEN,D_MODEL,
        1.f,1, br_f2,bi_f2,0);

    // ---- U = expm(-i H dt) ~ I - E/2 - i M  (E = M^2, M = H dt; G/6 dropped) ----
    scale_tf32_kernel<<<(int)((DD+255)/256), 256>>>(tM, Hmat, dtp, DD);
    cgc(0, Ta,nullptr, tM,nullptr, tM,nullptr, D_MODEL,D_MODEL,D_MODEL,
        D_MODEL,D_MODEL,D_MODEL, 1.f,0);
    buildD_kernel<<<(int)((DD+255)/256), 256>>>(tBr, tBi, tM, Ta, DD);   // D = U - I (tf32)

    // ---- out = x + x @ D (D symmetric, small) ----
    copy_kernel<<<(int)((ND+255)/256), 256>>>(outRe, Xr, ND);
    copy_kernel<<<(int)((ND+255)/256), 256>>>(outIm, Xi, ND);
    cvt(tAr, Xr, ND); cvt(tAi, Xi, ND);
    cgc(1, outRe,outIm, tAr,tAi, tBr,tBi, ROWS,D_MODEL,D_MODEL, D_MODEL,D_MODEL,D_MODEL,
        1.f,1, nullptr,nullptr,0);
}

// round 15
// speedup vs baseline: 1.1836x; 1.0053x over previous
#include <cuda_runtime.h>
#include <cuda_bf16.h>
#include <math.h>
#include <stdint.h>

#define SEQ     1024
#define D_MODEL 1024
#define NHEADS  16
#define DHEAD   64
#define HIDDEN  4096
#define NBATCH  2
#define ROWS    (NBATCH*SEQ)   // 2048

// ---------------- scratch (device statics; no allocation) ----------------
__device__ __align__(128) float g_Qr[ROWS*D_MODEL];
__device__ __align__(128) float g_Qi[ROWS*D_MODEL];
__device__ __align__(128) float g_Kr[ROWS*D_MODEL];
__device__ __align__(128) float g_Ki[ROWS*D_MODEL];
__device__ __align__(128) float g_Vr[ROWS*D_MODEL];
__device__ __align__(128) float g_Vi[ROWS*D_MODEL];
__device__ __align__(128) float g_Xr[ROWS*D_MODEL];
__device__ __align__(128) float g_Xi[ROWS*D_MODEL];
__device__ __align__(128) float g_Or[ROWS*D_MODEL];
__device__ __align__(128) float g_Oi[ROWS*D_MODEL];
__device__ __align__(128) float g_Hr[ROWS*HIDDEN];
__device__ __align__(128) float g_Hi[ROWS*HIDDEN];
__device__ __align__(128) float g_Sc[NBATCH*NHEADS*SEQ*SEQ];
__device__ __align__(128) float g_Ta[D_MODEL*D_MODEL];
// operand scratch (tf32 u32 payload OR packed bf16x2 planes)
__device__ __align__(128) uint32_t g_tAr[ROWS*HIDDEN];
__device__ __align__(128) uint32_t g_tAi[ROWS*HIDDEN];
__device__ __align__(128) uint32_t g_tBr[HIDDEN*D_MODEL];
__device__ __align__(128) uint32_t g_tBi[HIDDEN*D_MODEL];
__device__ __align__(128) uint32_t g_tM [D_MODEL*D_MODEL];

// ---------------- low-level helpers ----------------
__device__ __forceinline__ uint32_t f2tf32(float x) {
    uint32_t r;
    asm("cvt.rna.tf32.f32 %0, %1;" : "=r"(r) : "f"(x));
    return r;
}
__device__ __forceinline__ void mma_tf32(float* d, const uint32_t* a, const uint32_t* b) {
    asm volatile(
        "mma.sync.aligned.m16n8k8.row.col.f32.tf32.tf32.f32 "
        "{%0,%1,%2,%3}, {%4,%5,%6,%7}, {%8,%9}, {%0,%1,%2,%3};\n"
        : "+f"(d[0]), "+f"(d[1]), "+f"(d[2]), "+f"(d[3])
        : "r"(a[0]), "r"(a[1]), "r"(a[2]), "r"(a[3]), "r"(b[0]), "r"(b[1]));
}
__device__ __forceinline__ void mma_bf16(float* d, const uint32_t* a, const uint32_t* b) {
    asm volatile(
        "mma.sync.aligned.m16n8k16.row.col.f32.bf16.bf16.f32 "
        "{%0,%1,%2,%3}, {%4,%5,%6,%7}, {%8,%9}, {%0,%1,%2,%3};\n"
        : "+f"(d[0]), "+f"(d[1]), "+f"(d[2]), "+f"(d[3])
        : "r"(a[0]), "r"(a[1]), "r"(a[2]), "r"(a[3]), "r"(b[0]), "r"(b[1]));
}
__device__ __forceinline__ uint32_t pack_pair(float x0, float x1) {
    uint32_t r;
    asm("cvt.rn.bf16x2.f32 %0, %1, %2;" : "=r"(r) : "f"(x1), "f"(x0));
    return r;
}
__device__ __forceinline__ float gelu_f(float v) {
    return 0.5f * v * (1.0f + erff(v * 0.7071067811865476f));
}
__device__ __forceinline__ uint32_t smem_addr_of(const void* p) {
    return (uint32_t)__cvta_generic_to_shared(p);
}
#define CP16(dst, src) \
    asm volatile("cp.async.cg.shared.global [%0], [%1], 16;" :: "r"(dst), "l"(src) : "memory")

// =================== cp.async tf32 GEMM (pre-rounded operands) ===================
// MODE 0: REAL  C = alpha*(Ar.Br^T) (+C)
// MODE 1: COMPLEX Cr = Ar.Br^T - Ai.Bi^T (+bias,gelu)(+C); Ci = Ar.Bi^T + Ai.Br^T
// A[m,k], B[n,k] tf32-prerounded u32, k-contiguous. M%128==0, N%64==0, K%32==0.
template<int MODE>
__global__ __launch_bounds__(256, 2) void cgemm_c(
    float* __restrict__ Cr, float* __restrict__ Ci,
    const uint32_t* __restrict__ Ar, const uint32_t* __restrict__ Ai,
    const uint32_t* __restrict__ Br, const uint32_t* __restrict__ Bi,
    int M, int N, int K,
    long long sAm, long long sBn, long long sCm,
    float alpha, int accumulate,
    const float* __restrict__ biasR, const float* __restrict__ biasI, int gelu)
{
    constexpr int nAB = (MODE == 1) ? 2 : 1;
    constexpr int AW = 128 * 32;
    constexpr int BW = 64 * 32;
    constexpr int STAGE = nAB * (AW + BW);
    constexpr int MT = 2, NT = 4;

    extern __shared__ uint32_t sm[];

    int tid = threadIdx.x, lane = tid & 31, w = tid >> 5;
    int m0 = blockIdx.y * 128, n0 = blockIdx.x * 64;
    int mbase = (w >> 1) * 32, nbase = (w & 1) * 32;
    int lg = lane >> 2, lt = lane & 3;

    float accP[MT][NT][4], accI[MT][NT][4];
    #pragma unroll
    for (int mt = 0; mt < MT; mt++)
        #pragma unroll
        for (int nt = 0; nt < NT; nt++)
            #pragma unroll
            for (int e = 0; e < 4; e++) { accP[mt][nt][e] = 0.f; accI[mt][nt][e] = 0.f; }

    auto issue = [&](int k0, int buf) {
        uint32_t* base = sm + buf * STAGE;
        #pragma unroll
        for (int p = 0; p < nAB; p++) {
            const uint32_t* G = p ? Ai : Ar;
            uint32_t* S = base + p * AW;
            #pragma unroll
            for (int i = 0; i < 4; i++) {
                int idx = i * 256 + tid;
                int row = idx >> 3, c = idx & 7;
                const uint32_t* src = G + (long long)(m0 + row) * sAm + k0 + c * 4;
                CP16(smem_addr_of(S + row * 32 + ((c ^ (row & 7)) << 2)), src);
            }
        }
        #pragma unroll
        for (int p = 0; p < nAB; p++) {
            const uint32_t* G = p ? Bi : Br;
            uint32_t* S = base + nAB * AW + p * BW;
            #pragma unroll
            for (int i = 0; i < 2; i++) {
                int idx = i * 256 + tid;
                int row = idx >> 3, c = idx & 7;
                const uint32_t* src = G + (long long)(n0 + row) * sBn + k0 + c * 4;
                CP16(smem_addr_of(S + row * 32 + ((c ^ (row & 7)) << 2)), src);
            }
        }
        asm volatile("cp.async.commit_group;" ::: "memory");
    };

    auto compute = [&](int buf) {
        uint32_t* base = sm + buf * STAGE;
        const uint32_t* sAr = base;
        const uint32_t* sAi = base + AW;
        const uint32_t* sBr = base + nAB * AW;
        const uint32_t* sBi = sBr + BW;
        #pragma unroll
        for (int kk = 0; kk < 32; kk += 8) {
            int ck0 = kk >> 2, ck1 = ck0 + 1;
            uint32_t ar[MT][4], br[NT][2];
            #pragma unroll
            for (int mt = 0; mt < MT; mt++) {
                int row = mbase + mt * 16 + lg;
                int o0 = row * 32 + ((ck0 ^ (row & 7)) << 2) + lt;
                int o1 = row * 32 + ((ck1 ^ (row & 7)) << 2) + lt;
                ar[mt][0] = sAr[o0];       ar[mt][1] = sAr[o0 + 256];
                ar[mt][2] = sAr[o1];       ar[mt][3] = sAr[o1 + 256];
            }
            #pragma unroll
            for (int nt = 0; nt < NT; nt++) {
                int row = nbase + nt * 8 + lg;
                int o0 = row * 32 + ((ck0 ^ (row & 7)) << 2) + lt;
                int o1 = row * 32 + ((ck1 ^ (row & 7)) << 2) + lt;
                br[nt][0] = sBr[o0]; br[nt][1] = sBr[o1];
            }
            #pragma unroll
            for (int nt = 0; nt < NT; nt++)
                #pragma unroll
                for (int mt = 0; mt < MT; mt++)
                    mma_tf32(accP[mt][nt], ar[mt], br[nt]);
            if constexpr (MODE == 1) {
                uint32_t bi_[NT][2];
                #pragma unroll
                for (int nt = 0; nt < NT; nt++) {
                    int row = nbase + nt * 8 + lg;
                    int o0 = row * 32 + ((ck0 ^ (row & 7)) << 2) + lt;
                    int o1 = row * 32 + ((ck1 ^ (row & 7)) << 2) + lt;
                    bi_[nt][0] = sBi[o0]; bi_[nt][1] = sBi[o1];
                }
                #pragma unroll
                for (int nt = 0; nt < NT; nt++)
                    #pragma unroll
                    for (int mt = 0; mt < MT; mt++)
                        mma_tf32(accI[mt][nt], ar[mt], bi_[nt]);
                #pragma unroll
                for (int nt = 0; nt < NT; nt++) {
                    bi_[nt][0] ^= 0x80000000u; bi_[nt][1] ^= 0x80000000u;
                }
                uint32_t ai_[MT][4];
                #pragma unroll
                for (int mt = 0; mt < MT; mt++) {
                    int row = mbase + mt * 16 + lg;
                    int o0 = row * 32 + ((ck0 ^ (row & 7)) << 2) + lt;
                    int o1 = row * 32 + ((ck1 ^ (row & 7)) << 2) + lt;
                    ai_[mt][0] = sAi[o0];     ai_[mt][1] = sAi[o0 + 256];
                    ai_[mt][2] = sAi[o1];     ai_[mt][3] = sAi[o1 + 256];
                }
                #pragma unroll
                for (int nt = 0; nt < NT; nt++)
                    #pragma unroll
                    for (int mt = 0; mt < MT; mt++)
                        mma_tf32(accP[mt][nt], ai_[mt], bi_[nt]);
                #pragma unroll
                for (int nt = 0; nt < NT; nt++)
                    #pragma unroll
                    for (int mt = 0; mt < MT; mt++)
                        mma_tf32(accI[mt][nt], ai_[mt], br[nt]);
            }
        }
    };

    int nst = K >> 5;
    issue(0, 0);
    if (nst > 1) issue(32, 1);
    int buf = 0;
    for (int s = 0; s < nst; s++) {
        if (s + 1 < nst)
            asm volatile("cp.async.wait_group 1;" ::: "memory");
        else
            asm volatile("cp.async.wait_group 0;" ::: "memory");
        __syncthreads();
        compute(buf);
        __syncthreads();
        if (s + 2 < nst) issue((s + 2) << 5, buf);
        buf ^= 1;
    }

    #pragma unroll
    for (int mt = 0; mt < MT; mt++)
        #pragma unroll
        for (int nt = 0; nt < NT; nt++)
            #pragma unroll
            for (int e = 0; e < 4; e++) {
                int gm = m0 + mbase + mt * 16 + lg + (e >> 1) * 8;
                int gn = n0 + nbase + nt * 8 + lt * 2 + (e & 1);
                long long p = (long long)gm * sCm + gn;
                if constexpr (MODE == 1) {
                    float vr = accP[mt][nt][e];
                    float vi = accI[mt][nt][e];
                    if (biasR) { vr += biasR[gn]; vi += biasI[gn]; }
                    if (gelu)  { vr = gelu_f(vr); vi = gelu_f(vi); }
                    if (accumulate) { vr += Cr[p]; vi += Ci[p]; }
                    Cr[p] = vr; Ci[p] = vi;
                } else {
                    float v = alpha * accP[mt][nt][e];
                    if (accumulate) v += Cr[p];
                    Cr[p] = v;
                }
            }
}

// =================== PRECISE cp.async split-bf16 GEMM, 512 threads ===================
// Operands pre-split into bf16 hi/lo planes (u32 = 2 consecutive-k bf16), k-contiguous.
// MODE 1: COMPLEX  Cr = ArBr^T - AiBi^T (+bias)(+C); Ci = ArBi^T + AiBr^T
// MODE 2: CONJ_REAL C = alpha*(ArBr^T + AiBi^T)
// 3-pass per real product: hi*hi + hi*lo + lo*hi.  M%128==0, N%64==0, K%64==0.
// K staged 64 at a time; warp grid 4x4 (tile 32x16/warp).
template<int MODE>
__global__ __launch_bounds__(512, 1) void cgemm_q(
    float* __restrict__ Cr, float* __restrict__ Ci,
    const uint32_t* __restrict__ AhR, const uint32_t* __restrict__ AlR,
    const uint32_t* __restrict__ AhI, const uint32_t* __restrict__ AlI,
    const uint32_t* __restrict__ BhR, const uint32_t* __restrict__ BlR,
    const uint32_t* __restrict__ BhI, const uint32_t* __restrict__ BlI,
    int M, int N, int K,
    long long sAm, long long sBn, long long sCm,
    long long aB1, long long aB2, long long bB1, long long bB2,
    long long cB1, long long cB2, int batchDiv,
    float alpha, int accumulate,
    const float* __restrict__ biasR, const float* __restrict__ biasI)
{
    constexpr int AW = 128 * 32;   // u32 per A plane per stage (k-chunk 64 bf16 = 32 u32/row)
    constexpr int BW = 64 * 32;
    constexpr int STAGE = 4 * AW + 4 * BW;   // 24576 u32 = 96KB
    constexpr int MT = 2, NT = 2;

    extern __shared__ uint32_t sm[];

    int tid = threadIdx.x, lane = tid & 31, w = tid >> 5;
    int z = blockIdx.z, zb = z / batchDiv, zh = z % batchDiv;
    long long aOff = ((long long)zb * aB1 + (long long)zh * aB2) >> 1;
    long long bOff = ((long long)zb * bB1 + (long long)zh * bB2) >> 1;
    const uint32_t* pA[4] = { AhR + aOff, AlR + aOff, AhI + aOff, AlI + aOff };
    const uint32_t* pB[4] = { BhR + bOff, BlR + bOff, BhI + bOff, BlI + bOff };
    Cr += (long long)zb * cB1 + (long long)zh * cB2;
    if constexpr (MODE == 1) Ci += (long long)zb * cB1 + (long long)zh * cB2;

    int m0 = blockIdx.y * 128, n0 = blockIdx.x * 64;
    int mbase = (w >> 2) * 32, nbase = (w & 3) * 16;
    int lg = lane >> 2, lt = lane & 3;
    long long sAu = sAm >> 1, sBu = sBn >> 1;

    float accP[MT][NT][4], accI[MT][NT][4];
    #pragma unroll
    for (int mt = 0; mt < MT; mt++)
        #pragma unroll
        for (int nt = 0; nt < NT; nt++)
            #pragma unroll
            for (int e = 0; e < 4; e++) { accP[mt][nt][e] = 0.f; accI[mt][nt][e] = 0.f; }

    auto issue = [&](int k0, int buf) {
        uint32_t* base = sm + buf * STAGE;
        long long ku = k0 >> 1;
        #pragma unroll
        for (int p = 0; p < 4; p++) {
            #pragma unroll
            for (int i = 0; i < 2; i++) {
                int idx = i * 512 + tid;               // 1024 = 128 rows x 8 groups
                int row = idx >> 3, c = idx & 7;
                const uint32_t* src = pA[p] + (long long)(m0 + row) * sAu + ku + c * 4;
                CP16(smem_addr_of(base + p * AW + row * 32 + ((c ^ (row & 7)) << 2)), src);
            }
        }
        #pragma unroll
        for (int p = 0; p < 4; p++) {
            int row = tid >> 3, c = tid & 7;           // 512 = 64 rows x 8 groups
            const uint32_t* src = pB[p] + (long long)(n0 + row) * sBu + ku + c * 4;
            CP16(smem_addr_of(base + 4 * AW + p * BW + row * 32 + ((c ^ (row & 7)) << 2)), src);
        }
        asm volatile("cp.async.commit_group;" ::: "memory");
    };

    auto compute = [&](int buf) {
        uint32_t* base = sm + buf * STAGE;
        const uint32_t* sA[4] = { base, base + AW, base + 2*AW, base + 3*AW };
        const uint32_t* sB[4] = { base + 4*AW, base + 4*AW + BW,
                                  base + 4*AW + 2*BW, base + 4*AW + 3*BW };
        #pragma unroll
        for (int c = 0; c < 4; c++) {                 // 4 k16 sub-chunks
            int g0 = 2 * c, g1 = 2 * c + 1;
            int r0 = mbase + lg, r1 = r0 + 8, r2 = r0 + 16, r3 = r0 + 24;
            int oA[4][2];                              // [row of 4][group of 2]
            oA[0][0] = r0*32 + ((g0 ^ (r0&7))<<2) + lt; oA[0][1] = r0*32 + ((g1 ^ (r0&7))<<2) + lt;
            oA[1][0] = r1*32 + ((g0 ^ (r1&7))<<2) + lt; oA[1][1] = r1*32 + ((g1 ^ (r1&7))<<2) + lt;
            oA[2][0] = r2*32 + ((g0 ^ (r2&7))<<2) + lt; oA[2][1] = r2*32 + ((g1 ^ (r2&7))<<2) + lt;
            oA[3][0] = r3*32 + ((g0 ^ (r3&7))<<2) + lt; oA[3][1] = r3*32 + ((g1 ^ (r3&7))<<2) + lt;
            int rb0 = nbase + lg, rb1 = rb0 + 8;
            int oB[2][2];
            oB[0][0] = rb0*32 + ((g0 ^ (rb0&7))<<2) + lt; oB[0][1] = rb0*32 + ((g1 ^ (rb0&7))<<2) + lt;
            oB[1][0] = rb1*32 + ((g0 ^ (rb1&7))<<2) + lt; oB[1][1] = rb1*32 + ((g1 ^ (rb1&7))<<2) + lt;

            uint32_t arH[MT][4], arL[MT][4], aiH[MT][4], aiL[MT][4];
            #pragma unroll
            for (int mt = 0; mt < MT; mt++) {
                int ra = mt * 2, rbx = mt * 2 + 1;    // rows r0/r1 for mt=0, r2/r3 for mt=1
                arH[mt][0] = sA[0][oA[ra][0]]; arH[mt][1] = sA[0][oA[rbx][0]];
                arH[mt][2] = sA[0][oA[ra][1]]; arH[mt][3] = sA[0][oA[rbx][1]];
                arL[mt][0] = sA[1][oA[ra][0]]; arL[mt][1] = sA[1][oA[rbx][0]];
                arL[mt][2] = sA[1][oA[ra][1]]; arL[mt][3] = sA[1][oA[rbx][1]];
                aiH[mt][0] = sA[2][oA[ra][0]]; aiH[mt][1] = sA[2][oA[rbx][0]];
                aiH[mt][2] = sA[2][oA[ra][1]]; aiH[mt][3] = sA[2][oA[rbx][1]];
                aiL[mt][0] = sA[3][oA[ra][0]]; aiL[mt][1] = sA[3][oA[rbx][0]];
                aiL[mt][2] = sA[3][oA[ra][1]]; aiL[mt][3] = sA[3][oA[rbx][1]];
            }
            uint32_t brH[NT][2], brL[NT][2], biH[NT][2], biL[NT][2];
            #pragma unroll
            for (int nt = 0; nt < NT; nt++) {
                brH[nt][0] = sB[0][oB[nt][0]]; brH[nt][1] = sB[0][oB[nt][1]];
                brL[nt][0] = sB[1][oB[nt][0]]; brL[nt][1] = sB[1][oB[nt][1]];
                biH[nt][0] = sB[2][oB[nt][0]]; biH[nt][1] = sB[2][oB[nt][1]];
                biL[nt][0] = sB[3][oB[nt][0]]; biL[nt][1] = sB[3][oB[nt][1]];
            }
            #define SWEEP(D, A, B) \
                { _Pragma("unroll") for (int nt = 0; nt < NT; nt++) \
                    _Pragma("unroll") for (int mt = 0; mt < MT; mt++) \
                        mma_bf16(D[mt][nt], A[mt], B[nt]); }
            #define NEG(B) { _Pragma("unroll") for (int nt = 0; nt < NT; nt++) { \
                        B[nt][0] ^= 0x80008000u; B[nt][1] ^= 0x80008000u; } }
            if constexpr (MODE == 1) {
                SWEEP(accP, arH, brH);
                SWEEP(accI, arH, biH);
                SWEEP(accI, aiH, brH);
                NEG(biH); SWEEP(accP, aiH, biH);
                SWEEP(accP, arH, brL);
                SWEEP(accI, arH, biL);
                SWEEP(accI, aiH, brL);
                NEG(biL); SWEEP(accP, aiH, biL);
                SWEEP(accP, arL, brH);
                NEG(biH); SWEEP(accI, arL, biH);      // biH restored to original sign
                SWEEP(accI, aiL, brH);
                NEG(biH); SWEEP(accP, aiL, biH);
            } else {
                SWEEP(accP, arH, brH);
                SWEEP(accP, aiH, biH);
                SWEEP(accP, arH, brL);
                SWEEP(accP, aiH, biL);
                SWEEP(accP, arL, brH);
                SWEEP(accP, aiL, biH);
            }
            #undef SWEEP
            #undef NEG
        }
    };

    int nst = K >> 6;
    issue(0, 0);
    if (nst > 1) issue(64, 1);
    int buf = 0;
    for (int s = 0; s < nst; s++) {
        if (s + 1 < nst)
            asm volatile("cp.async.wait_group 1;" ::: "memory");
        else
            asm volatile("cp.async.wait_group 0;" ::: "memory");
        __syncthreads();
        compute(buf);
        __syncthreads();
        if (s + 2 < nst) issue((s + 2) << 6, buf);
        buf ^= 1;
    }

    #pragma unroll
    for (int mt = 0; mt < MT; mt++)
        #pragma unroll
        for (int nt = 0; nt < NT; nt++)
            #pragma unroll
            for (int e = 0; e < 4; e++) {
                int gm = m0 + mbase + mt * 16 + lg + (e >> 1) * 8;
                int gn = n0 + nbase + nt * 8 + lt * 2 + (e & 1);
                long long p = (long long)gm * sCm + gn;
                if constexpr (MODE == 1) {
                    float vr = accP[mt][nt][e];
                    float vi = accI[mt][nt][e];
                    if (biasR) { vr += biasR[gn]; vi += biasI[gn]; }
                    if (accumulate) { vr += Cr[p]; vi += Ci[p]; }
                    Cr[p] = vr; Ci[p] = vi;
                } else {
                    Cr[p] = alpha * accP[mt][nt][e];
                }
            }
}

// =================== legacy tf32 GEMM, REAL_A mode only (attn @ V) ===================
__global__ __launch_bounds__(256, 1) void cgemm_av(
    float* __restrict__ Cr, float* __restrict__ Ci,
    const float* __restrict__ Ar,
    const float* __restrict__ Br, const float* __restrict__ Bi,
    int M, int N, int K,
    long long sAm, long long sBk, long long sCm,
    long long aB1, long long aB2, long long bB1, long long bB2,
    long long cB1, long long cB2, int batchDiv)
{
    constexpr int BM = 128, BN = 64, BK = 32, LDS = 36;
    constexpr int MT = 2, NT = 4;
    constexpr int AT = BM * LDS, BT = BN * LDS;
    constexpr int STAGE = AT + 2 * BT;

    extern __shared__ uint32_t smem[];

    int z = blockIdx.z, zb = z / batchDiv, zh = z % batchDiv;
    Ar += (long long)zb * aB1 + (long long)zh * aB2;
    Br += (long long)zb * bB1 + (long long)zh * bB2;
    Bi += (long long)zb * bB1 + (long long)zh * bB2;
    Cr += (long long)zb * cB1 + (long long)zh * cB2;
    Ci += (long long)zb * cB1 + (long long)zh * cB2;

    int m0 = blockIdx.y * BM, n0 = blockIdx.x * BN;
    int tid = threadIdx.x;
    int lane = tid & 31, w = tid >> 5;
    int mbase = (w >> 1) * 32, nbase = (w & 1) * 32;
    int lg = lane >> 2, lt = lane & 3;

    float accP[MT][NT][4], accI[MT][NT][4];
    #pragma unroll
    for (int mt = 0; mt < MT; mt++)
        #pragma unroll
        for (int nt = 0; nt < NT; nt++)
            #pragma unroll
            for (int e = 0; e < 4; e++) { accP[mt][nt][e] = 0.f; accI[mt][nt][e] = 0.f; }

    float4 pA[4], pB[2][2];

    auto ldg = [&](int k0) {
        #pragma unroll
        for (int i = 0; i < 4; i++) {
            int idx = i * 256 + tid;
            int row = idx >> 3, c4 = idx & 7;
            pA[i] = *(const float4*)(Ar + (long long)(m0 + row) * sAm + k0 + c4 * 4);
        }
        #pragma unroll
        for (int c = 0; c < 2; c++) {
            const float* G = c ? Bi : Br;
            #pragma unroll
            for (int i = 0; i < 2; i++) {
                int idx = i * 256 + tid;
                int k = idx >> 4, c4 = idx & 15;
                pB[c][i] = *(const float4*)(G + (long long)(k0 + k) * sBk + n0 + c4 * 4);
            }
        }
    };
    auto sts = [&](uint32_t* base) {
        #pragma unroll
        for (int i = 0; i < 4; i++) {
            int idx = i * 256 + tid;
            int row = idx >> 3, c4 = idx & 7;
            float4 v = pA[i];
            uint32_t* p = base + row * LDS + c4 * 4;
            p[0] = f2tf32(v.x); p[1] = f2tf32(v.y);
            p[2] = f2tf32(v.z); p[3] = f2tf32(v.w);
        }
        #pragma unroll
        for (int c = 0; c < 2; c++) {
            uint32_t* SH = base + AT + c * BT;
            #pragma unroll
            for (int i = 0; i < 2; i++) {
                int idx = i * 256 + tid;
                int k = idx >> 4, c4 = idx & 15;
                float4 v = pB[c][i];
                float xs[4] = { v.x, v.y, v.z, v.w };
                #pragma unroll
                for (int j = 0; j < 4; j++)
                    SH[(c4 * 4 + j) * LDS + k] = f2tf32(xs[j]);
            }
        }
    };
    auto compute = [&](const uint32_t* base) {
        const uint32_t* sAr = base;
        const uint32_t* sBr = base + AT;
        const uint32_t* sBi = sBr + BT;
        #pragma unroll
        for (int kk = 0; kk < BK; kk += 8) {
            uint32_t ar[MT][4], br[NT][2], bi[NT][2];
            #pragma unroll
            for (int mt = 0; mt < MT; mt++) {
                int o0 = (mbase + mt * 16 + lg) * LDS + kk + lt;
                int o1 = o0 + 8 * LDS;
                ar[mt][0] = sAr[o0];   ar[mt][1] = sAr[o1];
                ar[mt][2] = sAr[o0+4]; ar[mt][3] = sAr[o1+4];
            }
            #pragma unroll
            for (int nt = 0; nt < NT; nt++) {
                int o0 = (nbase + nt * 8 + lg) * LDS + kk + lt;
                br[nt][0] = sBr[o0]; br[nt][1] = sBr[o0+4];
                bi[nt][0] = sBi[o0]; bi[nt][1] = sBi[o0+4];
            }
            #pragma unroll
            for (int nt = 0; nt < NT; nt++)
                #pragma unroll
                for (int mt = 0; mt < MT; mt++) {
                    mma_tf32(accP[mt][nt], ar[mt], br[nt]);
                    mma_tf32(accI[mt][nt], ar[mt], bi[nt]);
                }
        }
    };

    uint32_t* cur = smem;
    uint32_t* nxt = smem + STAGE;
    ldg(0);
    sts(cur);
    __syncthreads();
    for (int k0 = 0;;) {
        int kn = k0 + BK;
        bool more = kn < K;
        if (more) ldg(kn);
        compute(cur);
        if (!more) break;
        sts(nxt);
        __syncthreads();
        uint32_t* t = cur; cur = nxt; nxt = t;
        k0 = kn;
    }

    #pragma unroll
    for (int mt = 0; mt < MT; mt++)
        #pragma unroll
        for (int nt = 0; nt < NT; nt++)
            #pragma unroll
            for (int e = 0; e < 4; e++) {
                int gm = m0 + mbase + mt * 16 + lg + (e >> 1) * 8;
                int gn = n0 + nbase + nt * 8 + lt * 2 + (e & 1);
                long long p = (long long)gm * sCm + gn;
                Cr[p] = accP[mt][nt][e];
                Ci[p] = accI[mt][nt][e];
            }
}

// ---------------- coalesced 1024-pt FFT, twiddle table, 8 cols/block ----------------
#define FFT_COLS 8
#define FFT_LDP  1025
__global__ __launch_bounds__(256) void fft8_kernel(float* __restrict__ re,
                                                   float* __restrict__ im,
                                                   int inverse)
{
    extern __shared__ float fs[];
    float* sr = fs;
    float* si = fs + FFT_COLS * FFT_LDP;
    __shared__ float twr[512], twi[512];
    int blk = blockIdx.x;
    int b  = blk / (D_MODEL / FFT_COLS);
    int d0 = (blk % (D_MODEL / FFT_COLS)) * FFT_COLS;
    long long base = (long long)b * SEQ * D_MODEL + d0;
    int tid = threadIdx.x;

    float sgn = inverse ? 6.283185307179586f : -6.283185307179586f;
    #pragma unroll
    for (int j = 0; j < 2; j++) {
        int idx = j * 256 + tid;
        float ang = sgn * (float)idx * (1.0f / 1024.0f);
        float cs, sn;
        sincosf(ang, &sn, &cs);
        twr[idx] = cs; twi[idx] = sn;
    }

    #pragma unroll
    for (int i = 0; i < 8; i++) {
        int idx = i * 256 + tid;
        int row = idx >> 1, h = (idx & 1) * 4;
        int br = __brev((unsigned)row) >> 22;
        float4 vr = *(const float4*)(re + base + (long long)row * D_MODEL + h);
        float4 vi = *(const float4*)(im + base + (long long)row * D_MODEL + h);
        sr[(h+0)*FFT_LDP + br] = vr.x; sr[(h+1)*FFT_LDP + br] = vr.y;
        sr[(h+2)*FFT_LDP + br] = vr.z; sr[(h+3)*FFT_LDP + br] = vr.w;
        si[(h+0)*FFT_LDP + br] = vi.x; si[(h+1)*FFT_LDP + br] = vi.y;
        si[(h+2)*FFT_LDP + br] = vi.z; si[(h+3)*FFT_LDP + br] = vi.w;
    }
    __syncthreads();

    #pragma unroll
    for (int s = 1; s <= 10; s++) {
        int half = 1 << (s - 1);
        #pragma unroll
        for (int i = 0; i < 16; i++) {
            int idx = i * 256 + tid;
            int j = idx >> 3, c = idx & 7;
            int pos = j & (half - 1);
            int g = j >> (s - 1);
            int i0 = g * (half << 1) + pos, i1 = i0 + half;
            int tw = pos << (10 - s);
            float cs = twr[tw], sn = twi[tw];
            float* pr = sr + c * FFT_LDP;
            float* pi = si + c * FFT_LDP;
            float ur = pr[i0], ui = pi[i0];
            float vr = pr[i1], vi = pi[i1];
            float tr = cs * vr - sn * vi;
            float ti = cs * vi + sn * vr;
            pr[i0] = ur + tr; pi[i0] = ui + ti;
            pr[i1] = ur - tr; pi[i1] = ui - ti;
        }
        __syncthreads();
    }

    float sc = inverse ? (1.0f / 1024.0f) : 1.0f;
    #pragma unroll
    for (int i = 0; i < 8; i++) {
        int idx = i * 256 + tid;
        int row = idx >> 1, h = (idx & 1) * 4;
        float4 vr, vi;
        vr.x = sr[(h+0)*FFT_LDP + row] * sc; vr.y = sr[(h+1)*FFT_LDP + row] * sc;
        vr.z = sr[(h+2)*FFT_LDP + row] * sc; vr.w = sr[(h+3)*FFT_LDP + row] * sc;
        vi.x = si[(h+0)*FFT_LDP + row] * sc; vi.y = si[(h+1)*FFT_LDP + row] * sc;
        vi.z = si[(h+2)*FFT_LDP + row] * sc; vi.w = si[(h+3)*FFT_LDP + row] * sc;
        *(float4*)(re + base + (long long)row * D_MODEL + h) = vr;
        *(float4*)(im + base + (long long)row * D_MODEL + h) = vi;
    }
}
#define FFT_SMEM (2 * FFT_COLS * FFT_LDP * 4)

// ---------------- row softmax over 1024 columns ----------------
__global__ __launch_bounds__(256) void softmax_kernel(float* __restrict__ S)
{
    long long row = blockIdx.x;
    float* p = S + row*1024;
    int t = threadIdx.x;
    __shared__ float red[256];

    float vals[4];
    float m = -1e30f;
    #pragma unroll
    for (int i = 0; i < 4; i++) { vals[i] = p[t + i*256]; m = fmaxf(m, vals[i]); }
    red[t] = m; __syncthreads();
    for (int s = 128; s > 0; s >>= 1) { if (t < s) red[t] = fmaxf(red[t], red[t+s]); __syncthreads(); }
    m = red[0]; __syncthreads();

    float sum = 0.f;
    #pragma unroll
    for (int i = 0; i < 4; i++) { vals[i] = expf(vals[i] - m); sum += vals[i]; }
    red[t] = sum; __syncthreads();
    for (int s = 128; s > 0; s >>= 1) { if (t < s) red[t] += red[t+s]; __syncthreads(); }
    float inv = 1.0f / red[0];
    #pragma unroll
    for (int i = 0; i < 4; i++) p[t + i*256] = vals[i]*inv;
}

// ---------------- elementwise helpers ----------------
__global__ void copy_kernel(float* __restrict__ y, const float* __restrict__ x, long long n)
{
    long long i = (long long)blockIdx.x*blockDim.x + threadIdx.x;
    if (i < n) y[i] = x[i];
}
__global__ void cvt_tf32_kernel(uint32_t* __restrict__ dst, const float* __restrict__ src,
                                long long n4)
{
    long long i = (long long)blockIdx.x*blockDim.x + threadIdx.x;
    if (i < n4) {
        float4 v = ((const float4*)src)[i];
        uint4 o;
        o.x = f2tf32(v.x); o.y = f2tf32(v.y);
        o.z = f2tf32(v.z); o.w = f2tf32(v.w);
        ((uint4*)dst)[i] = o;
    }
}
// bf16 hi/lo split: hi = bf16(x), lo = bf16(x - hi); packed 2 bf16 per u32, k-contiguous
__global__ void split_bf16_kernel(uint32_t* __restrict__ hi, uint32_t* __restrict__ lo,
                                  const float* __restrict__ src, long long n4)
{
    long long i = (long long)blockIdx.x*blockDim.x + threadIdx.x;
    if (i < n4) {
        float4 v = ((const float4*)src)[i];
        uint32_t h0 = pack_pair(v.x, v.y);
        uint32_t h1 = pack_pair(v.z, v.w);
        float fx = __uint_as_float(h0 << 16);
        float fy = __uint_as_float(h0 & 0xFFFF0000u);
        float fz = __uint_as_float(h1 << 16);
        float fw = __uint_as_float(h1 & 0xFFFF0000u);
        uint32_t l0 = pack_pair(v.x - fx, v.y - fy);
        uint32_t l1 = pack_pair(v.z - fz, v.w - fw);
        ((uint2*)hi)[i] = make_uint2(h0, h1);
        ((uint2*)lo)[i] = make_uint2(l0, l1);
    }
}
__global__ void scale_tf32_kernel(uint32_t* __restrict__ y, const float* __restrict__ x,
                                  const float* __restrict__ dt, long long n)
{
    long long i = (long long)blockIdx.x*blockDim.x + threadIdx.x;
    if (i < n) y[i] = f2tf32(x[i]*dt[0]);
}
// D = U - I with U ~ I - E/2 - i M:  Dr = tf32(-E/2), Di = -tf32(M)
__global__ void buildD_kernel(uint32_t* __restrict__ Dr, uint32_t* __restrict__ Di,
                              const uint32_t* __restrict__ tM, const float* __restrict__ E,
                              long long n)
{
    long long i = (long long)blockIdx.x*blockDim.x + threadIdx.x;
    if (i < n) {
        Dr[i] = f2tf32(-0.5f * E[i]);
        Di[i] = tM[i] ^ 0x80000000u;
    }
}

// ---------------- host orchestration ----------------
static void cgc(int mode, float* Cr, float* Ci,
    const uint32_t* Ar, const uint32_t* Ai,
    const uint32_t* Br, const uint32_t* Bi,
    int M, int N, int K, long long sAm, long long sBn, long long sCm,
    float alpha, int acc,
    const float* bR = nullptr, const float* bI = nullptr, int gelu = 0)
{
    dim3 grid(N / 64, M / 128);
    if (mode == 1) {
        size_t sh = 2 * 2 * (128*32 + 64*32) * 4;
        cgemm_c<1><<<grid, 256, sh>>>(Cr, Ci, Ar, Ai, Br, Bi, M, N, K,
                                      sAm, sBn, sCm, alpha, acc, bR, bI, gelu);
    } else {
        size_t sh = 2 * (128*32 + 64*32) * 4;
        cgemm_c<0><<<grid, 256, sh>>>(Cr, Ci, Ar, Ai, Br, Bi, M, N, K,
                                      sAm, sBn, sCm, alpha, acc, bR, bI, gelu);
    }
}

static void cvt(uint32_t* dst, const float* src, long long n)
{
    long long n4 = n >> 2;
    cvt_tf32_kernel<<<(int)((n4 + 255) / 256), 256>>>(dst, src, n4);
}
static void splitp(uint32_t* hi, uint32_t* lo, const float* src, long long n)
{
    long long n4 = n >> 2;
    split_bf16_kernel<<<(int)((n4 + 255) / 256), 256>>>(hi, lo, src, n4);
}

#define TGQ_SMEM (2 * (4 * 128 * 32 + 4 * 64 * 32) * 4)   // 196608

extern "C" void kernel_launch(void* const* d_in, const int* in_sizes, int n_in,
                              void* d_out, int out_size)
{
    cudaFuncSetAttribute(cgemm_c<1>, cudaFuncAttributeMaxDynamicSharedMemorySize, 98304);
    cudaFuncSetAttribute(cgemm_c<0>, cudaFuncAttributeMaxDynamicSharedMemorySize, 49152);
    cudaFuncSetAttribute(cgemm_q<1>, cudaFuncAttributeMaxDynamicSharedMemorySize, TGQ_SMEM);
    cudaFuncSetAttribute(cgemm_q<2>, cudaFuncAttributeMaxDynamicSharedMemorySize, TGQ_SMEM);
    cudaFuncSetAttribute(cgemm_av,  cudaFuncAttributeMaxDynamicSharedMemorySize, 73728);
    cudaFuncSetAttribute(fft8_kernel, cudaFuncAttributeMaxDynamicSharedMemorySize, FFT_SMEM);

    const float* x_real = (const float*)d_in[0];
    const float* x_imag = (const float*)d_in[1];
    const float* Wr_q = (const float*)d_in[2];   const float* Wi_q = (const float*)d_in[3];
    const float* br_q = (const float*)d_in[4];   const float* bi_q = (const float*)d_in[5];
    const float* Wr_k = (const float*)d_in[6];   const float* Wi_k = (const float*)d_in[7];
    const float* br_k = (const float*)d_in[8];   const float* bi_k = (const float*)d_in[9];
    const float* Wr_v = (const float*)d_in[10];  const float* Wi_v = (const float*)d_in[11];
    const float* br_v = (const float*)d_in[12];  const float* bi_v = (const float*)d_in[13];
    const float* Wr_o = (const float*)d_in[14];  const float* Wi_o = (const float*)d_in[15];
    const float* br_o = (const float*)d_in[16];  const float* bi_o = (const float*)d_in[17];
    const float* Wr_f1 = (const float*)d_in[18]; const float* Wi_f1 = (const float*)d_in[19];
    const float* br_f1 = (const float*)d_in[20]; const float* bi_f1 = (const float*)d_in[21];
    const float* Wr_f2 = (const float*)d_in[22]; const float* Wi_f2 = (const float*)d_in[23];
    const float* br_f2 = (const float*)d_in[24]; const float* bi_f2 = (const float*)d_in[25];
    const float* Hmat = (const float*)d_in[26];
    const float* dtp  = (const float*)d_in[27];

    float* outRe = (float*)d_out;
    float* outIm = outRe + (long long)ROWS*D_MODEL;

    float *Qr,*Qi,*Kr,*Ki,*Vr,*Vi,*Xr,*Xi,*Or,*Oi,*Hr,*Hi,*Sc,*Ta;
    uint32_t *tAr,*tAi,*tBr,*tBi,*tM;
    cudaGetSymbolAddress((void**)&Qr, g_Qr); cudaGetSymbolAddress((void**)&Qi, g_Qi);
    cudaGetSymbolAddress((void**)&Kr, g_Kr); cudaGetSymbolAddress((void**)&Ki, g_Ki);
    cudaGetSymbolAddress((void**)&Vr, g_Vr); cudaGetSymbolAddress((void**)&Vi, g_Vi);
    cudaGetSymbolAddress((void**)&Xr, g_Xr); cudaGetSymbolAddress((void**)&Xi, g_Xi);
    cudaGetSymbolAddress((void**)&Or, g_Or); cudaGetSymbolAddress((void**)&Oi, g_Oi);
    cudaGetSymbolAddress((void**)&Hr, g_Hr); cudaGetSymbolAddress((void**)&Hi, g_Hi);
    cudaGetSymbolAddress((void**)&Sc, g_Sc); cudaGetSymbolAddress((void**)&Ta, g_Ta);
    cudaGetSymbolAddress((void**)&tAr, g_tAr); cudaGetSymbolAddress((void**)&tAi, g_tAi);
    cudaGetSymbolAddress((void**)&tBr, g_tBr); cudaGetSymbolAddress((void**)&tBi, g_tBi);
    cudaGetSymbolAddress((void**)&tM,  g_tM);

    const long long ND = (long long)ROWS*D_MODEL;
    const long long NH = (long long)ROWS*HIDDEN;
    const long long DD = (long long)D_MODEL*D_MODEL;
    const long long DH = (long long)D_MODEL*HIDDEN;
    const long long hM = (long long)SEQ*SEQ;
    const long long ND2 = ND >> 1;     // u32 per bf16 plane of an ND array
    const long long DD2 = DD >> 1;
    const int FFT_GRID = NBATCH * (D_MODEL / FFT_COLS);
    copy_kernel<<<(int)((ND+255)/256), 256>>>(Xr, x_real, ND);
    copy_kernel<<<(int)((ND+255)/256), 256>>>(Xi, x_imag, ND);

    // ---- Q/K projections: precise split-bf16 via cp.async engine ----
    splitp(tAr, tAr + ND2, Xr, ND);            // X hiR, loR
    splitp(tAi, tAi + ND2, Xi, ND);            // X hiI, loI
    splitp(tBr, tBr + DD2, Wr_q, DD);          // Wq hiR, loR
    splitp(tBr + 2*DD2, tBr + 3*DD2, Wi_q, DD);// Wq hiI, loI
    splitp(tBi, tBi + DD2, Wr_k, DD);          // Wk planes
    splitp(tBi + 2*DD2, tBi + 3*DD2, Wi_k, DD);
    {
        dim3 grid(D_MODEL/64, ROWS/128);
        cgemm_q<1><<<grid, 512, TGQ_SMEM>>>(Qr, Qi,
            tAr, tAr + ND2, tAi, tAi + ND2,
            tBr, tBr + DD2, tBr + 2*DD2, tBr + 3*DD2,
            ROWS, D_MODEL, D_MODEL, D_MODEL, D_MODEL, D_MODEL,
            0,0,0,0,0,0,1, 1.f, 0, br_q, bi_q);
        cgemm_q<1><<<grid, 512, TGQ_SMEM>>>(Kr, Ki,
            tAr, tAr + ND2, tAi, tAi + ND2,
            tBi, tBi + DD2, tBi + 2*DD2, tBi + 3*DD2,
            ROWS, D_MODEL, D_MODEL, D_MODEL, D_MODEL, D_MODEL,
            0,0,0,0,0,0,1, 1.f, 0, br_k, bi_k);
    }

    // ---- V projection (cp.async tf32 engine) ----
    cvt(tAr, Xr, ND); cvt(tAi, Xi, ND);
    cvt(tBr, Wr_v, DD); cvt(tBi, Wi_v, DD);
    cgc(1, Vr,Vi, tAr,tAi, tBr,tBi, ROWS,D_MODEL,D_MODEL, D_MODEL,D_MODEL,D_MODEL,
        1.f,0, br_v,bi_v,0);

    // ---- forward FFT along sequence axis ----
    fft8_kernel<<<FFT_GRID, 256, FFT_SMEM>>>(Qr, Qi, 0);
    fft8_kernel<<<FFT_GRID, 256, FFT_SMEM>>>(Kr, Ki, 0);
    fft8_kernel<<<FFT_GRID, 256, FFT_SMEM>>>(Vr, Vi, 0);

    // ---- scores = scale*Re(Qf conj(Kf)); precise, batched over (b,h) ----
    splitp(tAr, tAr + ND2, Qr, ND);
    splitp(tAi, tAi + ND2, Qi, ND);
    splitp(tBr, tBr + ND2, Kr, ND);
    splitp(tBr + 2*ND2, tBr + 3*ND2, Ki, ND);
    {
        dim3 grid(SEQ/64, SEQ/128, NBATCH*NHEADS);
        cgemm_q<2><<<grid, 512, TGQ_SMEM>>>(Sc, nullptr,
            tAr, tAr + ND2, tAi, tAi + ND2,
            tBr, tBr + ND2, tBr + 2*ND2, tBr + 3*ND2,
            SEQ, SEQ, DHEAD, D_MODEL, D_MODEL, SEQ,
            (long long)SEQ*D_MODEL, DHEAD,
            (long long)SEQ*D_MODEL, DHEAD,
            (long long)NHEADS*hM, hM, NHEADS,
            0.125f, 0, nullptr, nullptr);
    }

    softmax_kernel<<<NBATCH*NHEADS*SEQ, 256>>>(Sc);

    // ---- out_f = attn @ Vf (legacy path; B n-contiguous) ----
    cgemm_av<<<dim3(1, SEQ/128, NBATCH*NHEADS), 256, 73728>>>(
        Or, Oi, Sc, Vr, Vi, SEQ, DHEAD, SEQ,
        SEQ, D_MODEL, D_MODEL,
        (long long)NHEADS*hM, hM,
        (long long)SEQ*D_MODEL, DHEAD,
        (long long)SEQ*D_MODEL, DHEAD, NHEADS);

    // ---- inverse FFT ----
    fft8_kernel<<<FFT_GRID, 256, FFT_SMEM>>>(Or, Oi, 1);

    // ---- x += clin(out, Wo) ----
    cvt(tAr, Or, ND); cvt(tAi, Oi, ND);
    cvt(tBr, Wr_o, DD); cvt(tBi, Wi_o, DD);
    cgc(1, Xr,Xi, tAr,tAi, tBr,tBi, ROWS,D_MODEL,D_MODEL, D_MODEL,D_MODEL,D_MODEL,
        1.f,1, br_o,bi_o,0);

    // ---- FFN ----
    cvt(tAr, Xr, ND); cvt(tAi, Xi, ND);
    cvt(tBr, Wr_f1, DH); cvt(tBi, Wi_f1, DH);
    cgc(1, Hr,Hi, tAr,tAi, tBr,tBi, ROWS,HIDDEN,D_MODEL, D_MODEL,D_MODEL,HIDDEN,
        1.f,0, br_f1,bi_f1,1);
    cvt(tAr, Hr, NH); cvt(tAi, Hi, NH);
    cvt(tBr, Wr_f2, DH); cvt(tBi, Wi_f2, DH);
    cgc(1, Xr,Xi, tAr,tAi, tBr,tBi, ROWS,D_MODEL,HIDDEN, HIDDEN,HIDDEN,D_MODEL,
        1.f,1, br_f2,bi_f2,0);

    // ---- U = expm(-i H dt) ~ I - E/2 - i M  (E = M^2, M = H dt) ----
    scale_tf32_kernel<<<(int)((DD+255)/256), 256>>>(tM, Hmat, dtp, DD);
    cgc(0, Ta,nullptr, tM,nullptr, tM,nullptr, D_MODEL,D_MODEL,D_MODEL,
        D_MODEL,D_MODEL,D_MODEL, 1.f,0);
    buildD_kernel<<<(int)((DD+255)/256), 256>>>(tBr, tBi, tM, Ta, DD);

    // ---- out = x + x @ D (D symmetric, small) ----
    copy_kernel<<<(int)((ND+255)/256), 256>>>(outRe, Xr, ND);
    copy_kernel<<<(int)((ND+255)/256), 256>>>(outIm, Xi, ND);
    cvt(tAr, Xr, ND); cvt(tAi, Xi, ND);
    cgc(1, outRe,outIm, tAr,tAi, tBr,tBi, ROWS,D_MODEL,D_MODEL, D_MODEL,D_MODEL,D_MODEL,
        1.f,1, nullptr,nullptr,0);
}

// round 16
// speedup vs baseline: 1.1867x; 1.0027x over previous
#include <cuda_runtime.h>
#include <cuda_bf16.h>
#include <math.h>
#include <stdint.h>

#define SEQ     1024
#define D_MODEL 1024
#define NHEADS  16
#define DHEAD   64
#define HIDDEN  4096
#define NBATCH  2
#define ROWS    (NBATCH*SEQ)   // 2048

// ---------------- scratch (device statics; no allocation) ----------------
__device__ __align__(128) float g_Qr[ROWS*D_MODEL];
__device__ __align__(128) float g_Qi[ROWS*D_MODEL];
__device__ __align__(128) float g_Kr[ROWS*D_MODEL];
__device__ __align__(128) float g_Ki[ROWS*D_MODEL];
__device__ __align__(128) float g_Vr[ROWS*D_MODEL];
__device__ __align__(128) float g_Vi[ROWS*D_MODEL];
__device__ __align__(128) float g_Xr[ROWS*D_MODEL];
__device__ __align__(128) float g_Xi[ROWS*D_MODEL];
__device__ __align__(128) float g_Or[ROWS*D_MODEL];
__device__ __align__(128) float g_Oi[ROWS*D_MODEL];
__device__ __align__(128) float g_Hr[ROWS*HIDDEN];
__device__ __align__(128) float g_Hi[ROWS*HIDDEN];
__device__ __align__(128) float g_Sc[NBATCH*NHEADS*SEQ*SEQ];
__device__ __align__(128) float g_Ta[D_MODEL*D_MODEL];
// operand scratch (tf32 u32 payload OR packed bf16x2 planes)
__device__ __align__(128) uint32_t g_tAr[ROWS*HIDDEN];
__device__ __align__(128) uint32_t g_tAi[ROWS*HIDDEN];
__device__ __align__(128) uint32_t g_tBr[HIDDEN*D_MODEL];
__device__ __align__(128) uint32_t g_tBi[HIDDEN*D_MODEL];
__device__ __align__(128) uint32_t g_tM [D_MODEL*D_MODEL];
__device__ __align__(128) uint32_t g_tXr[ROWS*D_MODEL];
__device__ __align__(128) uint32_t g_tXi[ROWS*D_MODEL];
__device__ __align__(128) uint32_t g_tHr[ROWS*HIDDEN];
__device__ __align__(128) uint32_t g_tHi[ROWS*HIDDEN];

// ---------------- low-level helpers ----------------
__device__ __forceinline__ uint32_t f2tf32(float x) {
    uint32_t r;
    asm("cvt.rna.tf32.f32 %0, %1;" : "=r"(r) : "f"(x));
    return r;
}
__device__ __forceinline__ void mma_tf32(float* d, const uint32_t* a, const uint32_t* b) {
    asm volatile(
        "mma.sync.aligned.m16n8k8.row.col.f32.tf32.tf32.f32 "
        "{%0,%1,%2,%3}, {%4,%5,%6,%7}, {%8,%9}, {%0,%1,%2,%3};\n"
        : "+f"(d[0]), "+f"(d[1]), "+f"(d[2]), "+f"(d[3])
        : "r"(a[0]), "r"(a[1]), "r"(a[2]), "r"(a[3]), "r"(b[0]), "r"(b[1]));
}
__device__ __forceinline__ void mma_bf16(float* d, const uint32_t* a, const uint32_t* b) {
    asm volatile(
        "mma.sync.aligned.m16n8k16.row.col.f32.bf16.bf16.f32 "
        "{%0,%1,%2,%3}, {%4,%5,%6,%7}, {%8,%9}, {%0,%1,%2,%3};\n"
        : "+f"(d[0]), "+f"(d[1]), "+f"(d[2]), "+f"(d[3])
        : "r"(a[0]), "r"(a[1]), "r"(a[2]), "r"(a[3]), "r"(b[0]), "r"(b[1]));
}
__device__ __forceinline__ uint32_t pack_pair(float x0, float x1) {
    uint32_t r;
    asm("cvt.rn.bf16x2.f32 %0, %1, %2;" : "=r"(r) : "f"(x1), "f"(x0));
    return r;
}
__device__ __forceinline__ void split2g(float x, float y, uint32_t& h, uint32_t& l) {
    h = pack_pair(x, y);
    float fx = __uint_as_float(h << 16);
    float fy = __uint_as_float(h & 0xFFFF0000u);
    l = pack_pair(x - fx, y - fy);
}
__device__ __forceinline__ float gelu_f(float v) {
    return 0.5f * v * (1.0f + erff(v * 0.7071067811865476f));
}
__device__ __forceinline__ uint32_t smem_addr_of(const void* p) {
    return (uint32_t)__cvta_generic_to_shared(p);
}
#define CP16(dst, src) \
    asm volatile("cp.async.cg.shared.global [%0], [%1], 16;" :: "r"(dst), "l"(src) : "memory")

// =================== cp.async tf32 GEMM (pre-rounded operands, fused epilogue) ===================
// MODE 0: REAL  C = alpha*(Ar.Br^T) (+C)
// MODE 1: COMPLEX Cr = Ar.Br^T - Ai.Bi^T (+bias,gelu)(+C or +add[]); Ci = ...
//   optional: outTr/outTi (tf32 copy of result), dupR/dupI (duplicate fp32 store)
template<int MODE>
__global__ __launch_bounds__(256, 2) void cgemm_c(
    float* __restrict__ Cr, float* __restrict__ Ci,
    const uint32_t* __restrict__ Ar, const uint32_t* __restrict__ Ai,
    const uint32_t* __restrict__ Br, const uint32_t* __restrict__ Bi,
    int M, int N, int K,
    long long sAm, long long sBn, long long sCm,
    float alpha, int accumulate,
    const float* __restrict__ biasR, const float* __restrict__ biasI, int gelu,
    uint32_t* __restrict__ outTr, uint32_t* __restrict__ outTi,
    const float* __restrict__ addR, const float* __restrict__ addI,
    float* __restrict__ dupR, float* __restrict__ dupI)
{
    constexpr int nAB = (MODE == 1) ? 2 : 1;
    constexpr int AW = 128 * 32;
    constexpr int BW = 64 * 32;
    constexpr int STAGE = nAB * (AW + BW);
    constexpr int MT = 2, NT = 4;

    extern __shared__ uint32_t sm[];

    int tid = threadIdx.x, lane = tid & 31, w = tid >> 5;
    int m0 = blockIdx.y * 128, n0 = blockIdx.x * 64;
    int mbase = (w >> 1) * 32, nbase = (w & 1) * 32;
    int lg = lane >> 2, lt = lane & 3;

    float accP[MT][NT][4], accI[MT][NT][4];
    #pragma unroll
    for (int mt = 0; mt < MT; mt++)
        #pragma unroll
        for (int nt = 0; nt < NT; nt++)
            #pragma unroll
            for (int e = 0; e < 4; e++) { accP[mt][nt][e] = 0.f; accI[mt][nt][e] = 0.f; }

    auto issue = [&](int k0, int buf) {
        uint32_t* base = sm + buf * STAGE;
        #pragma unroll
        for (int p = 0; p < nAB; p++) {
            const uint32_t* G = p ? Ai : Ar;
            uint32_t* S = base + p * AW;
            #pragma unroll
            for (int i = 0; i < 4; i++) {
                int idx = i * 256 + tid;
                int row = idx >> 3, c = idx & 7;
                const uint32_t* src = G + (long long)(m0 + row) * sAm + k0 + c * 4;
                CP16(smem_addr_of(S + row * 32 + ((c ^ (row & 7)) << 2)), src);
            }
        }
        #pragma unroll
        for (int p = 0; p < nAB; p++) {
            const uint32_t* G = p ? Bi : Br;
            uint32_t* S = base + nAB * AW + p * BW;
            #pragma unroll
            for (int i = 0; i < 2; i++) {
                int idx = i * 256 + tid;
                int row = idx >> 3, c = idx & 7;
                const uint32_t* src = G + (long long)(n0 + row) * sBn + k0 + c * 4;
                CP16(smem_addr_of(S + row * 32 + ((c ^ (row & 7)) << 2)), src);
            }
        }
        asm volatile("cp.async.commit_group;" ::: "memory");
    };

    auto compute = [&](int buf) {
        uint32_t* base = sm + buf * STAGE;
        const uint32_t* sAr = base;
        const uint32_t* sAi = base + AW;
        const uint32_t* sBr = base + nAB * AW;
        const uint32_t* sBi = sBr + BW;
        #pragma unroll
        for (int kk = 0; kk < 32; kk += 8) {
            int ck0 = kk >> 2, ck1 = ck0 + 1;
            uint32_t ar[MT][4], br[NT][2];
            #pragma unroll
            for (int mt = 0; mt < MT; mt++) {
                int row = mbase + mt * 16 + lg;
                int o0 = row * 32 + ((ck0 ^ (row & 7)) << 2) + lt;
                int o1 = row * 32 + ((ck1 ^ (row & 7)) << 2) + lt;
                ar[mt][0] = sAr[o0];       ar[mt][1] = sAr[o0 + 256];
                ar[mt][2] = sAr[o1];       ar[mt][3] = sAr[o1 + 256];
            }
            #pragma unroll
            for (int nt = 0; nt < NT; nt++) {
                int row = nbase + nt * 8 + lg;
                int o0 = row * 32 + ((ck0 ^ (row & 7)) << 2) + lt;
                int o1 = row * 32 + ((ck1 ^ (row & 7)) << 2) + lt;
                br[nt][0] = sBr[o0]; br[nt][1] = sBr[o1];
            }
            #pragma unroll
            for (int nt = 0; nt < NT; nt++)
                #pragma unroll
                for (int mt = 0; mt < MT; mt++)
                    mma_tf32(accP[mt][nt], ar[mt], br[nt]);
            if constexpr (MODE == 1) {
                uint32_t bi_[NT][2];
                #pragma unroll
                for (int nt = 0; nt < NT; nt++) {
                    int row = nbase + nt * 8 + lg;
                    int o0 = row * 32 + ((ck0 ^ (row & 7)) << 2) + lt;
                    int o1 = row * 32 + ((ck1 ^ (row & 7)) << 2) + lt;
                    bi_[nt][0] = sBi[o0]; bi_[nt][1] = sBi[o1];
                }
                #pragma unroll
                for (int nt = 0; nt < NT; nt++)
                    #pragma unroll
                    for (int mt = 0; mt < MT; mt++)
                        mma_tf32(accI[mt][nt], ar[mt], bi_[nt]);
                #pragma unroll
                for (int nt = 0; nt < NT; nt++) {
                    bi_[nt][0] ^= 0x80000000u; bi_[nt][1] ^= 0x80000000u;
                }
                uint32_t ai_[MT][4];
                #pragma unroll
                for (int mt = 0; mt < MT; mt++) {
                    int row = mbase + mt * 16 + lg;
                    int o0 = row * 32 + ((ck0 ^ (row & 7)) << 2) + lt;
                    int o1 = row * 32 + ((ck1 ^ (row & 7)) << 2) + lt;
                    ai_[mt][0] = sAi[o0];     ai_[mt][1] = sAi[o0 + 256];
                    ai_[mt][2] = sAi[o1];     ai_[mt][3] = sAi[o1 + 256];
                }
                #pragma unroll
                for (int nt = 0; nt < NT; nt++)
                    #pragma unroll
                    for (int mt = 0; mt < MT; mt++)
                        mma_tf32(accP[mt][nt], ai_[mt], bi_[nt]);
                #pragma unroll
                for (int nt = 0; nt < NT; nt++)
                    #pragma unroll
                    for (int mt = 0; mt < MT; mt++)
                        mma_tf32(accI[mt][nt], ai_[mt], br[nt]);
            }
        }
    };

    int nst = K >> 5;
    issue(0, 0);
    if (nst > 1) issue(32, 1);
    int buf = 0;
    for (int s = 0; s < nst; s++) {
        if (s + 1 < nst)
            asm volatile("cp.async.wait_group 1;" ::: "memory");
        else
            asm volatile("cp.async.wait_group 0;" ::: "memory");
        __syncthreads();
        compute(buf);
        __syncthreads();
        if (s + 2 < nst) issue((s + 2) << 5, buf);
        buf ^= 1;
    }

    #pragma unroll
    for (int mt = 0; mt < MT; mt++)
        #pragma unroll
        for (int nt = 0; nt < NT; nt++)
            #pragma unroll
            for (int e = 0; e < 4; e++) {
                int gm = m0 + mbase + mt * 16 + lg + (e >> 1) * 8;
                int gn = n0 + nbase + nt * 8 + lt * 2 + (e & 1);
                long long p = (long long)gm * sCm + gn;
                if constexpr (MODE == 1) {
                    float vr = accP[mt][nt][e];
                    float vi = accI[mt][nt][e];
                    if (biasR) { vr += biasR[gn]; vi += biasI[gn]; }
                    if (gelu)  { vr = gelu_f(vr); vi = gelu_f(vi); }
                    if (addR)  { vr += addR[p]; vi += addI[p]; }
                    else if (accumulate) { vr += Cr[p]; vi += Ci[p]; }
                    Cr[p] = vr; Ci[p] = vi;
                    if (outTr) { outTr[p] = f2tf32(vr); outTi[p] = f2tf32(vi); }
                    if (dupR)  { dupR[p] = vr; dupI[p] = vi; }
                } else {
                    float v = alpha * accP[mt][nt][e];
                    if (accumulate) v += Cr[p];
                    Cr[p] = v;
                }
            }
}

// =================== PRECISE cp.async split-bf16 GEMM, 512 threads ===================
template<int MODE>
__global__ __launch_bounds__(512, 1) void cgemm_q(
    float* __restrict__ Cr, float* __restrict__ Ci,
    const uint32_t* __restrict__ AhR, const uint32_t* __restrict__ AlR,
    const uint32_t* __restrict__ AhI, const uint32_t* __restrict__ AlI,
    const uint32_t* __restrict__ BhR, const uint32_t* __restrict__ BlR,
    const uint32_t* __restrict__ BhI, const uint32_t* __restrict__ BlI,
    int M, int N, int K,
    long long sAm, long long sBn, long long sCm,
    long long aB1, long long aB2, long long bB1, long long bB2,
    long long cB1, long long cB2, int batchDiv,
    float alpha, int accumulate,
    const float* __restrict__ biasR, const float* __restrict__ biasI)
{
    constexpr int AW = 128 * 32;
    constexpr int BW = 64 * 32;
    constexpr int STAGE = 4 * AW + 4 * BW;
    constexpr int MT = 2, NT = 2;

    extern __shared__ uint32_t sm[];

    int tid = threadIdx.x, lane = tid & 31, w = tid >> 5;
    int z = blockIdx.z, zb = z / batchDiv, zh = z % batchDiv;
    long long aOff = ((long long)zb * aB1 + (long long)zh * aB2) >> 1;
    long long bOff = ((long long)zb * bB1 + (long long)zh * bB2) >> 1;
    const uint32_t* pA[4] = { AhR + aOff, AlR + aOff, AhI + aOff, AlI + aOff };
    const uint32_t* pB[4] = { BhR + bOff, BlR + bOff, BhI + bOff, BlI + bOff };
    Cr += (long long)zb * cB1 + (long long)zh * cB2;
    if constexpr (MODE == 1) Ci += (long long)zb * cB1 + (long long)zh * cB2;

    int m0 = blockIdx.y * 128, n0 = blockIdx.x * 64;
    int mbase = (w >> 2) * 32, nbase = (w & 3) * 16;
    int lg = lane >> 2, lt = lane & 3;
    long long sAu = sAm >> 1, sBu = sBn >> 1;

    float accP[MT][NT][4], accI[MT][NT][4];
    #pragma unroll
    for (int mt = 0; mt < MT; mt++)
        #pragma unroll
        for (int nt = 0; nt < NT; nt++)
            #pragma unroll
            for (int e = 0; e < 4; e++) { accP[mt][nt][e] = 0.f; accI[mt][nt][e] = 0.f; }

    auto issue = [&](int k0, int buf) {
        uint32_t* base = sm + buf * STAGE;
        long long ku = k0 >> 1;
        #pragma unroll
        for (int p = 0; p < 4; p++) {
            #pragma unroll
            for (int i = 0; i < 2; i++) {
                int idx = i * 512 + tid;
                int row = idx >> 3, c = idx & 7;
                const uint32_t* src = pA[p] + (long long)(m0 + row) * sAu + ku + c * 4;
                CP16(smem_addr_of(base + p * AW + row * 32 + ((c ^ (row & 7)) << 2)), src);
            }
        }
        #pragma unroll
        for (int p = 0; p < 4; p++) {
            int row = tid >> 3, c = tid & 7;
            const uint32_t* src = pB[p] + (long long)(n0 + row) * sBu + ku + c * 4;
            CP16(smem_addr_of(base + 4 * AW + p * BW + row * 32 + ((c ^ (row & 7)) << 2)), src);
        }
        asm volatile("cp.async.commit_group;" ::: "memory");
    };

    auto compute = [&](int buf) {
        uint32_t* base = sm + buf * STAGE;
        const uint32_t* sA[4] = { base, base + AW, base + 2*AW, base + 3*AW };
        const uint32_t* sB[4] = { base + 4*AW, base + 4*AW + BW,
                                  base + 4*AW + 2*BW, base + 4*AW + 3*BW };
        #pragma unroll
        for (int c = 0; c < 4; c++) {
            int g0 = 2 * c, g1 = 2 * c + 1;
            int r0 = mbase + lg, r1 = r0 + 8, r2 = r0 + 16, r3 = r0 + 24;
            int oA[4][2];
            oA[0][0] = r0*32 + ((g0 ^ (r0&7))<<2) + lt; oA[0][1] = r0*32 + ((g1 ^ (r0&7))<<2) + lt;
            oA[1][0] = r1*32 + ((g0 ^ (r1&7))<<2) + lt; oA[1][1] = r1*32 + ((g1 ^ (r1&7))<<2) + lt;
            oA[2][0] = r2*32 + ((g0 ^ (r2&7))<<2) + lt; oA[2][1] = r2*32 + ((g1 ^ (r2&7))<<2) + lt;
            oA[3][0] = r3*32 + ((g0 ^ (r3&7))<<2) + lt; oA[3][1] = r3*32 + ((g1 ^ (r3&7))<<2) + lt;
            int rb0 = nbase + lg, rb1 = rb0 + 8;
            int oB[2][2];
            oB[0][0] = rb0*32 + ((g0 ^ (rb0&7))<<2) + lt; oB[0][1] = rb0*32 + ((g1 ^ (rb0&7))<<2) + lt;
            oB[1][0] = rb1*32 + ((g0 ^ (rb1&7))<<2) + lt; oB[1][1] = rb1*32 + ((g1 ^ (rb1&7))<<2) + lt;

            uint32_t arH[MT][4], arL[MT][4], aiH[MT][4], aiL[MT][4];
            #pragma unroll
            for (int mt = 0; mt < MT; mt++) {
                int ra = mt * 2, rbx = mt * 2 + 1;
                arH[mt][0] = sA[0][oA[ra][0]]; arH[mt][1] = sA[0][oA[rbx][0]];
                arH[mt][2] = sA[0][oA[ra][1]]; arH[mt][3] = sA[0][oA[rbx][1]];
                arL[mt][0] = sA[1][oA[ra][0]]; arL[mt][1] = sA[1][oA[rbx][0]];
                arL[mt][2] = sA[1][oA[ra][1]]; arL[mt][3] = sA[1][oA[rbx][1]];
                aiH[mt][0] = sA[2][oA[ra][0]]; aiH[mt][1] = sA[2][oA[rbx][0]];
                aiH[mt][2] = sA[2][oA[ra][1]]; aiH[mt][3] = sA[2][oA[rbx][1]];
                aiL[mt][0] = sA[3][oA[ra][0]]; aiL[mt][1] = sA[3][oA[rbx][0]];
                aiL[mt][2] = sA[3][oA[ra][1]]; aiL[mt][3] = sA[3][oA[rbx][1]];
            }
            uint32_t brH[NT][2], brL[NT][2], biH[NT][2], biL[NT][2];
            #pragma unroll
            for (int nt = 0; nt < NT; nt++) {
                brH[nt][0] = sB[0][oB[nt][0]]; brH[nt][1] = sB[0][oB[nt][1]];
                brL[nt][0] = sB[1][oB[nt][0]]; brL[nt][1] = sB[1][oB[nt][1]];
                biH[nt][0] = sB[2][oB[nt][0]]; biH[nt][1] = sB[2][oB[nt][1]];
                biL[nt][0] = sB[3][oB[nt][0]]; biL[nt][1] = sB[3][oB[nt][1]];
            }
            #define SWEEP(D, A, B) \
                { _Pragma("unroll") for (int nt = 0; nt < NT; nt++) \
                    _Pragma("unroll") for (int mt = 0; mt < MT; mt++) \
                        mma_bf16(D[mt][nt], A[mt], B[nt]); }
            #define NEG(B) { _Pragma("unroll") for (int nt = 0; nt < NT; nt++) { \
                        B[nt][0] ^= 0x80008000u; B[nt][1] ^= 0x80008000u; } }
            if constexpr (MODE == 1) {
                SWEEP(accP, arH, brH);
                SWEEP(accI, arH, biH);
                SWEEP(accI, aiH, brH);
                NEG(biH); SWEEP(accP, aiH, biH);
                SWEEP(accP, arH, brL);
                SWEEP(accI, arH, biL);
                SWEEP(accI, aiH, brL);
                NEG(biL); SWEEP(accP, aiH, biL);
                SWEEP(accP, arL, brH);
                NEG(biH); SWEEP(accI, arL, biH);
                SWEEP(accI, aiL, brH);
                NEG(biH); SWEEP(accP, aiL, biH);
            } else {
                SWEEP(accP, arH, brH);
                SWEEP(accP, aiH, biH);
                SWEEP(accP, arH, brL);
                SWEEP(accP, aiH, biL);
                SWEEP(accP, arL, brH);
                SWEEP(accP, aiL, biH);
            }
            #undef SWEEP
            #undef NEG
        }
    };

    int nst = K >> 6;
    issue(0, 0);
    if (nst > 1) issue(64, 1);
    int buf = 0;
    for (int s = 0; s < nst; s++) {
        if (s + 1 < nst)
            asm volatile("cp.async.wait_group 1;" ::: "memory");
        else
            asm volatile("cp.async.wait_group 0;" ::: "memory");
        __syncthreads();
        compute(buf);
        __syncthreads();
        if (s + 2 < nst) issue((s + 2) << 6, buf);
        buf ^= 1;
    }

    #pragma unroll
    for (int mt = 0; mt < MT; mt++)
        #pragma unroll
        for (int nt = 0; nt < NT; nt++)
            #pragma unroll
            for (int e = 0; e < 4; e++) {
                int gm = m0 + mbase + mt * 16 + lg + (e >> 1) * 8;
                int gn = n0 + nbase + nt * 8 + lt * 2 + (e & 1);
                long long p = (long long)gm * sCm + gn;
                if constexpr (MODE == 1) {
                    float vr = accP[mt][nt][e];
                    float vi = accI[mt][nt][e];
                    if (biasR) { vr += biasR[gn]; vi += biasI[gn]; }
                    if (accumulate) { vr += Cr[p]; vi += Ci[p]; }
                    Cr[p] = vr; Ci[p] = vi;
                } else {
                    Cr[p] = alpha * accP[mt][nt][e];
                }
            }
}

// =================== legacy tf32 GEMM, REAL_A mode only (attn @ V) ===================
__global__ __launch_bounds__(256, 1) void cgemm_av(
    float* __restrict__ Cr, float* __restrict__ Ci,
    const float* __restrict__ Ar,
    const float* __restrict__ Br, const float* __restrict__ Bi,
    int M, int N, int K,
    long long sAm, long long sBk, long long sCm,
    long long aB1, long long aB2, long long bB1, long long bB2,
    long long cB1, long long cB2, int batchDiv)
{
    constexpr int BM = 128, BN = 64, BK = 32, LDS = 36;
    constexpr int MT = 2, NT = 4;
    constexpr int AT = BM * LDS, BT = BN * LDS;
    constexpr int STAGE = AT + 2 * BT;

    extern __shared__ uint32_t smem[];

    int z = blockIdx.z, zb = z / batchDiv, zh = z % batchDiv;
    Ar += (long long)zb * aB1 + (long long)zh * aB2;
    Br += (long long)zb * bB1 + (long long)zh * bB2;
    Bi += (long long)zb * bB1 + (long long)zh * bB2;
    Cr += (long long)zb * cB1 + (long long)zh * cB2;
    Ci += (long long)zb * cB1 + (long long)zh * cB2;

    int m0 = blockIdx.y * BM, n0 = blockIdx.x * BN;
    int tid = threadIdx.x;
    int lane = tid & 31, w = tid >> 5;
    int mbase = (w >> 1) * 32, nbase = (w & 1) * 32;
    int lg = lane >> 2, lt = lane & 3;

    float accP[MT][NT][4], accI[MT][NT][4];
    #pragma unroll
    for (int mt = 0; mt < MT; mt++)
        #pragma unroll
        for (int nt = 0; nt < NT; nt++)
            #pragma unroll
            for (int e = 0; e < 4; e++) { accP[mt][nt][e] = 0.f; accI[mt][nt][e] = 0.f; }

    float4 pA[4], pB[2][2];

    auto ldg = [&](int k0) {
        #pragma unroll
        for (int i = 0; i < 4; i++) {
            int idx = i * 256 + tid;
            int row = idx >> 3, c4 = idx & 7;
            pA[i] = *(const float4*)(Ar + (long long)(m0 + row) * sAm + k0 + c4 * 4);
        }
        #pragma unroll
        for (int c = 0; c < 2; c++) {
            const float* G = c ? Bi : Br;
            #pragma unroll
            for (int i = 0; i < 2; i++) {
                int idx = i * 256 + tid;
                int k = idx >> 4, c4 = idx & 15;
                pB[c][i] = *(const float4*)(G + (long long)(k0 + k) * sBk + n0 + c4 * 4);
            }
        }
    };
    auto sts = [&](uint32_t* base) {
        #pragma unroll
        for (int i = 0; i < 4; i++) {
            int idx = i * 256 + tid;
            int row = idx >> 3, c4 = idx & 7;
            float4 v = pA[i];
            uint32_t* p = base + row * LDS + c4 * 4;
            p[0] = f2tf32(v.x); p[1] = f2tf32(v.y);
            p[2] = f2tf32(v.z); p[3] = f2tf32(v.w);
        }
        #pragma unroll
        for (int c = 0; c < 2; c++) {
            uint32_t* SH = base + AT + c * BT;
            #pragma unroll
            for (int i = 0; i < 2; i++) {
                int idx = i * 256 + tid;
                int k = idx >> 4, c4 = idx & 15;
                float4 v = pB[c][i];
                float xs[4] = { v.x, v.y, v.z, v.w };
                #pragma unroll
                for (int j = 0; j < 4; j++)
                    SH[(c4 * 4 + j) * LDS + k] = f2tf32(xs[j]);
            }
        }
    };
    auto compute = [&](const uint32_t* base) {
        const uint32_t* sAr = base;
        const uint32_t* sBr = base + AT;
        const uint32_t* sBi = sBr + BT;
        #pragma unroll
        for (int kk = 0; kk < BK; kk += 8) {
            uint32_t ar[MT][4], br[NT][2], bi[NT][2];
            #pragma unroll
            for (int mt = 0; mt < MT; mt++) {
                int o0 = (mbase + mt * 16 + lg) * LDS + kk + lt;
                int o1 = o0 + 8 * LDS;
                ar[mt][0] = sAr[o0];   ar[mt][1] = sAr[o1];
                ar[mt][2] = sAr[o0+4]; ar[mt][3] = sAr[o1+4];
            }
            #pragma unroll
            for (int nt = 0; nt < NT; nt++) {
                int o0 = (nbase + nt * 8 + lg) * LDS + kk + lt;
                br[nt][0] = sBr[o0]; br[nt][1] = sBr[o0+4];
                bi[nt][0] = sBi[o0]; bi[nt][1] = sBi[o0+4];
            }
            #pragma unroll
            for (int nt = 0; nt < NT; nt++)
                #pragma unroll
                for (int mt = 0; mt < MT; mt++) {
                    mma_tf32(accP[mt][nt], ar[mt], br[nt]);
                    mma_tf32(accI[mt][nt], ar[mt], bi[nt]);
                }
        }
    };

    uint32_t* cur = smem;
    uint32_t* nxt = smem + STAGE;
    ldg(0);
    sts(cur);
    __syncthreads();
    for (int k0 = 0;;) {
        int kn = k0 + BK;
        bool more = kn < K;
        if (more) ldg(kn);
        compute(cur);
        if (!more) break;
        sts(nxt);
        __syncthreads();
        uint32_t* t = cur; cur = nxt; nxt = t;
        k0 = kn;
    }

    #pragma unroll
    for (int mt = 0; mt < MT; mt++)
        #pragma unroll
        for (int nt = 0; nt < NT; nt++)
            #pragma unroll
            for (int e = 0; e < 4; e++) {
                int gm = m0 + mbase + mt * 16 + lg + (e >> 1) * 8;
                int gn = n0 + nbase + nt * 8 + lt * 2 + (e & 1);
                long long p = (long long)gm * sCm + gn;
                Cr[p] = accP[mt][nt][e];
                Ci[p] = accI[mt][nt][e];
            }
}

// ---------------- coalesced 1024-pt FFT, twiddle table, optional fused bf16 split ----
#define FFT_COLS 8
#define FFT_LDP  1025
__global__ __launch_bounds__(256) void fft8_kernel(float* __restrict__ re,
                                                   float* __restrict__ im,
                                                   int inverse,
                                                   uint32_t* __restrict__ shR,
                                                   uint32_t* __restrict__ slR,
                                                   uint32_t* __restrict__ shI,
                                                   uint32_t* __restrict__ slI)
{
    extern __shared__ float fs[];
    float* sr = fs;
    float* si = fs + FFT_COLS * FFT_LDP;
    __shared__ float twr[512], twi[512];
    int blk = blockIdx.x;
    int b  = blk / (D_MODEL / FFT_COLS);
    int d0 = (blk % (D_MODEL / FFT_COLS)) * FFT_COLS;
    long long base = (long long)b * SEQ * D_MODEL + d0;
    int tid = threadIdx.x;

    float sgn = inverse ? 6.283185307179586f : -6.283185307179586f;
    #pragma unroll
    for (int j = 0; j < 2; j++) {
        int idx = j * 256 + tid;
        float ang = sgn * (float)idx * (1.0f / 1024.0f);
        float cs, sn;
        sincosf(ang, &sn, &cs);
        twr[idx] = cs; twi[idx] = sn;
    }

    #pragma unroll
    for (int i = 0; i < 8; i++) {
        int idx = i * 256 + tid;
        int row = idx >> 1, h = (idx & 1) * 4;
        int br = __brev((unsigned)row) >> 22;
        float4 vr = *(const float4*)(re + base + (long long)row * D_MODEL + h);
        float4 vi = *(const float4*)(im + base + (long long)row * D_MODEL + h);
        sr[(h+0)*FFT_LDP + br] = vr.x; sr[(h+1)*FFT_LDP + br] = vr.y;
        sr[(h+2)*FFT_LDP + br] = vr.z; sr[(h+3)*FFT_LDP + br] = vr.w;
        si[(h+0)*FFT_LDP + br] = vi.x; si[(h+1)*FFT_LDP + br] = vi.y;
        si[(h+2)*FFT_LDP + br] = vi.z; si[(h+3)*FFT_LDP + br] = vi.w;
    }
    __syncthreads();

    #pragma unroll
    for (int s = 1; s <= 10; s++) {
        int half = 1 << (s - 1);
        #pragma unroll
        for (int i = 0; i < 16; i++) {
            int idx = i * 256 + tid;
            int j = idx >> 3, c = idx & 7;
            int pos = j & (half - 1);
            int g = j >> (s - 1);
            int i0 = g * (half << 1) + pos, i1 = i0 + half;
            int tw = pos << (10 - s);
            float cs = twr[tw], sn = twi[tw];
            float* pr = sr + c * FFT_LDP;
            float* pi = si + c * FFT_LDP;
            float ur = pr[i0], ui = pi[i0];
            float vr = pr[i1], vi = pi[i1];
            float tr = cs * vr - sn * vi;
            float ti = cs * vi + sn * vr;
            pr[i0] = ur + tr; pi[i0] = ui + ti;
            pr[i1] = ur - tr; pi[i1] = ui - ti;
        }
        __syncthreads();
    }

    float sc = inverse ? (1.0f / 1024.0f) : 1.0f;
    #pragma unroll
    for (int i = 0; i < 8; i++) {
        int idx = i * 256 + tid;
        int row = idx >> 1, h = (idx & 1) * 4;
        float4 vr, vi;
        vr.x = sr[(h+0)*FFT_LDP + row] * sc; vr.y = sr[(h+1)*FFT_LDP + row] * sc;
        vr.z = sr[(h+2)*FFT_LDP + row] * sc; vr.w = sr[(h+3)*FFT_LDP + row] * sc;
        vi.x = si[(h+0)*FFT_LDP + row] * sc; vi.y = si[(h+1)*FFT_LDP + row] * sc;
        vi.z = si[(h+2)*FFT_LDP + row] * sc; vi.w = si[(h+3)*FFT_LDP + row] * sc;
        if (shR) {
            // fused bf16 hi/lo split output (packed pairs along d); skip fp32 writeback
            long long gi = (base + (long long)row * D_MODEL + h) >> 1;
            uint32_t h0, l0, h1, l1;
            split2g(vr.x, vr.y, h0, l0);
            split2g(vr.z, vr.w, h1, l1);
            *(uint2*)(shR + gi) = make_uint2(h0, h1);
            *(uint2*)(slR + gi) = make_uint2(l0, l1);
            split2g(vi.x, vi.y, h0, l0);
            split2g(vi.z, vi.w, h1, l1);
            *(uint2*)(shI + gi) = make_uint2(h0, h1);
            *(uint2*)(slI + gi) = make_uint2(l0, l1);
        } else {
            *(float4*)(re + base + (long long)row * D_MODEL + h) = vr;
            *(float4*)(im + base + (long long)row * D_MODEL + h) = vi;
        }
    }
}
#define FFT_SMEM (2 * FFT_COLS * FFT_LDP * 4)

// ---------------- row softmax over 1024 columns ----------------
__global__ __launch_bounds__(256) void softmax_kernel(float* __restrict__ S)
{
    long long row = blockIdx.x;
    float* p = S + row*1024;
    int t = threadIdx.x;
    __shared__ float red[256];

    float vals[4];
    float m = -1e30f;
    #pragma unroll
    for (int i = 0; i < 4; i++) { vals[i] = p[t + i*256]; m = fmaxf(m, vals[i]); }
    red[t] = m; __syncthreads();
    for (int s = 128; s > 0; s >>= 1) { if (t < s) red[t] = fmaxf(red[t], red[t+s]); __syncthreads(); }
    m = red[0]; __syncthreads();

    float sum = 0.f;
    #pragma unroll
    for (int i = 0; i < 4; i++) { vals[i] = expf(vals[i] - m); sum += vals[i]; }
    red[t] = sum; __syncthreads();
    for (int s = 128; s > 0; s >>= 1) { if (t < s) red[t] += red[t+s]; __syncthreads(); }
    float inv = 1.0f / red[0];
    #pragma unroll
    for (int i = 0; i < 4; i++) p[t + i*256] = vals[i]*inv;
}

// ---------------- elementwise helpers ----------------
__global__ void cvt_tf32_kernel(uint32_t* __restrict__ dst, const float* __restrict__ src,
                                long long n4)
{
    long long i = (long long)blockIdx.x*blockDim.x + threadIdx.x;
    if (i < n4) {
        float4 v = ((const float4*)src)[i];
        uint4 o;
        o.x = f2tf32(v.x); o.y = f2tf32(v.y);
        o.z = f2tf32(v.z); o.w = f2tf32(v.w);
        ((uint4*)dst)[i] = o;
    }
}
__global__ void split_bf16_kernel(uint32_t* __restrict__ hi, uint32_t* __restrict__ lo,
                                  const float* __restrict__ src, long long n4)
{
    long long i = (long long)blockIdx.x*blockDim.x + threadIdx.x;
    if (i < n4) {
        float4 v = ((const float4*)src)[i];
        uint32_t h0, l0, h1, l1;
        split2g(v.x, v.y, h0, l0);
        split2g(v.z, v.w, h1, l1);
        ((uint2*)hi)[i] = make_uint2(h0, h1);
        ((uint2*)lo)[i] = make_uint2(l0, l1);
    }
}
__global__ void scale_tf32_kernel(uint32_t* __restrict__ y, const float* __restrict__ x,
                                  const float* __restrict__ dt, long long n)
{
    long long i = (long long)blockIdx.x*blockDim.x + threadIdx.x;
    if (i < n) y[i] = f2tf32(x[i]*dt[0]);
}
__global__ void buildD_kernel(uint32_t* __restrict__ Dr, uint32_t* __restrict__ Di,
                              const uint32_t* __restrict__ tM, const float* __restrict__ E,
                              long long n)
{
    long long i = (long long)blockIdx.x*blockDim.x + threadIdx.x;
    if (i < n) {
        Dr[i] = f2tf32(-0.5f * E[i]);
        Di[i] = tM[i] ^ 0x80000000u;
    }
}

// ---------------- host orchestration ----------------
static void cgc(int mode, float* Cr, float* Ci,
    const uint32_t* Ar, const uint32_t* Ai,
    const uint32_t* Br, const uint32_t* Bi,
    int M, int N, int K, long long sAm, long long sBn, long long sCm,
    float alpha, int acc,
    const float* bR = nullptr, const float* bI = nullptr, int gelu = 0,
    uint32_t* outTr = nullptr, uint32_t* outTi = nullptr,
    const float* addR = nullptr, const float* addI = nullptr,
    float* dupR = nullptr, float* dupI = nullptr)
{
    dim3 grid(N / 64, M / 128);
    if (mode == 1) {
        size_t sh = 2 * 2 * (128*32 + 64*32) * 4;
        cgemm_c<1><<<grid, 256, sh>>>(Cr, Ci, Ar, Ai, Br, Bi, M, N, K,
                                      sAm, sBn, sCm, alpha, acc, bR, bI, gelu,
                                      outTr, outTi, addR, addI, dupR, dupI);
    } else {
        size_t sh = 2 * (128*32 + 64*32) * 4;
        cgemm_c<0><<<grid, 256, sh>>>(Cr, Ci, Ar, Ai, Br, Bi, M, N, K,
                                      sAm, sBn, sCm, alpha, acc, bR, bI, gelu,
                                      nullptr, nullptr, nullptr, nullptr, nullptr, nullptr);
    }
}

static void cvt(uint32_t* dst, const float* src, long long n)
{
    long long n4 = n >> 2;
    cvt_tf32_kernel<<<(int)((n4 + 255) / 256), 256>>>(dst, src, n4);
}
static void splitp(uint32_t* hi, uint32_t* lo, const float* src, long long n)
{
    long long n4 = n >> 2;
    split_bf16_kernel<<<(int)((n4 + 255) / 256), 256>>>(hi, lo, src, n4);
}

#define TGQ_SMEM (2 * (4 * 128 * 32 + 4 * 64 * 32) * 4)   // 196608

extern "C" void kernel_launch(void* const* d_in, const int* in_sizes, int n_in,
                              void* d_out, int out_size)
{
    cudaFuncSetAttribute(cgemm_c<1>, cudaFuncAttributeMaxDynamicSharedMemorySize, 98304);
    cudaFuncSetAttribute(cgemm_c<0>, cudaFuncAttributeMaxDynamicSharedMemorySize, 49152);
    cudaFuncSetAttribute(cgemm_q<1>, cudaFuncAttributeMaxDynamicSharedMemorySize, TGQ_SMEM);
    cudaFuncSetAttribute(cgemm_q<2>, cudaFuncAttributeMaxDynamicSharedMemorySize, TGQ_SMEM);
    cudaFuncSetAttribute(cgemm_av,  cudaFuncAttributeMaxDynamicSharedMemorySize, 73728);
    cudaFuncSetAttribute(fft8_kernel, cudaFuncAttributeMaxDynamicSharedMemorySize, FFT_SMEM);

    const float* x_real = (const float*)d_in[0];
    const float* x_imag = (const float*)d_in[1];
    const float* Wr_q = (const float*)d_in[2];   const float* Wi_q = (const float*)d_in[3];
    const float* br_q = (const float*)d_in[4];   const float* bi_q = (const float*)d_in[5];
    const float* Wr_k = (const float*)d_in[6];   const float* Wi_k = (const float*)d_in[7];
    const float* br_k = (const float*)d_in[8];   const float* bi_k = (const float*)d_in[9];
    const float* Wr_v = (const float*)d_in[10];  const float* Wi_v = (const float*)d_in[11];
    const float* br_v = (const float*)d_in[12];  const float* bi_v = (const float*)d_in[13];
    const float* Wr_o = (const float*)d_in[14];  const float* Wi_o = (const float*)d_in[15];
    const float* br_o = (const float*)d_in[16];  const float* bi_o = (const float*)d_in[17];
    const float* Wr_f1 = (const float*)d_in[18]; const float* Wi_f1 = (const float*)d_in[19];
    const float* br_f1 = (const float*)d_in[20]; const float* bi_f1 = (const float*)d_in[21];
    const float* Wr_f2 = (const float*)d_in[22]; const float* Wi_f2 = (const float*)d_in[23];
    const float* br_f2 = (const float*)d_in[24]; const float* bi_f2 = (const float*)d_in[25];
    const float* Hmat = (const float*)d_in[26];
    const float* dtp  = (const float*)d_in[27];

    float* outRe = (float*)d_out;
    float* outIm = outRe + (long long)ROWS*D_MODEL;

    float *Qr,*Qi,*Kr,*Ki,*Vr,*Vi,*Xr,*Xi,*Or,*Oi,*Hr,*Hi,*Sc,*Ta;
    uint32_t *tAr,*tAi,*tBr,*tBi,*tM,*tXr,*tXi,*tHr,*tHi;
    cudaGetSymbolAddress((void**)&Qr, g_Qr); cudaGetSymbolAddress((void**)&Qi, g_Qi);
    cudaGetSymbolAddress((void**)&Kr, g_Kr); cudaGetSymbolAddress((void**)&Ki, g_Ki);
    cudaGetSymbolAddress((void**)&Vr, g_Vr); cudaGetSymbolAddress((void**)&Vi, g_Vi);
    cudaGetSymbolAddress((void**)&Xr, g_Xr); cudaGetSymbolAddress((void**)&Xi, g_Xi);
    cudaGetSymbolAddress((void**)&Or, g_Or); cudaGetSymbolAddress((void**)&Oi, g_Oi);
    cudaGetSymbolAddress((void**)&Hr, g_Hr); cudaGetSymbolAddress((void**)&Hi, g_Hi);
    cudaGetSymbolAddress((void**)&Sc, g_Sc); cudaGetSymbolAddress((void**)&Ta, g_Ta);
    cudaGetSymbolAddress((void**)&tAr, g_tAr); cudaGetSymbolAddress((void**)&tAi, g_tAi);
    cudaGetSymbolAddress((void**)&tBr, g_tBr); cudaGetSymbolAddress((void**)&tBi, g_tBi);
    cudaGetSymbolAddress((void**)&tM,  g_tM);
    cudaGetSymbolAddress((void**)&tXr, g_tXr); cudaGetSymbolAddress((void**)&tXi, g_tXi);
    cudaGetSymbolAddress((void**)&tHr, g_tHr); cudaGetSymbolAddress((void**)&tHi, g_tHi);

    const long long ND = (long long)ROWS*D_MODEL;
    const long long DD = (long long)D_MODEL*D_MODEL;
    const long long DH = (long long)D_MODEL*HIDDEN;
    const long long hM = (long long)SEQ*SEQ;
    const long long ND2 = ND >> 1;
    const long long DD2 = DD >> 1;
    const int FFT_GRID = NBATCH * (D_MODEL / FFT_COLS);

    // ---- Q/K projections: precise split-bf16 (inputs read directly from x) ----
    splitp(tAr, tAr + ND2, x_real, ND);
    splitp(tAi, tAi + ND2, x_imag, ND);
    splitp(tBr, tBr + DD2, Wr_q, DD);
    splitp(tBr + 2*DD2, tBr + 3*DD2, Wi_q, DD);
    splitp(tBi, tBi + DD2, Wr_k, DD);
    splitp(tBi + 2*DD2, tBi + 3*DD2, Wi_k, DD);
    {
        dim3 grid(D_MODEL/64, ROWS/128);
        cgemm_q<1><<<grid, 512, TGQ_SMEM>>>(Qr, Qi,
            tAr, tAr + ND2, tAi, tAi + ND2,
            tBr, tBr + DD2, tBr + 2*DD2, tBr + 3*DD2,
            ROWS, D_MODEL, D_MODEL, D_MODEL, D_MODEL, D_MODEL,
            0,0,0,0,0,0,1, 1.f, 0, br_q, bi_q);
        cgemm_q<1><<<grid, 512, TGQ_SMEM>>>(Kr, Ki,
            tAr, tAr + ND2, tAi, tAi + ND2,
            tBi, tBi + DD2, tBi + 2*DD2, tBi + 3*DD2,
            ROWS, D_MODEL, D_MODEL, D_MODEL, D_MODEL, D_MODEL,
            0,0,0,0,0,0,1, 1.f, 0, br_k, bi_k);
    }

    // ---- V projection (cp.async tf32 engine; inputs from x directly) ----
    cvt(tAr, x_real, ND); cvt(tAi, x_imag, ND);
    cvt(tBr, Wr_v, DD); cvt(tBi, Wi_v, DD);
    cgc(1, Vr,Vi, tAr,tAi, tBr,tBi, ROWS,D_MODEL,D_MODEL, D_MODEL,D_MODEL,D_MODEL,
        1.f,0, br_v,bi_v,0);

    // ---- forward FFTs; Q/K emit fused bf16 splits (scores operands) ----
    fft8_kernel<<<FFT_GRID, 256, FFT_SMEM>>>(Qr, Qi, 0,
        tAr, tAr + ND2, tAi, tAi + ND2);
    fft8_kernel<<<FFT_GRID, 256, FFT_SMEM>>>(Kr, Ki, 0,
        tBr, tBr + ND2, tBr + 2*ND2, tBr + 3*ND2);
    fft8_kernel<<<FFT_GRID, 256, FFT_SMEM>>>(Vr, Vi, 0,
        nullptr, nullptr, nullptr, nullptr);

    // ---- scores = scale*Re(Qf conj(Kf)); precise, batched over (b,h) ----
    {
        dim3 grid(SEQ/64, SEQ/128, NBATCH*NHEADS);
        cgemm_q<2><<<grid, 512, TGQ_SMEM>>>(Sc, nullptr,
            tAr, tAr + ND2, tAi, tAi + ND2,
            tBr, tBr + ND2, tBr + 2*ND2, tBr + 3*ND2,
            SEQ, SEQ, DHEAD, D_MODEL, D_MODEL, SEQ,
            (long long)SEQ*D_MODEL, DHEAD,
            (long long)SEQ*D_MODEL, DHEAD,
            (long long)NHEADS*hM, hM, NHEADS,
            0.125f, 0, nullptr, nullptr);
    }

    softmax_kernel<<<NBATCH*NHEADS*SEQ, 256>>>(Sc);

    // ---- out_f = attn @ Vf ----
    cgemm_av<<<dim3(1, SEQ/128, NBATCH*NHEADS), 256, 73728>>>(
        Or, Oi, Sc, Vr, Vi, SEQ, DHEAD, SEQ,
        SEQ, D_MODEL, D_MODEL,
        (long long)NHEADS*hM, hM,
        (long long)SEQ*D_MODEL, DHEAD,
        (long long)SEQ*D_MODEL, DHEAD, NHEADS);

    // ---- inverse FFT ----
    fft8_kernel<<<FFT_GRID, 256, FFT_SMEM>>>(Or, Oi, 1,
        nullptr, nullptr, nullptr, nullptr);

    // ---- X = x + clin(O, Wo); emits tf32(X) for FFN1 ----
    cvt(tAr, Or, ND); cvt(tAi, Oi, ND);
    cvt(tBr, Wr_o, DD); cvt(tBi, Wi_o, DD);
    cgc(1, Xr,Xi, tAr,tAi, tBr,tBi, ROWS,D_MODEL,D_MODEL, D_MODEL,D_MODEL,D_MODEL,
        1.f,0, br_o,bi_o,0, tXr,tXi, x_real,x_imag);

    // ---- FFN1: H = gelu(clin(X, Wf1)); emits tf32(H) ----
    cvt(tBr, Wr_f1, DH); cvt(tBi, Wi_f1, DH);
    cgc(1, Hr,Hi, tXr,tXi, tBr,tBi, ROWS,HIDDEN,D_MODEL, D_MODEL,D_MODEL,HIDDEN,
        1.f,0, br_f1,bi_f1,1, tHr,tHi);

    // ---- FFN2: X += clin(H, Wf2); emits tf32(X) and duplicates X into out ----
    cvt(tBr, Wr_f2, DH); cvt(tBi, Wi_f2, DH);
    cgc(1, Xr,Xi, tHr,tHi, tBr,tBi, ROWS,D_MODEL,HIDDEN, HIDDEN,HIDDEN,D_MODEL,
        1.f,1, br_f2,bi_f2,0, tXr,tXi, nullptr,nullptr, outRe,outIm);

    // ---- U = expm(-i H dt) ~ I - E/2 - i M  (E = M^2, M = H dt) ----
    scale_tf32_kernel<<<(int)((DD+255)/256), 256>>>(tM, Hmat, dtp, DD);
    cgc(0, Ta,nullptr, tM,nullptr, tM,nullptr, D_MODEL,D_MODEL,D_MODEL,
        D_MODEL,D_MODEL,D_MODEL, 1.f,0);
    buildD_kernel<<<(int)((DD+255)/256), 256>>>(tBr, tBi, tM, Ta, DD);

    // ---- out = X + X @ D (out already holds X via dup) ----
    cgc(1, outRe,outIm, tXr,tXi, tBr,tBi, ROWS,D_MODEL,D_MODEL, D_MODEL,D_MODEL,D_MODEL,
        1.f,1);
}

// round 17
// speedup vs baseline: 1.2401x; 1.0449x over previous
#include <cuda_runtime.h>
#include <cuda_bf16.h>
#include <math.h>
#include <stdint.h>

#define SEQ     1024
#define D_MODEL 1024
#define NHEADS  16
#define DHEAD   64
#define HIDDEN  4096
#define NBATCH  2
#define ROWS    (NBATCH*SEQ)   // 2048

// ---------------- scratch (device statics; no allocation) ----------------
__device__ __align__(128) float g_Qr[ROWS*D_MODEL];
__device__ __align__(128) float g_Qi[ROWS*D_MODEL];
__device__ __align__(128) float g_Kr[ROWS*D_MODEL];
__device__ __align__(128) float g_Ki[ROWS*D_MODEL];
__device__ __align__(128) float g_Vr[ROWS*D_MODEL];
__device__ __align__(128) float g_Vi[ROWS*D_MODEL];
__device__ __align__(128) float g_Xr[ROWS*D_MODEL];
__device__ __align__(128) float g_Xi[ROWS*D_MODEL];
__device__ __align__(128) float g_Or[ROWS*D_MODEL];
__device__ __align__(128) float g_Oi[ROWS*D_MODEL];
__device__ __align__(128) float g_Hr[ROWS*HIDDEN];
__device__ __align__(128) float g_Hi[ROWS*HIDDEN];
__device__ __align__(128) float g_Ta[D_MODEL*D_MODEL];
// operand scratch (tf32 u32 payload OR packed bf16x2 planes)
__device__ __align__(128) uint32_t g_tAr[ROWS*HIDDEN];
__device__ __align__(128) uint32_t g_tAi[ROWS*HIDDEN];
__device__ __align__(128) uint32_t g_tBr[HIDDEN*D_MODEL];
__device__ __align__(128) uint32_t g_tBi[HIDDEN*D_MODEL];
__device__ __align__(128) uint32_t g_tM [D_MODEL*D_MODEL];
__device__ __align__(128) uint32_t g_tXr[ROWS*D_MODEL];
__device__ __align__(128) uint32_t g_tXi[ROWS*D_MODEL];
__device__ __align__(128) uint32_t g_tHr[ROWS*HIDDEN];
__device__ __align__(128) uint32_t g_tHi[ROWS*HIDDEN];

// ---------------- low-level helpers ----------------
__device__ __forceinline__ uint32_t f2tf32(float x) {
    uint32_t r;
    asm("cvt.rna.tf32.f32 %0, %1;" : "=r"(r) : "f"(x));
    return r;
}
__device__ __forceinline__ void mma_tf32(float* d, const uint32_t* a, const uint32_t* b) {
    asm volatile(
        "mma.sync.aligned.m16n8k8.row.col.f32.tf32.tf32.f32 "
        "{%0,%1,%2,%3}, {%4,%5,%6,%7}, {%8,%9}, {%0,%1,%2,%3};\n"
        : "+f"(d[0]), "+f"(d[1]), "+f"(d[2]), "+f"(d[3])
        : "r"(a[0]), "r"(a[1]), "r"(a[2]), "r"(a[3]), "r"(b[0]), "r"(b[1]));
}
__device__ __forceinline__ void mma_bf16(float* d, const uint32_t* a, const uint32_t* b) {
    asm volatile(
        "mma.sync.aligned.m16n8k16.row.col.f32.bf16.bf16.f32 "
        "{%0,%1,%2,%3}, {%4,%5,%6,%7}, {%8,%9}, {%0,%1,%2,%3};\n"
        : "+f"(d[0]), "+f"(d[1]), "+f"(d[2]), "+f"(d[3])
        : "r"(a[0]), "r"(a[1]), "r"(a[2]), "r"(a[3]), "r"(b[0]), "r"(b[1]));
}
__device__ __forceinline__ uint32_t pack_pair(float x0, float x1) {
    uint32_t r;
    asm("cvt.rn.bf16x2.f32 %0, %1, %2;" : "=r"(r) : "f"(x1), "f"(x0));
    return r;
}
__device__ __forceinline__ void split2g(float x, float y, uint32_t& h, uint32_t& l) {
    h = pack_pair(x, y);
    float fx = __uint_as_float(h << 16);
    float fy = __uint_as_float(h & 0xFFFF0000u);
    l = pack_pair(x - fx, y - fy);
}
__device__ __forceinline__ float gelu_f(float v) {
    return 0.5f * v * (1.0f + erff(v * 0.7071067811865476f));
}
__device__ __forceinline__ uint32_t smem_addr_of(const void* p) {
    return (uint32_t)__cvta_generic_to_shared(p);
}
#define CP16(dst, src) \
    asm volatile("cp.async.cg.shared.global [%0], [%1], 16;" :: "r"(dst), "l"(src) : "memory")

// =================== cp.async tf32 GEMM (pre-rounded operands, fused epilogue) ===================
template<int MODE>
__global__ __launch_bounds__(256, 2) void cgemm_c(
    float* __restrict__ Cr, float* __restrict__ Ci,
    const uint32_t* __restrict__ Ar, const uint32_t* __restrict__ Ai,
    const uint32_t* __restrict__ Br, const uint32_t* __restrict__ Bi,
    int M, int N, int K,
    long long sAm, long long sBn, long long sCm,
    float alpha, int accumulate,
    const float* __restrict__ biasR, const float* __restrict__ biasI, int gelu,
    uint32_t* __restrict__ outTr, uint32_t* __restrict__ outTi,
    const float* __restrict__ addR, const float* __restrict__ addI,
    float* __restrict__ dupR, float* __restrict__ dupI)
{
    constexpr int nAB = (MODE == 1) ? 2 : 1;
    constexpr int AW = 128 * 32;
    constexpr int BW = 64 * 32;
    constexpr int STAGE = nAB * (AW + BW);
    constexpr int MT = 2, NT = 4;

    extern __shared__ uint32_t sm[];

    int tid = threadIdx.x, lane = tid & 31, w = tid >> 5;
    int m0 = blockIdx.y * 128, n0 = blockIdx.x * 64;
    int mbase = (w >> 1) * 32, nbase = (w & 1) * 32;
    int lg = lane >> 2, lt = lane & 3;

    float accP[MT][NT][4], accI[MT][NT][4];
    #pragma unroll
    for (int mt = 0; mt < MT; mt++)
        #pragma unroll
        for (int nt = 0; nt < NT; nt++)
            #pragma unroll
            for (int e = 0; e < 4; e++) { accP[mt][nt][e] = 0.f; accI[mt][nt][e] = 0.f; }

    auto issue = [&](int k0, int buf) {
        uint32_t* base = sm + buf * STAGE;
        #pragma unroll
        for (int p = 0; p < nAB; p++) {
            const uint32_t* G = p ? Ai : Ar;
            uint32_t* S = base + p * AW;
            #pragma unroll
            for (int i = 0; i < 4; i++) {
                int idx = i * 256 + tid;
                int row = idx >> 3, c = idx & 7;
                const uint32_t* src = G + (long long)(m0 + row) * sAm + k0 + c * 4;
                CP16(smem_addr_of(S + row * 32 + ((c ^ (row & 7)) << 2)), src);
            }
        }
        #pragma unroll
        for (int p = 0; p < nAB; p++) {
            const uint32_t* G = p ? Bi : Br;
            uint32_t* S = base + nAB * AW + p * BW;
            #pragma unroll
            for (int i = 0; i < 2; i++) {
                int idx = i * 256 + tid;
                int row = idx >> 3, c = idx & 7;
                const uint32_t* src = G + (long long)(n0 + row) * sBn + k0 + c * 4;
                CP16(smem_addr_of(S + row * 32 + ((c ^ (row & 7)) << 2)), src);
            }
        }
        asm volatile("cp.async.commit_group;" ::: "memory");
    };

    auto compute = [&](int buf) {
        uint32_t* base = sm + buf * STAGE;
        const uint32_t* sAr = base;
        const uint32_t* sAi = base + AW;
        const uint32_t* sBr = base + nAB * AW;
        const uint32_t* sBi = sBr + BW;
        #pragma unroll
        for (int kk = 0; kk < 32; kk += 8) {
            int ck0 = kk >> 2, ck1 = ck0 + 1;
            uint32_t ar[MT][4], br[NT][2];
            #pragma unroll
            for (int mt = 0; mt < MT; mt++) {
                int row = mbase + mt * 16 + lg;
                int o0 = row * 32 + ((ck0 ^ (row & 7)) << 2) + lt;
                int o1 = row * 32 + ((ck1 ^ (row & 7)) << 2) + lt;
                ar[mt][0] = sAr[o0];       ar[mt][1] = sAr[o0 + 256];
                ar[mt][2] = sAr[o1];       ar[mt][3] = sAr[o1 + 256];
            }
            #pragma unroll
            for (int nt = 0; nt < NT; nt++) {
                int row = nbase + nt * 8 + lg;
                int o0 = row * 32 + ((ck0 ^ (row & 7)) << 2) + lt;
                int o1 = row * 32 + ((ck1 ^ (row & 7)) << 2) + lt;
                br[nt][0] = sBr[o0]; br[nt][1] = sBr[o1];
            }
            #pragma unroll
            for (int nt = 0; nt < NT; nt++)
                #pragma unroll
                for (int mt = 0; mt < MT; mt++)
                    mma_tf32(accP[mt][nt], ar[mt], br[nt]);
            if constexpr (MODE == 1) {
                uint32_t bi_[NT][2];
                #pragma unroll
                for (int nt = 0; nt < NT; nt++) {
                    int row = nbase + nt * 8 + lg;
                    int o0 = row * 32 + ((ck0 ^ (row & 7)) << 2) + lt;
                    int o1 = row * 32 + ((ck1 ^ (row & 7)) << 2) + lt;
                    bi_[nt][0] = sBi[o0]; bi_[nt][1] = sBi[o1];
                }
                #pragma unroll
                for (int nt = 0; nt < NT; nt++)
                    #pragma unroll
                    for (int mt = 0; mt < MT; mt++)
                        mma_tf32(accI[mt][nt], ar[mt], bi_[nt]);
                #pragma unroll
                for (int nt = 0; nt < NT; nt++) {
                    bi_[nt][0] ^= 0x80000000u; bi_[nt][1] ^= 0x80000000u;
                }
                uint32_t ai_[MT][4];
                #pragma unroll
                for (int mt = 0; mt < MT; mt++) {
                    int row = mbase + mt * 16 + lg;
                    int o0 = row * 32 + ((ck0 ^ (row & 7)) << 2) + lt;
                    int o1 = row * 32 + ((ck1 ^ (row & 7)) << 2) + lt;
                    ai_[mt][0] = sAi[o0];     ai_[mt][1] = sAi[o0 + 256];
                    ai_[mt][2] = sAi[o1];     ai_[mt][3] = sAi[o1 + 256];
                }
                #pragma unroll
                for (int nt = 0; nt < NT; nt++)
                    #pragma unroll
                    for (int mt = 0; mt < MT; mt++)
                        mma_tf32(accP[mt][nt], ai_[mt], bi_[nt]);
                #pragma unroll
                for (int nt = 0; nt < NT; nt++)
                    #pragma unroll
                    for (int mt = 0; mt < MT; mt++)
                        mma_tf32(accI[mt][nt], ai_[mt], br[nt]);
            }
        }
    };

    int nst = K >> 5;
    issue(0, 0);
    if (nst > 1) issue(32, 1);
    int buf = 0;
    for (int s = 0; s < nst; s++) {
        if (s + 1 < nst)
            asm volatile("cp.async.wait_group 1;" ::: "memory");
        else
            asm volatile("cp.async.wait_group 0;" ::: "memory");
        __syncthreads();
        compute(buf);
        __syncthreads();
        if (s + 2 < nst) issue((s + 2) << 5, buf);
        buf ^= 1;
    }

    #pragma unroll
    for (int mt = 0; mt < MT; mt++)
        #pragma unroll
        for (int nt = 0; nt < NT; nt++)
            #pragma unroll
            for (int e = 0; e < 4; e++) {
                int gm = m0 + mbase + mt * 16 + lg + (e >> 1) * 8;
                int gn = n0 + nbase + nt * 8 + lt * 2 + (e & 1);
                long long p = (long long)gm * sCm + gn;
                if constexpr (MODE == 1) {
                    float vr = accP[mt][nt][e];
                    float vi = accI[mt][nt][e];
                    if (biasR) { vr += biasR[gn]; vi += biasI[gn]; }
                    if (gelu)  { vr = gelu_f(vr); vi = gelu_f(vi); }
                    if (addR)  { vr += addR[p]; vi += addI[p]; }
                    else if (accumulate) { vr += Cr[p]; vi += Ci[p]; }
                    Cr[p] = vr; Ci[p] = vi;
                    if (outTr) { outTr[p] = f2tf32(vr); outTi[p] = f2tf32(vi); }
                    if (dupR)  { dupR[p] = vr; dupI[p] = vi; }
                } else {
                    float v = alpha * accP[mt][nt][e];
                    if (accumulate) v += Cr[p];
                    Cr[p] = v;
                }
            }
}

// =================== PRECISE cp.async split-bf16 GEMM, 512 threads (Q/K proj) ===================
template<int MODE>
__global__ __launch_bounds__(512, 1) void cgemm_q(
    float* __restrict__ Cr, float* __restrict__ Ci,
    const uint32_t* __restrict__ AhR, const uint32_t* __restrict__ AlR,
    const uint32_t* __restrict__ AhI, const uint32_t* __restrict__ AlI,
    const uint32_t* __restrict__ BhR, const uint32_t* __restrict__ BlR,
    const uint32_t* __restrict__ BhI, const uint32_t* __restrict__ BlI,
    int M, int N, int K,
    long long sAm, long long sBn, long long sCm,
    long long aB1, long long aB2, long long bB1, long long bB2,
    long long cB1, long long cB2, int batchDiv,
    float alpha, int accumulate,
    const float* __restrict__ biasR, const float* __restrict__ biasI)
{
    constexpr int AW = 128 * 32;
    constexpr int BW = 64 * 32;
    constexpr int STAGE = 4 * AW + 4 * BW;
    constexpr int MT = 2, NT = 2;

    extern __shared__ uint32_t sm[];

    int tid = threadIdx.x, lane = tid & 31, w = tid >> 5;
    int z = blockIdx.z, zb = z / batchDiv, zh = z % batchDiv;
    long long aOff = ((long long)zb * aB1 + (long long)zh * aB2) >> 1;
    long long bOff = ((long long)zb * bB1 + (long long)zh * bB2) >> 1;
    const uint32_t* pA[4] = { AhR + aOff, AlR + aOff, AhI + aOff, AlI + aOff };
    const uint32_t* pB[4] = { BhR + bOff, BlR + bOff, BhI + bOff, BlI + bOff };
    Cr += (long long)zb * cB1 + (long long)zh * cB2;
    if constexpr (MODE == 1) Ci += (long long)zb * cB1 + (long long)zh * cB2;

    int m0 = blockIdx.y * 128, n0 = blockIdx.x * 64;
    int mbase = (w >> 2) * 32, nbase = (w & 3) * 16;
    int lg = lane >> 2, lt = lane & 3;
    long long sAu = sAm >> 1, sBu = sBn >> 1;

    float accP[MT][NT][4], accI[MT][NT][4];
    #pragma unroll
    for (int mt = 0; mt < MT; mt++)
        #pragma unroll
        for (int nt = 0; nt < NT; nt++)
            #pragma unroll
            for (int e = 0; e < 4; e++) { accP[mt][nt][e] = 0.f; accI[mt][nt][e] = 0.f; }

    auto issue = [&](int k0, int buf) {
        uint32_t* base = sm + buf * STAGE;
        long long ku = k0 >> 1;
        #pragma unroll
        for (int p = 0; p < 4; p++) {
            #pragma unroll
            for (int i = 0; i < 2; i++) {
                int idx = i * 512 + tid;
                int row = idx >> 3, c = idx & 7;
                const uint32_t* src = pA[p] + (long long)(m0 + row) * sAu + ku + c * 4;
                CP16(smem_addr_of(base + p * AW + row * 32 + ((c ^ (row & 7)) << 2)), src);
            }
        }
        #pragma unroll
        for (int p = 0; p < 4; p++) {
            int row = tid >> 3, c = tid & 7;
            const uint32_t* src = pB[p] + (long long)(n0 + row) * sBu + ku + c * 4;
            CP16(smem_addr_of(base + 4 * AW + p * BW + row * 32 + ((c ^ (row & 7)) << 2)), src);
        }
        asm volatile("cp.async.commit_group;" ::: "memory");
    };

    auto compute = [&](int buf) {
        uint32_t* base = sm + buf * STAGE;
        const uint32_t* sA[4] = { base, base + AW, base + 2*AW, base + 3*AW };
        const uint32_t* sB[4] = { base + 4*AW, base + 4*AW + BW,
                                  base + 4*AW + 2*BW, base + 4*AW + 3*BW };
        #pragma unroll
        for (int c = 0; c < 4; c++) {
            int g0 = 2 * c, g1 = 2 * c + 1;
            int r0 = mbase + lg, r1 = r0 + 8, r2 = r0 + 16, r3 = r0 + 24;
            int oA[4][2];
            oA[0][0] = r0*32 + ((g0 ^ (r0&7))<<2) + lt; oA[0][1] = r0*32 + ((g1 ^ (r0&7))<<2) + lt;
            oA[1][0] = r1*32 + ((g0 ^ (r1&7))<<2) + lt; oA[1][1] = r1*32 + ((g1 ^ (r1&7))<<2) + lt;
            oA[2][0] = r2*32 + ((g0 ^ (r2&7))<<2) + lt; oA[2][1] = r2*32 + ((g1 ^ (r2&7))<<2) + lt;
            oA[3][0] = r3*32 + ((g0 ^ (r3&7))<<2) + lt; oA[3][1] = r3*32 + ((g1 ^ (r3&7))<<2) + lt;
            int rb0 = nbase + lg, rb1 = rb0 + 8;
            int oB[2][2];
            oB[0][0] = rb0*32 + ((g0 ^ (rb0&7))<<2) + lt; oB[0][1] = rb0*32 + ((g1 ^ (rb0&7))<<2) + lt;
            oB[1][0] = rb1*32 + ((g0 ^ (rb1&7))<<2) + lt; oB[1][1] = rb1*32 + ((g1 ^ (rb1&7))<<2) + lt;

            uint32_t arH[MT][4], arL[MT][4], aiH[MT][4], aiL[MT][4];
            #pragma unroll
            for (int mt = 0; mt < MT; mt++) {
                int ra = mt * 2, rbx = mt * 2 + 1;
                arH[mt][0] = sA[0][oA[ra][0]]; arH[mt][1] = sA[0][oA[rbx][0]];
                arH[mt][2] = sA[0][oA[ra][1]]; arH[mt][3] = sA[0][oA[rbx][1]];
                arL[mt][0] = sA[1][oA[ra][0]]; arL[mt][1] = sA[1][oA[rbx][0]];
                arL[mt][2] = sA[1][oA[ra][1]]; arL[mt][3] = sA[1][oA[rbx][1]];
                aiH[mt][0] = sA[2][oA[ra][0]]; aiH[mt][1] = sA[2][oA[rbx][0]];
                aiH[mt][2] = sA[2][oA[ra][1]]; aiH[mt][3] = sA[2][oA[rbx][1]];
                aiL[mt][0] = sA[3][oA[ra][0]]; aiL[mt][1] = sA[3][oA[rbx][0]];
                aiL[mt][2] = sA[3][oA[ra][1]]; aiL[mt][3] = sA[3][oA[rbx][1]];
            }
            uint32_t brH[NT][2], brL[NT][2], biH[NT][2], biL[NT][2];
            #pragma unroll
            for (int nt = 0; nt < NT; nt++) {
                brH[nt][0] = sB[0][oB[nt][0]]; brH[nt][1] = sB[0][oB[nt][1]];
                brL[nt][0] = sB[1][oB[nt][0]]; brL[nt][1] = sB[1][oB[nt][1]];
                biH[nt][0] = sB[2][oB[nt][0]]; biH[nt][1] = sB[2][oB[nt][1]];
                biL[nt][0] = sB[3][oB[nt][0]]; biL[nt][1] = sB[3][oB[nt][1]];
            }
            #define SWEEP(D, A, B) \
                { _Pragma("unroll") for (int nt = 0; nt < NT; nt++) \
                    _Pragma("unroll") for (int mt = 0; mt < MT; mt++) \
                        mma_bf16(D[mt][nt], A[mt], B[nt]); }
            #define NEG(B) { _Pragma("unroll") for (int nt = 0; nt < NT; nt++) { \
                        B[nt][0] ^= 0x80008000u; B[nt][1] ^= 0x80008000u; } }
            if constexpr (MODE == 1) {
                SWEEP(accP, arH, brH);
                SWEEP(accI, arH, biH);
                SWEEP(accI, aiH, brH);
                NEG(biH); SWEEP(accP, aiH, biH);
                SWEEP(accP, arH, brL);
                SWEEP(accI, arH, biL);
                SWEEP(accI, aiH, brL);
                NEG(biL); SWEEP(accP, aiH, biL);
                SWEEP(accP, arL, brH);
                NEG(biH); SWEEP(accI, arL, biH);
                SWEEP(accI, aiL, brH);
                NEG(biH); SWEEP(accP, aiL, biH);
            } else {
                SWEEP(accP, arH, brH);
                SWEEP(accP, aiH, biH);
                SWEEP(accP, arH, brL);
                SWEEP(accP, aiH, biL);
                SWEEP(accP, arL, brH);
                SWEEP(accP, aiL, biH);
            }
            #undef SWEEP
            #undef NEG
        }
    };

    int nst = K >> 6;
    issue(0, 0);
    if (nst > 1) issue(64, 1);
    int buf = 0;
    for (int s = 0; s < nst; s++) {
        if (s + 1 < nst)
            asm volatile("cp.async.wait_group 1;" ::: "memory");
        else
            asm volatile("cp.async.wait_group 0;" ::: "memory");
        __syncthreads();
        compute(buf);
        __syncthreads();
        if (s + 2 < nst) issue((s + 2) << 6, buf);
        buf ^= 1;
    }

    #pragma unroll
    for (int mt = 0; mt < MT; mt++)
        #pragma unroll
        for (int nt = 0; nt < NT; nt++)
            #pragma unroll
            for (int e = 0; e < 4; e++) {
                int gm = m0 + mbase + mt * 16 + lg + (e >> 1) * 8;
                int gn = n0 + nbase + nt * 8 + lt * 2 + (e & 1);
                long long p = (long long)gm * sCm + gn;
                if constexpr (MODE == 1) {
                    float vr = accP[mt][nt][e];
                    float vi = accI[mt][nt][e];
                    if (biasR) { vr += biasR[gn]; vi += biasI[gn]; }
                    if (accumulate) { vr += Cr[p]; vi += Ci[p]; }
                    Cr[p] = vr; Ci[p] = vi;
                } else {
                    Cr[p] = alpha * accP[mt][nt][e];
                }
            }
}

// =================== FLASH ATTENTION (scores + softmax + attn@V fused) ===================
// Grid: (SEQ/128, NBATCH*NHEADS). 256 threads, 8 warps x m16.
// Q/K as pre-split bf16 planes [token][dh packed]; V fp32 (split+transposed on the fly).
// Of = softmax(scale*(QfrKfr^T + QfiKfi^T)) @ (Vfr + i Vfi), online softmax.
#define FA_SMEM (49152 * 4)
__global__ __launch_bounds__(256, 1) void flash_kernel(
    float* __restrict__ Or_, float* __restrict__ Oi_,
    const uint32_t* __restrict__ QhR, const uint32_t* __restrict__ QlR,
    const uint32_t* __restrict__ QhI, const uint32_t* __restrict__ QlI,
    const uint32_t* __restrict__ KhR, const uint32_t* __restrict__ KlR,
    const uint32_t* __restrict__ KhI, const uint32_t* __restrict__ KlI,
    const float* __restrict__ Vr_, const float* __restrict__ Vi_)
{
    extern __shared__ uint32_t sm[];
    int tid = threadIdx.x, lane = tid & 31, w = tid >> 5;
    int lg = lane >> 2, lt = lane & 3;
    int z = blockIdx.y, zb = z >> 4, zh = z & 15;
    int q0 = blockIdx.x * 128;
    long long rowQ = (long long)(zb * SEQ + q0);
    long long rowK = (long long)(zb * SEQ);
    const uint32_t* QP[4] = { QhR, QlR, QhI, QlI };
    const uint32_t* KP[4] = { KhR, KlR, KhI, KlI };

    // ---- load Q (4 planes, 128x32 u32 each) via cp.async ----
    #pragma unroll
    for (int p = 0; p < 4; p++)
        #pragma unroll
        for (int i = 0; i < 4; i++) {
            int idx = i * 256 + tid;
            int row = idx >> 3, c = idx & 7;
            const uint32_t* src = QP[p] + (rowQ + row) * 512 + zh * 32 + c * 4;
            CP16(smem_addr_of(sm + p * 4096 + row * 32 + ((c ^ (row & 7)) << 2)), src);
        }
    asm volatile("cp.async.commit_group;" ::: "memory");

    auto issueK = [&](int j, int buf) {
        uint32_t* base = sm + 16384 + buf * 16384;
        #pragma unroll
        for (int p = 0; p < 4; p++)
            #pragma unroll
            for (int i = 0; i < 2; i++) {
                int idx = i * 256 + tid;
                int row = idx >> 3, c = idx & 7;
                const uint32_t* src = KP[p] + (rowK + j * 64 + row) * 512 + zh * 32 + c * 4;
                CP16(smem_addr_of(base + p * 2048 + row * 32 + ((c ^ (row & 7)) << 2)), src);
            }
        asm volatile("cp.async.commit_group;" ::: "memory");
    };

    float4 vreg[2][4];
    auto ldV = [&](int j) {
        #pragma unroll
        for (int cp = 0; cp < 2; cp++) {
            const float* G = cp ? Vi_ : Vr_;
            #pragma unroll
            for (int i = 0; i < 4; i++) {
                int idx = i * 256 + tid;
                int t = idx >> 4, gd = idx & 15;
                vreg[cp][i] = *(const float4*)(G + (rowK + j * 64 + t) * 1024 + zh * 64 + gd * 4);
            }
        }
    };
    auto stV = [&](int buf) {
        // planes (u16 view): VrH, VrL, ViH, ViL at stage+8192 u32, each 2048 u32
        uint16_t* vb = (uint16_t*)(sm + 16384 + buf * 16384 + 8192);
        #pragma unroll
        for (int cp = 0; cp < 2; cp++)
            #pragma unroll
            for (int i = 0; i < 4; i++) {
                int idx = i * 256 + tid;
                int t = idx >> 4, gd = idx & 15;
                float xs[4] = { vreg[cp][i].x, vreg[cp][i].y, vreg[cp][i].z, vreg[cp][i].w };
                #pragma unroll
                for (int jj = 0; jj < 4; jj++) {
                    int d = gd * 4 + jj;
                    __nv_bfloat16 hb = __float2bfloat16(xs[jj]);
                    __nv_bfloat16 lb = __float2bfloat16(xs[jj] - __bfloat162float(hb));
                    int word = d * 32 + (((t >> 3) ^ (d & 7)) << 2) + ((t >> 1) & 3);
                    int u16i = 2 * word + (t & 1);
                    ((__nv_bfloat16*)vb)[(cp * 2 + 0) * 4096 + u16i] = hb;
                    ((__nv_bfloat16*)vb)[(cp * 2 + 1) * 4096 + u16i] = lb;
                }
            }
    };

    float m_[2] = { -1e30f, -1e30f }, l_[2] = { 0.f, 0.f };
    float accO[2][8][4];
    #pragma unroll
    for (int cp = 0; cp < 2; cp++)
        #pragma unroll
        for (int nt = 0; nt < 8; nt++)
            #pragma unroll
            for (int e = 0; e < 4; e++) accO[cp][nt][e] = 0.f;

    issueK(0, 0);
    ldV(0);

    int r0w = w * 16 + lg;
    for (int j = 0; j < 16; j++) {
        int buf = j & 1;
        asm volatile("cp.async.wait_group 0;" ::: "memory");
        stV(buf);
        __syncthreads();
        if (j + 1 < 16) { issueK(j + 1, buf ^ 1); ldV(j + 1); }

        const uint32_t* KB = sm + 16384 + buf * 16384;
        // ---- scores: S = QfrKfr^T + QfiKfi^T (split-bf16, 6 sweeps) ----
        float accS[8][4];
        #pragma unroll
        for (int nt = 0; nt < 8; nt++)
            #pragma unroll
            for (int e = 0; e < 4; e++) accS[nt][e] = 0.f;
        #pragma unroll
        for (int kc = 0; kc < 4; kc++) {
            int g0 = 2 * kc, g1 = g0 + 1;
            int oq0 = r0w * 32 + ((g0 ^ (r0w & 7)) << 2) + lt;
            int oq1 = (r0w + 8) * 32 + ((g0 ^ ((r0w + 8) & 7)) << 2) + lt;
            int oq2 = r0w * 32 + ((g1 ^ (r0w & 7)) << 2) + lt;
            int oq3 = (r0w + 8) * 32 + ((g1 ^ ((r0w + 8) & 7)) << 2) + lt;
            uint32_t qf[4][4];
            #pragma unroll
            for (int p = 0; p < 4; p++) {
                qf[p][0] = sm[p * 4096 + oq0]; qf[p][1] = sm[p * 4096 + oq1];
                qf[p][2] = sm[p * 4096 + oq2]; qf[p][3] = sm[p * 4096 + oq3];
            }
            #pragma unroll
            for (int nt = 0; nt < 8; nt++) {
                int kr = nt * 8 + lg;
                int ob0 = kr * 32 + ((g0 ^ (kr & 7)) << 2) + lt;
                int ob1 = kr * 32 + ((g1 ^ (kr & 7)) << 2) + lt;
                uint32_t kb[4][2];
                #pragma unroll
                for (int p = 0; p < 4; p++) { kb[p][0] = KB[p * 2048 + ob0]; kb[p][1] = KB[p * 2048 + ob1]; }
                mma_bf16(accS[nt], qf[0], kb[0]);   // QrH KrH
                mma_bf16(accS[nt], qf[0], kb[1]);   // QrH KrL
                mma_bf16(accS[nt], qf[1], kb[0]);   // QrL KrH
                mma_bf16(accS[nt], qf[2], kb[2]);   // QiH KiH
                mma_bf16(accS[nt], qf[2], kb[3]);   // QiH KiL
                mma_bf16(accS[nt], qf[3], kb[2]);   // QiL KiH
            }
        }
        // ---- online softmax (rows: lg -> ri0, lg+8 -> ri1; 16 cols/thread/row) ----
        #pragma unroll
        for (int ri = 0; ri < 2; ri++) {
            float mb = -1e30f;
            #pragma unroll
            for (int nt = 0; nt < 8; nt++) {
                mb = fmaxf(mb, accS[nt][ri * 2]);
                mb = fmaxf(mb, accS[nt][ri * 2 + 1]);
            }
            mb *= 0.125f;
            mb = fmaxf(mb, __shfl_xor_sync(0xffffffffu, mb, 1));
            mb = fmaxf(mb, __shfl_xor_sync(0xffffffffu, mb, 2));
            float mn = fmaxf(m_[ri], mb);
            float lb = 0.f;
            #pragma unroll
            for (int nt = 0; nt < 8; nt++) {
                float p0 = expf(accS[nt][ri * 2] * 0.125f - mn);
                float p1 = expf(accS[nt][ri * 2 + 1] * 0.125f - mn);
                accS[nt][ri * 2] = p0; accS[nt][ri * 2 + 1] = p1;
                lb += p0 + p1;
            }
            lb += __shfl_xor_sync(0xffffffffu, lb, 1);
            lb += __shfl_xor_sync(0xffffffffu, lb, 2);
            float corr = expf(m_[ri] - mn);
            l_[ri] = l_[ri] * corr + lb;
            m_[ri] = mn;
            #pragma unroll
            for (int cp = 0; cp < 2; cp++)
                #pragma unroll
                for (int nt = 0; nt < 8; nt++) {
                    accO[cp][nt][ri * 2]     *= corr;
                    accO[cp][nt][ri * 2 + 1] *= corr;
                }
        }
        // ---- P @ V (P hi/lo bf16 from acc-layout trick; V split planes) ----
        const uint32_t* VB = sm + 16384 + buf * 16384 + 8192;
        #pragma unroll
        for (int kc = 0; kc < 4; kc++) {
            uint32_t ph[4], pl[4];
            split2g(accS[2*kc][0],   accS[2*kc][1],   ph[0], pl[0]);
            split2g(accS[2*kc][2],   accS[2*kc][3],   ph[1], pl[1]);
            split2g(accS[2*kc+1][0], accS[2*kc+1][1], ph[2], pl[2]);
            split2g(accS[2*kc+1][2], accS[2*kc+1][3], ph[3], pl[3]);
            int g0 = 2 * kc, g1 = g0 + 1;
            #pragma unroll
            for (int nto = 0; nto < 8; nto++) {
                int vr = nto * 8 + lg;
                int ov0 = vr * 32 + ((g0 ^ (vr & 7)) << 2) + lt;
                int ov1 = vr * 32 + ((g1 ^ (vr & 7)) << 2) + lt;
                uint32_t vb[4][2];
                #pragma unroll
                for (int p = 0; p < 4; p++) { vb[p][0] = VB[p * 2048 + ov0]; vb[p][1] = VB[p * 2048 + ov1]; }
                mma_bf16(accO[0][nto], ph, vb[0]);   // Ph VrH
                mma_bf16(accO[0][nto], ph, vb[1]);   // Ph VrL
                mma_bf16(accO[0][nto], pl, vb[0]);   // Pl VrH
                mma_bf16(accO[1][nto], ph, vb[2]);   // Ph ViH
                mma_bf16(accO[1][nto], ph, vb[3]);   // Ph ViL
                mma_bf16(accO[1][nto], pl, vb[2]);   // Pl ViH
            }
        }
        __syncthreads();
    }

    // ---- write O = accO / l ----
    float inv0 = 1.0f / l_[0], inv1 = 1.0f / l_[1];
    #pragma unroll
    for (int cp = 0; cp < 2; cp++) {
        float* G = cp ? Oi_ : Or_;
        #pragma unroll
        for (int nto = 0; nto < 8; nto++)
            #pragma unroll
            for (int e = 0; e < 4; e++) {
                int row = w * 16 + lg + (e >> 1) * 8;
                int col = zh * 64 + nto * 8 + 2 * lt + (e & 1);
                G[(rowQ + row) * 1024 + col] = accO[cp][nto][e] * ((e >> 1) ? inv1 : inv0);
            }
    }
}

// ---------------- coalesced 1024-pt FFT, twiddle table, optional fused bf16 split ----
#define FFT_COLS 8
#define FFT_LDP  1025
__global__ __launch_bounds__(256) void fft8_kernel(float* __restrict__ re,
                                                   float* __restrict__ im,
                                                   int inverse,
                                                   uint32_t* __restrict__ shR,
                                                   uint32_t* __restrict__ slR,
                                                   uint32_t* __restrict__ shI,
                                                   uint32_t* __restrict__ slI)
{
    extern __shared__ float fs[];
    float* sr = fs;
    float* si = fs + FFT_COLS * FFT_LDP;
    __shared__ float twr[512], twi[512];
    int blk = blockIdx.x;
    int b  = blk / (D_MODEL / FFT_COLS);
    int d0 = (blk % (D_MODEL / FFT_COLS)) * FFT_COLS;
    long long base = (long long)b * SEQ * D_MODEL + d0;
    int tid = threadIdx.x;

    float sgn = inverse ? 6.283185307179586f : -6.283185307179586f;
    #pragma unroll
    for (int j = 0; j < 2; j++) {
        int idx = j * 256 + tid;
        float ang = sgn * (float)idx * (1.0f / 1024.0f);
        float cs, sn;
        sincosf(ang, &sn, &cs);
        twr[idx] = cs; twi[idx] = sn;
    }

    #pragma unroll
    for (int i = 0; i < 8; i++) {
        int idx = i * 256 + tid;
        int row = idx >> 1, h = (idx & 1) * 4;
        int br = __brev((unsigned)row) >> 22;
        float4 vr = *(const float4*)(re + base + (long long)row * D_MODEL + h);
        float4 vi = *(const float4*)(im + base + (long long)row * D_MODEL + h);
        sr[(h+0)*FFT_LDP + br] = vr.x; sr[(h+1)*FFT_LDP + br] = vr.y;
        sr[(h+2)*FFT_LDP + br] = vr.z; sr[(h+3)*FFT_LDP + br] = vr.w;
        si[(h+0)*FFT_LDP + br] = vi.x; si[(h+1)*FFT_LDP + br] = vi.y;
        si[(h+2)*FFT_LDP + br] = vi.z; si[(h+3)*FFT_LDP + br] = vi.w;
    }
    __syncthreads();

    #pragma unroll
    for (int s = 1; s <= 10; s++) {
        int half = 1 << (s - 1);
        #pragma unroll
        for (int i = 0; i < 16; i++) {
            int idx = i * 256 + tid;
            int j = idx >> 3, c = idx & 7;
            int pos = j & (half - 1);
            int g = j >> (s - 1);
            int i0 = g * (half << 1) + pos, i1 = i0 + half;
            int tw = pos << (10 - s);
            float cs = twr[tw], sn = twi[tw];
            float* pr = sr + c * FFT_LDP;
            float* pi = si + c * FFT_LDP;
            float ur = pr[i0], ui = pi[i0];
            float vr = pr[i1], vi = pi[i1];
            float tr = cs * vr - sn * vi;
            float ti = cs * vi + sn * vr;
            pr[i0] = ur + tr; pi[i0] = ui + ti;
            pr[i1] = ur - tr; pi[i1] = ui - ti;
        }
        __syncthreads();
    }

    float sc = inverse ? (1.0f / 1024.0f) : 1.0f;
    #pragma unroll
    for (int i = 0; i < 8; i++) {
        int idx = i * 256 + tid;
        int row = idx >> 1, h = (idx & 1) * 4;
        float4 vr, vi;
        vr.x = sr[(h+0)*FFT_LDP + row] * sc; vr.y = sr[(h+1)*FFT_LDP + row] * sc;
        vr.z = sr[(h+2)*FFT_LDP + row] * sc; vr.w = sr[(h+3)*FFT_LDP + row] * sc;
        vi.x = si[(h+0)*FFT_LDP + row] * sc; vi.y = si[(h+1)*FFT_LDP + row] * sc;
        vi.z = si[(h+2)*FFT_LDP + row] * sc; vi.w = si[(h+3)*FFT_LDP + row] * sc;
        if (shR) {
            long long gi = (base + (long long)row * D_MODEL + h) >> 1;
            uint32_t h0, l0, h1, l1;
            split2g(vr.x, vr.y, h0, l0);
            split2g(vr.z, vr.w, h1, l1);
            *(uint2*)(shR + gi) = make_uint2(h0, h1);
            *(uint2*)(slR + gi) = make_uint2(l0, l1);
            split2g(vi.x, vi.y, h0, l0);
            split2g(vi.z, vi.w, h1, l1);
            *(uint2*)(shI + gi) = make_uint2(h0, h1);
            *(uint2*)(slI + gi) = make_uint2(l0, l1);
        } else {
            *(float4*)(re + base + (long long)row * D_MODEL + h) = vr;
            *(float4*)(im + base + (long long)row * D_MODEL + h) = vi;
        }
    }
}
#define FFT_SMEM (2 * FFT_COLS * FFT_LDP * 4)

// ---------------- elementwise helpers ----------------
__global__ void cvt_tf32_kernel(uint32_t* __restrict__ dst, const float* __restrict__ src,
                                long long n4)
{
    long long i = (long long)blockIdx.x*blockDim.x + threadIdx.x;
    if (i < n4) {
        float4 v = ((const float4*)src)[i];
        uint4 o;
        o.x = f2tf32(v.x); o.y = f2tf32(v.y);
        o.z = f2tf32(v.z); o.w = f2tf32(v.w);
        ((uint4*)dst)[i] = o;
    }
}
__global__ void split_bf16_kernel(uint32_t* __restrict__ hi, uint32_t* __restrict__ lo,
                                  const float* __restrict__ src, long long n4)
{
    long long i = (long long)blockIdx.x*blockDim.x + threadIdx.x;
    if (i < n4) {
        float4 v = ((const float4*)src)[i];
        uint32_t h0, l0, h1, l1;
        split2g(v.x, v.y, h0, l0);
        split2g(v.z, v.w, h1, l1);
        ((uint2*)hi)[i] = make_uint2(h0, h1);
        ((uint2*)lo)[i] = make_uint2(l0, l1);
    }
}
__global__ void scale_tf32_kernel(uint32_t* __restrict__ y, const float* __restrict__ x,
                                  const float* __restrict__ dt, long long n)
{
    long long i = (long long)blockIdx.x*blockDim.x + threadIdx.x;
    if (i < n) y[i] = f2tf32(x[i]*dt[0]);
}
__global__ void buildD_kernel(uint32_t* __restrict__ Dr, uint32_t* __restrict__ Di,
                              const uint32_t* __restrict__ tM, const float* __restrict__ E,
                              long long n)
{
    long long i = (long long)blockIdx.x*blockDim.x + threadIdx.x;
    if (i < n) {
        Dr[i] = f2tf32(-0.5f * E[i]);
        Di[i] = tM[i] ^ 0x80000000u;
    }
}

// ---------------- host orchestration ----------------
static void cgc(int mode, float* Cr, float* Ci,
    const uint32_t* Ar, const uint32_t* Ai,
    const uint32_t* Br, const uint32_t* Bi,
    int M, int N, int K, long long sAm, long long sBn, long long sCm,
    float alpha, int acc,
    const float* bR = nullptr, const float* bI = nullptr, int gelu = 0,
    uint32_t* outTr = nullptr, uint32_t* outTi = nullptr,
    const float* addR = nullptr, const float* addI = nullptr,
    float* dupR = nullptr, float* dupI = nullptr)
{
    dim3 grid(N / 64, M / 128);
    if (mode == 1) {
        size_t sh = 2 * 2 * (128*32 + 64*32) * 4;
        cgemm_c<1><<<grid, 256, sh>>>(Cr, Ci, Ar, Ai, Br, Bi, M, N, K,
                                      sAm, sBn, sCm, alpha, acc, bR, bI, gelu,
                                      outTr, outTi, addR, addI, dupR, dupI);
    } else {
        size_t sh = 2 * (128*32 + 64*32) * 4;
        cgemm_c<0><<<grid, 256, sh>>>(Cr, Ci, Ar, Ai, Br, Bi, M, N, K,
                                      sAm, sBn, sCm, alpha, acc, bR, bI, gelu,
                                      nullptr, nullptr, nullptr, nullptr, nullptr, nullptr);
    }
}

static void cvt(uint32_t* dst, const float* src, long long n)
{
    long long n4 = n >> 2;
    cvt_tf32_kernel<<<(int)((n4 + 255) / 256), 256>>>(dst, src, n4);
}
static void splitp(uint32_t* hi, uint32_t* lo, const float* src, long long n)
{
    long long n4 = n >> 2;
    split_bf16_kernel<<<(int)((n4 + 255) / 256), 256>>>(hi, lo, src, n4);
}

#define TGQ_SMEM (2 * (4 * 128 * 32 + 4 * 64 * 32) * 4)   // 196608

extern "C" void kernel_launch(void* const* d_in, const int* in_sizes, int n_in,
                              void* d_out, int out_size)
{
    cudaFuncSetAttribute(cgemm_c<1>, cudaFuncAttributeMaxDynamicSharedMemorySize, 98304);
    cudaFuncSetAttribute(cgemm_c<0>, cudaFuncAttributeMaxDynamicSharedMemorySize, 49152);
    cudaFuncSetAttribute(cgemm_q<1>, cudaFuncAttributeMaxDynamicSharedMemorySize, TGQ_SMEM);
    cudaFuncSetAttribute(flash_kernel, cudaFuncAttributeMaxDynamicSharedMemorySize, FA_SMEM);
    cudaFuncSetAttribute(fft8_kernel, cudaFuncAttributeMaxDynamicSharedMemorySize, FFT_SMEM);

    const float* x_real = (const float*)d_in[0];
    const float* x_imag = (const float*)d_in[1];
    const float* Wr_q = (const float*)d_in[2];   const float* Wi_q = (const float*)d_in[3];
    const float* br_q = (const float*)d_in[4];   const float* bi_q = (const float*)d_in[5];
    const float* Wr_k = (const float*)d_in[6];   const float* Wi_k = (const float*)d_in[7];
    const float* br_k = (const float*)d_in[8];   const float* bi_k = (const float*)d_in[9];
    const float* Wr_v = (const float*)d_in[10];  const float* Wi_v = (const float*)d_in[11];
    const float* br_v = (const float*)d_in[12];  const float* bi_v = (const float*)d_in[13];
    const float* Wr_o = (const float*)d_in[14];  const float* Wi_o = (const float*)d_in[15];
    const float* br_o = (const float*)d_in[16];  const float* bi_o = (const float*)d_in[17];
    const float* Wr_f1 = (const float*)d_in[18]; const float* Wi_f1 = (const float*)d_in[19];
    const float* br_f1 = (const float*)d_in[20]; const float* bi_f1 = (const float*)d_in[21];
    const float* Wr_f2 = (const float*)d_in[22]; const float* Wi_f2 = (const float*)d_in[23];
    const float* br_f2 = (const float*)d_in[24]; const float* bi_f2 = (const float*)d_in[25];
    const float* Hmat = (const float*)d_in[26];
    const float* dtp  = (const float*)d_in[27];

    float* outRe = (float*)d_out;
    float* outIm = outRe + (long long)ROWS*D_MODEL;

    float *Qr,*Qi,*Kr,*Ki,*Vr,*Vi,*Xr,*Xi,*Or,*Oi,*Hr,*Hi,*Ta;
    uint32_t *tAr,*tAi,*tBr,*tBi,*tM,*tXr,*tXi,*tHr,*tHi;
    cudaGetSymbolAddress((void**)&Qr, g_Qr); cudaGetSymbolAddress((void**)&Qi, g_Qi);
    cudaGetSymbolAddress((void**)&Kr, g_Kr); cudaGetSymbolAddress((void**)&Ki, g_Ki);
    cudaGetSymbolAddress((void**)&Vr, g_Vr); cudaGetSymbolAddress((void**)&Vi, g_Vi);
    cudaGetSymbolAddress((void**)&Xr, g_Xr); cudaGetSymbolAddress((void**)&Xi, g_Xi);
    cudaGetSymbolAddress((void**)&Or, g_Or); cudaGetSymbolAddress((void**)&Oi, g_Oi);
    cudaGetSymbolAddress((void**)&Hr, g_Hr); cudaGetSymbolAddress((void**)&Hi, g_Hi);
    cudaGetSymbolAddress((void**)&Ta, g_Ta);
    cudaGetSymbolAddress((void**)&tAr, g_tAr); cudaGetSymbolAddress((void**)&tAi, g_tAi);
    cudaGetSymbolAddress((void**)&tBr, g_tBr); cudaGetSymbolAddress((void**)&tBi, g_tBi);
    cudaGetSymbolAddress((void**)&tM,  g_tM);
    cudaGetSymbolAddress((void**)&tXr, g_tXr); cudaGetSymbolAddress((void**)&tXi, g_tXi);
    cudaGetSymbolAddress((void**)&tHr, g_tHr); cudaGetSymbolAddress((void**)&tHi, g_tHi);

    const long long ND = (long long)ROWS*D_MODEL;
    const long long DD = (long long)D_MODEL*D_MODEL;
    const long long DH = (long long)D_MODEL*HIDDEN;
    const long long ND2 = ND >> 1;
    const long long DD2 = DD >> 1;
    const int FFT_GRID = NBATCH * (D_MODEL / FFT_COLS);

    // ---- Q/K projections: precise split-bf16 (inputs read directly from x) ----
    splitp(tAr, tAr + ND2, x_real, ND);
    splitp(tAi, tAi + ND2, x_imag, ND);
    splitp(tBr, tBr + DD2, Wr_q, DD);
    splitp(tBr + 2*DD2, tBr + 3*DD2, Wi_q, DD);
    splitp(tBi, tBi + DD2, Wr_k, DD);
    splitp(tBi + 2*DD2, tBi + 3*DD2, Wi_k, DD);
    {
        dim3 grid(D_MODEL/64, ROWS/128);
        cgemm_q<1><<<grid, 512, TGQ_SMEM>>>(Qr, Qi,
            tAr, tAr + ND2, tAi, tAi + ND2,
            tBr, tBr + DD2, tBr + 2*DD2, tBr + 3*DD2,
            ROWS, D_MODEL, D_MODEL, D_MODEL, D_MODEL, D_MODEL,
            0,0,0,0,0,0,1, 1.f, 0, br_q, bi_q);
        cgemm_q<1><<<grid, 512, TGQ_SMEM>>>(Kr, Ki,
            tAr, tAr + ND2, tAi, tAi + ND2,
            tBi, tBi + DD2, tBi + 2*DD2, tBi + 3*DD2,
            ROWS, D_MODEL, D_MODEL, D_MODEL, D_MODEL, D_MODEL,
            0,0,0,0,0,0,1, 1.f, 0, br_k, bi_k);
    }

    // ---- V projection (cp.async tf32 engine; inputs from x directly) ----
    cvt(tXr, x_real, ND); cvt(tXi, x_imag, ND);
    cvt(tM, Wr_v, DD); cvt(tHr, Wi_v, DD);
    cgc(1, Vr,Vi, tXr,tXi, tM,tHr, ROWS,D_MODEL,D_MODEL, D_MODEL,D_MODEL,D_MODEL,
        1.f,0, br_v,bi_v,0);

    // ---- forward FFTs; Q/K emit fused bf16 splits (flash operands); V stays fp32 ----
    fft8_kernel<<<FFT_GRID, 256, FFT_SMEM>>>(Qr, Qi, 0,
        tAr, tAr + ND2, tAi, tAi + ND2);
    fft8_kernel<<<FFT_GRID, 256, FFT_SMEM>>>(Kr, Ki, 0,
        tBr, tBr + ND2, tBr + 2*ND2, tBr + 3*ND2);
    fft8_kernel<<<FFT_GRID, 256, FFT_SMEM>>>(Vr, Vi, 0,
        nullptr, nullptr, nullptr, nullptr);

    // ---- FLASH: Of = softmax(scale*Re(Qf conj(Kf))) @ Vf ----
    flash_kernel<<<dim3(SEQ/128, NBATCH*NHEADS), 256, FA_SMEM>>>(
        Or, Oi,
        tAr, tAr + ND2, tAi, tAi + ND2,
        tBr, tBr + ND2, tBr + 2*ND2, tBr + 3*ND2,
        Vr, Vi);

    // ---- inverse FFT ----
    fft8_kernel<<<FFT_GRID, 256, FFT_SMEM>>>(Or, Oi, 1,
        nullptr, nullptr, nullptr, nullptr);

    // ---- X = x + clin(O, Wo); emits tf32(X) for FFN1 ----
    cvt(tAr, Or, ND); cvt(tAi, Oi, ND);
    cvt(tBr, Wr_o, DD); cvt(tBi, Wi_o, DD);
    cgc(1, Xr,Xi, tAr,tAi, tBr,tBi, ROWS,D_MODEL,D_MODEL, D_MODEL,D_MODEL,D_MODEL,
        1.f,0, br_o,bi_o,0, tXr,tXi, x_real,x_imag);

    // ---- FFN1: H = gelu(clin(X, Wf1)); emits tf32(H) ----
    cvt(tBr, Wr_f1, DH); cvt(tBi, Wi_f1, DH);
    cgc(1, Hr,Hi, tXr,tXi, tBr,tBi, ROWS,HIDDEN,D_MODEL, D_MODEL,D_MODEL,HIDDEN,
        1.f,0, br_f1,bi_f1,1, tHr,tHi);

    // ---- FFN2: X += clin(H, Wf2); emits tf32(X) and duplicates X into out ----
    cvt(tBr, Wr_f2, DH); cvt(tBi, Wi_f2, DH);
    cgc(1, Xr,Xi, tHr,tHi, tBr,tBi, ROWS,D_MODEL,HIDDEN, HIDDEN,HIDDEN,D_MODEL,
        1.f,1, br_f2,bi_f2,0, tXr,tXi, nullptr,nullptr, outRe,outIm);

    // ---- U = expm(-i H dt) ~ I - E/2 - i M  (E = M^2, M = H dt) ----
    scale_tf32_kernel<<<(int)((DD+255)/256), 256>>>(tM, Hmat, dtp, DD);
    cgc(0, Ta,nullptr, tM,nullptr, tM,nullptr, D_MODEL,D_MODEL,D_MODEL,
        D_MODEL,D_MODEL,D_MODEL, 1.f,0);
    buildD_kernel<<<(int)((DD+255)/256), 256>>>(tBr, tBi, tM, Ta, DD);

    // ---- out = X + X @ D (out already holds X via dup) ----
    cgc(1, outRe,outIm, tXr,tXi, tBr,tBi, ROWS,D_MODEL,D_MODEL, D_MODEL,D_MODEL,D_MODEL,
        1.f,1);
}